// round 1
// baseline (speedup 1.0000x reference)
#include <cuda_runtime.h>
#include <math.h>

#define B_SESS   8192
#define NPS      21
#define N_NODES  (B_SESS * NPS)      // 172032
#define F_IN     171
#define F_HID    256
#define F_OUT    128

// Output layout: hidden_state (N*128) | y (N*1) | x (N*171)
#define OUT_HID_OFF  0
#define OUT_Y_OFF    ((size_t)N_NODES * F_OUT)                  // 22020096
#define OUT_X_OFF    ((size_t)N_NODES * (F_OUT + 1))            // 22192128

// Scratch (static device arrays: allocation-free)
__device__ float g_h1[(size_t)N_NODES * F_HID];
__device__ float g_y [(size_t)N_NODES * F_HID];
__device__ float g_h2[(size_t)N_NODES * F_OUT];

// ---------------------------------------------------------------------------
// Kernel 1: build x_mod (embedding scatter) directly into the output x slice.
// ---------------------------------------------------------------------------
__global__ __launch_bounds__(256) void build_x_kernel(
    const float* __restrict__ x,
    const int*   __restrict__ click,
    const int*   __restrict__ query,
    const int*   __restrict__ docu,
    const int*   __restrict__ title_id,
    const float* __restrict__ qtab,
    const float* __restrict__ dtab,
    const float* __restrict__ ttab,
    const float* __restrict__ ptab,
    const float* __restrict__ ctab,
    float* __restrict__ xout)
{
    int idx = blockIdx.x * blockDim.x + threadIdx.x;
    if (idx >= N_NODES * F_IN) return;
    int n = idx / F_IN;
    int c = idx - n * F_IN;
    int b = n / NPS;
    int s = n - b * NPS;

    float v;
    if (s == 0) {
        // query node
        v = (c < 160) ? qtab[(size_t)query[b] * 160 + c] : x[idx];
    } else if (s <= 10) {
        int j = s - 1;
        if      (c < 160)  v = dtab[(size_t)docu[b * 10 + j] * 160 + c];
        else if (c == 160) v = ptab[j];              // pos_table[j,0]
        else if (c == 161) v = ctab[click[b]];       // click_table[click,0]
        else               v = x[idx];
    } else {
        int j = s - 11;
        v = (c < 160) ? ttab[(size_t)title_id[b * 10 + j] * 160 + c] : x[idx];
    }
    xout[idx] = v;
}

// ---------------------------------------------------------------------------
// Kernel 2: SGEMM  C[n][m] = sum_k A[n][k] * W[m][k]   (A: n x K, W: M x K)
// BM=BN=128, BK=16, 256 threads, 8x8 register tile per thread.
// n multiple of 128; M multiple of 128; K arbitrary (zero-padded loads).
// ---------------------------------------------------------------------------
__global__ __launch_bounds__(256) void sgemm_nt(
    const float* __restrict__ A, const float* __restrict__ W,
    float* __restrict__ C, int K, int M)
{
    __shared__ float As[16][129];
    __shared__ float Bs[16][129];

    const int tid = threadIdx.x;
    const int tx = tid & 15;         // col group
    const int ty = tid >> 4;         // row group
    const int rowBase = blockIdx.x * 128;
    const int colBase = blockIdx.y * 128;

    const int ldRow = tid >> 1;        // 0..127
    const int ldK   = (tid & 1) * 8;   // 0 or 8

    float acc[8][8];
    #pragma unroll
    for (int i = 0; i < 8; i++)
        #pragma unroll
        for (int j = 0; j < 8; j++) acc[i][j] = 0.f;

    for (int k0 = 0; k0 < K; k0 += 16) {
        const float* Ap = A + (size_t)(rowBase + ldRow) * K + k0 + ldK;
        #pragma unroll
        for (int i = 0; i < 8; i++) {
            int kk = k0 + ldK + i;
            As[ldK + i][ldRow] = (kk < K) ? Ap[i] : 0.f;
        }
        const float* Wp = W + (size_t)(colBase + ldRow) * K + k0 + ldK;
        #pragma unroll
        for (int i = 0; i < 8; i++) {
            int kk = k0 + ldK + i;
            Bs[ldK + i][ldRow] = (kk < K) ? Wp[i] : 0.f;
        }
        __syncthreads();

        #pragma unroll
        for (int k = 0; k < 16; k++) {
            float a[8], bb[8];
            #pragma unroll
            for (int i = 0; i < 8; i++) a[i]  = As[k][ty + 16 * i];
            #pragma unroll
            for (int j = 0; j < 8; j++) bb[j] = Bs[k][tx + 16 * j];
            #pragma unroll
            for (int i = 0; i < 8; i++)
                #pragma unroll
                for (int j = 0; j < 8; j++)
                    acc[i][j] = fmaf(a[i], bb[j], acc[i][j]);
        }
        __syncthreads();
    }

    #pragma unroll
    for (int i = 0; i < 8; i++) {
        int r = rowBase + ty + 16 * i;
        float* Cp = C + (size_t)r * M + colBase;
        #pragma unroll
        for (int j = 0; j < 8; j++)
            Cp[tx + 16 * j] = acc[i][j];
    }
}

// ---------------------------------------------------------------------------
// Static adjacency: in-neighbor list (incl. self-loop) for slot `node` (0..20)
// ---------------------------------------------------------------------------
__device__ __forceinline__ int get_srcs(int node, int* s)
{
    if (node == 0) {
        #pragma unroll
        for (int j = 0; j < 10; j++) s[j] = 1 + j;
        s[10] = 0;
        return 11;
    }
    if (node <= 10) { s[0] = 0; s[1] = node + 10; s[2] = node; return 3; }
    s[0] = node - 10; s[1] = node; return 2;
}

// ---------------------------------------------------------------------------
// Kernel 3: GAT aggregate layer 1 (F=256), + bias + relu. 1 block = 1 session.
// ---------------------------------------------------------------------------
__global__ __launch_bounds__(256) void gat_agg1(
    const float* __restrict__ H,
    const float* __restrict__ asrc, const float* __restrict__ adst,
    const float* __restrict__ bias, float* __restrict__ Y)
{
    __shared__ float hs[NPS][F_HID];
    __shared__ float sv[NPS], dv[NPS];
    __shared__ float alpha[NPS][11];

    const int b = blockIdx.x, tid = threadIdx.x;
    const size_t base = (size_t)b * NPS;
    const float* Hb = H + base * F_HID;

    #pragma unroll
    for (int r = 0; r < NPS; r++) hs[r][tid] = Hb[r * F_HID + tid];
    __syncthreads();

    const int wid = tid >> 5, lid = tid & 31;
    for (int node = wid; node < NPS; node += 8) {
        float ss = 0.f, dd = 0.f;
        #pragma unroll
        for (int c = lid; c < F_HID; c += 32) {
            float h = hs[node][c];
            ss = fmaf(h, asrc[c], ss);
            dd = fmaf(h, adst[c], dd);
        }
        #pragma unroll
        for (int o = 16; o; o >>= 1) {
            ss += __shfl_down_sync(0xffffffffu, ss, o);
            dd += __shfl_down_sync(0xffffffffu, dd, o);
        }
        if (lid == 0) { sv[node] = ss; dv[node] = dd; }
    }
    __syncthreads();

    if (tid < NPS) {
        int s[11]; int cnt = get_srcs(tid, s);
        float d = dv[tid];
        float e[11]; float m = -1e30f;
        for (int k = 0; k < cnt; k++) {
            float v = sv[s[k]] + d;
            v = v > 0.f ? v : 0.2f * v;   // leaky_relu 0.2
            e[k] = v; m = fmaxf(m, v);
        }
        float sum = 0.f;
        for (int k = 0; k < cnt; k++) { float t = expf(e[k] - m); e[k] = t; sum += t; }
        float inv = 1.f / sum;
        for (int k = 0; k < cnt; k++) alpha[tid][k] = e[k] * inv;
    }
    __syncthreads();

    const float bcol = bias[tid];
    float* Yb = Y + base * F_HID;
    #pragma unroll
    for (int node = 0; node < NPS; node++) {
        int s[11]; int cnt = get_srcs(node, s);
        float acc = 0.f;
        for (int k = 0; k < cnt; k++)
            acc = fmaf(alpha[node][k], hs[s[k]][tid], acc);
        Yb[node * F_HID + tid] = fmaxf(acc + bcol, 0.f);  // relu
    }
}

// ---------------------------------------------------------------------------
// Kernel 4: GAT aggregate layer 2 (F=128) + bias -> hidden (no relu),
// plus fused head: y = sigmoid(relu(hidden) @ Wl^T + bl)
// ---------------------------------------------------------------------------
__global__ __launch_bounds__(128) void gat_agg2(
    const float* __restrict__ H,
    const float* __restrict__ asrc, const float* __restrict__ adst,
    const float* __restrict__ bias,
    const float* __restrict__ Wl, const float* __restrict__ bl,
    float* __restrict__ hid, float* __restrict__ yout)
{
    __shared__ float hs[NPS][F_OUT];
    __shared__ float os[NPS][F_OUT];
    __shared__ float sv[NPS], dv[NPS];
    __shared__ float alpha[NPS][11];

    const int b = blockIdx.x, tid = threadIdx.x;
    const size_t base = (size_t)b * NPS;
    const float* Hb = H + base * F_OUT;

    #pragma unroll
    for (int r = 0; r < NPS; r++) hs[r][tid] = Hb[r * F_OUT + tid];
    __syncthreads();

    const int wid = tid >> 5, lid = tid & 31;
    for (int node = wid; node < NPS; node += 4) {
        float ss = 0.f, dd = 0.f;
        #pragma unroll
        for (int c = lid; c < F_OUT; c += 32) {
            float h = hs[node][c];
            ss = fmaf(h, asrc[c], ss);
            dd = fmaf(h, adst[c], dd);
        }
        #pragma unroll
        for (int o = 16; o; o >>= 1) {
            ss += __shfl_down_sync(0xffffffffu, ss, o);
            dd += __shfl_down_sync(0xffffffffu, dd, o);
        }
        if (lid == 0) { sv[node] = ss; dv[node] = dd; }
    }
    __syncthreads();

    if (tid < NPS) {
        int s[11]; int cnt = get_srcs(tid, s);
        float d = dv[tid];
        float e[11]; float m = -1e30f;
        for (int k = 0; k < cnt; k++) {
            float v = sv[s[k]] + d;
            v = v > 0.f ? v : 0.2f * v;
            e[k] = v; m = fmaxf(m, v);
        }
        float sum = 0.f;
        for (int k = 0; k < cnt; k++) { float t = expf(e[k] - m); e[k] = t; sum += t; }
        float inv = 1.f / sum;
        for (int k = 0; k < cnt; k++) alpha[tid][k] = e[k] * inv;
    }
    __syncthreads();

    const float bcol = bias[tid];
    float* Hob = hid + base * F_OUT;
    #pragma unroll
    for (int node = 0; node < NPS; node++) {
        int s[11]; int cnt = get_srcs(node, s);
        float acc = 0.f;
        for (int k = 0; k < cnt; k++)
            acc = fmaf(alpha[node][k], hs[s[k]][tid], acc);
        float v = acc + bcol;
        Hob[node * F_OUT + tid] = v;           // hidden_state (pre-relu)
        os[node][tid] = fmaxf(v, 0.f);         // relu for head
    }
    __syncthreads();

    const float blv = bl[0];
    for (int node = wid; node < NPS; node += 4) {
        float p = 0.f;
        #pragma unroll
        for (int c = lid; c < F_OUT; c += 32)
            p = fmaf(os[node][c], Wl[c], p);
        #pragma unroll
        for (int o = 16; o; o >>= 1)
            p += __shfl_down_sync(0xffffffffu, p, o);
        if (lid == 0)
            yout[base + node] = 1.f / (1.f + expf(-(p + blv)));
    }
}

// ---------------------------------------------------------------------------
extern "C" void kernel_launch(void* const* d_in, const int* in_sizes, int n_in,
                              void* d_out, int out_size)
{
    // metadata order: i, x, edge_index, doc_id, click, query, docu, title_id,
    // query_table, doc_table, title_table, pos_table, click_table,
    // W1, a_src1, a_dst1, b1, W2, a_src2, a_dst2, b2, Wl, bl
    const float* x     = (const float*)d_in[1];
    const int*   click = (const int*)  d_in[4];
    const int*   query = (const int*)  d_in[5];
    const int*   docu  = (const int*)  d_in[6];
    const int*   title = (const int*)  d_in[7];
    const float* qtab  = (const float*)d_in[8];
    const float* dtab  = (const float*)d_in[9];
    const float* ttab  = (const float*)d_in[10];
    const float* ptab  = (const float*)d_in[11];
    const float* ctab  = (const float*)d_in[12];
    const float* W1    = (const float*)d_in[13];
    const float* as1   = (const float*)d_in[14];
    const float* ad1   = (const float*)d_in[15];
    const float* b1    = (const float*)d_in[16];
    const float* W2    = (const float*)d_in[17];
    const float* as2   = (const float*)d_in[18];
    const float* ad2   = (const float*)d_in[19];
    const float* b2    = (const float*)d_in[20];
    const float* Wl    = (const float*)d_in[21];
    const float* bl    = (const float*)d_in[22];

    float* out  = (float*)d_out;
    float* xout = out + OUT_X_OFF;
    float* hout = out + OUT_HID_OFF;
    float* yout = out + OUT_Y_OFF;

    float *h1p, *yp, *h2p;
    cudaGetSymbolAddress((void**)&h1p, g_h1);
    cudaGetSymbolAddress((void**)&yp,  g_y);
    cudaGetSymbolAddress((void**)&h2p, g_h2);

    // 1. scatter embeddings into x (also the x output slice)
    build_x_kernel<<<(N_NODES * F_IN + 255) / 256, 256>>>(
        x, click, query, docu, title, qtab, dtab, ttab, ptab, ctab, xout);

    // 2. h1 = x_mod @ W1^T
    sgemm_nt<<<dim3(N_NODES / 128, F_HID / 128), 256>>>(xout, W1, h1p, F_IN, F_HID);

    // 3. GAT aggregate 1 + relu
    gat_agg1<<<B_SESS, 256>>>(h1p, as1, ad1, b1, yp);

    // 4. h2 = y @ W2^T
    sgemm_nt<<<dim3(N_NODES / 128, F_OUT / 128), 256>>>(yp, W2, h2p, F_HID, F_OUT);

    // 5. GAT aggregate 2 + head
    gat_agg2<<<B_SESS, 128>>>(h2p, as2, ad2, b2, Wl, bl, hout, yout);
}

// round 3
// speedup vs baseline: 1.9284x; 1.9284x over previous
#include <cuda_runtime.h>
#include <cuda_bf16.h>
#include <math.h>
#include <stdint.h>

#define B_SESS   8192
#define NPS      21
#define N_NODES  (B_SESS * NPS)      // 172032
#define F_IN     171
#define K1_PAD   192                 // F_IN padded to 6*32
#define F_HID    256
#define F_OUT    128

// Output layout: hidden_state (N*128) | y (N*1) | x (N*171)
#define OUT_HID_OFF  0
#define OUT_Y_OFF    ((size_t)N_NODES * F_OUT)
#define OUT_X_OFF    ((size_t)N_NODES * (F_OUT + 1))

// Scratch (static device arrays: allocation-free)
__device__ float          g_h1[(size_t)N_NODES * F_HID];
__device__ float          g_h2[(size_t)N_NODES * F_OUT];
__device__ __nv_bfloat16  g_xhi[(size_t)N_NODES * K1_PAD];
__device__ __nv_bfloat16  g_xlo[(size_t)N_NODES * K1_PAD];
__device__ __nv_bfloat16  g_yhi[(size_t)N_NODES * F_HID];
__device__ __nv_bfloat16  g_ylo[(size_t)N_NODES * F_HID];
__device__ __nv_bfloat16  g_w1hi[(size_t)F_HID * K1_PAD];
__device__ __nv_bfloat16  g_w1lo[(size_t)F_HID * K1_PAD];
__device__ __nv_bfloat16  g_w2hi[(size_t)F_OUT * F_HID];
__device__ __nv_bfloat16  g_w2lo[(size_t)F_OUT * F_HID];

// ===========================================================================
// helpers (baseline PTX only: ldmatrix / mma.sync / cp.async)
// ===========================================================================
__device__ __forceinline__ uint32_t smem_to_u32(const void* p) {
    uint32_t a;
    asm("{ .reg .u64 t; cvta.to.shared.u64 t, %1; cvt.u32.u64 %0, t; }" : "=r"(a) : "l"(p));
    return a;
}
__device__ __forceinline__ void cp_async16(uint32_t dst, const void* src) {
    asm volatile("cp.async.cg.shared.global [%0], [%1], 16;" :: "r"(dst), "l"(src));
}
#define CP_COMMIT() asm volatile("cp.async.commit_group;" ::: "memory")
#define CP_WAIT0()  asm volatile("cp.async.wait_group 0;" ::: "memory")

__device__ __forceinline__ void ldsm_x4(uint32_t addr, uint32_t* r) {
    asm volatile("ldmatrix.sync.aligned.m8n8.x4.shared.b16 {%0,%1,%2,%3}, [%4];"
        : "=r"(r[0]), "=r"(r[1]), "=r"(r[2]), "=r"(r[3]) : "r"(addr));
}
__device__ __forceinline__ void mma_bf16(float* d, const uint32_t* a, const uint32_t* b) {
    asm volatile("mma.sync.aligned.m16n8k16.row.col.f32.bf16.bf16.f32 "
        "{%0,%1,%2,%3}, {%4,%5,%6,%7}, {%8,%9}, {%0,%1,%2,%3};"
        : "+f"(d[0]), "+f"(d[1]), "+f"(d[2]), "+f"(d[3])
        : "r"(a[0]), "r"(a[1]), "r"(a[2]), "r"(a[3]), "r"(b[0]), "r"(b[1]));
}

// ===========================================================================
// Kernel 1: build x_mod (scatter) + fused bf16 hi/lo split (padded to K1_PAD)
// ===========================================================================
__global__ __launch_bounds__(256) void build_x_kernel(
    const float* __restrict__ x,
    const int*   __restrict__ click,
    const int*   __restrict__ query,
    const int*   __restrict__ docu,
    const int*   __restrict__ title_id,
    const float* __restrict__ qtab,
    const float* __restrict__ dtab,
    const float* __restrict__ ttab,
    const float* __restrict__ ptab,
    const float* __restrict__ ctab,
    float* __restrict__ xout,
    __nv_bfloat16* __restrict__ xhi,
    __nv_bfloat16* __restrict__ xlo)
{
    long long idx = (long long)blockIdx.x * blockDim.x + threadIdx.x;
    if (idx >= (long long)N_NODES * K1_PAD) return;
    int n = (int)(idx / K1_PAD);
    int c = (int)(idx - (long long)n * K1_PAD);
    int b = n / NPS;
    int s = n - b * NPS;

    float v = 0.f;
    if (c < F_IN) {
        long long xi = (long long)n * F_IN + c;
        if (s == 0) {
            v = (c < 160) ? qtab[(size_t)query[b] * 160 + c] : x[xi];
        } else if (s <= 10) {
            int j = s - 1;
            if      (c < 160)  v = dtab[(size_t)docu[b * 10 + j] * 160 + c];
            else if (c == 160) v = ptab[j];
            else if (c == 161) v = ctab[click[b]];
            else               v = x[xi];
        } else {
            int j = s - 11;
            v = (c < 160) ? ttab[(size_t)title_id[b * 10 + j] * 160 + c] : x[xi];
        }
        xout[xi] = v;
    }
    __nv_bfloat16 h = __float2bfloat16(v);
    xhi[idx] = h;
    xlo[idx] = __float2bfloat16(v - __bfloat162float(h));
}

// ===========================================================================
// Kernel 2: fp32 -> bf16 hi/lo split for weights (with K padding)
// ===========================================================================
__global__ __launch_bounds__(256) void conv_split(
    const float* __restrict__ src, int Ksrc,
    __nv_bfloat16* __restrict__ hi, __nv_bfloat16* __restrict__ lo,
    int Kdst, long long total)
{
    long long idx = (long long)blockIdx.x * blockDim.x + threadIdx.x;
    if (idx >= total) return;
    long long row = idx / Kdst;
    int c = (int)(idx - row * Kdst);
    float v = (c < Ksrc) ? src[row * Ksrc + c] : 0.f;
    __nv_bfloat16 h = __float2bfloat16(v);
    hi[idx] = h;
    lo[idx] = __float2bfloat16(v - __bfloat162float(h));
}

// ===========================================================================
// Kernel 3: HMMA bf16 split-3 GEMM.  C[row][m] = sum_k A[row][k]*W[m][k]
// 128x128x32 tiles, 8 warps (32x64 each), double-buffered cp.async.
// ===========================================================================
#define BM 128
#define BN 128
#define BK 32
#define ASTRIDE 144                       // bytes per smem row (72 bf16) — conflict-free ldmatrix
#define ARR_B   (128 * ASTRIDE)           // 18432 per array
#define STAGE_B (4 * ARR_B)               // Ah, Al, Bh, Bl
#define GEMM_SMEM (2 * STAGE_B)           // 147456

__global__ __launch_bounds__(256, 1) void mma_gemm(
    const __nv_bfloat16* __restrict__ Ahi, const __nv_bfloat16* __restrict__ Alo,
    const __nv_bfloat16* __restrict__ Bhi, const __nv_bfloat16* __restrict__ Blo,
    float* __restrict__ C, int Kpad, int NK, int Mout)
{
    extern __shared__ char smem[];
    const uint32_t sb = smem_to_u32(smem);
    const int tid = threadIdx.x;
    const int wid = tid >> 5, lane = tid & 31;
    const int warpM = wid & 3, warpN = wid >> 2;           // 4 x 2 warp grid
    const size_t rowBase = (size_t)blockIdx.x * BM;
    const size_t colBase = (size_t)blockIdx.y * BN;

    const __nv_bfloat16* srcs[4] = {
        Ahi + rowBase * Kpad, Alo + rowBase * Kpad,
        Bhi + colBase * Kpad, Blo + colBase * Kpad
    };

    auto load_stage = [&](int ck, int st) {
        uint32_t base = sb + st * STAGE_B;
        #pragma unroll
        for (int i = 0; i < 8; i++) {
            int id = tid + i * 256;            // 0..2047
            int m  = id >> 9;                  // which array
            int v  = id & 511;
            int row = v >> 2, c = v & 3;       // 4 x 16B chunks per 64B row
            const char* g = (const char*)(srcs[m] + (size_t)row * Kpad + ck * BK) + c * 16;
            cp_async16(base + m * ARR_B + row * ASTRIDE + c * 16, g);
        }
        CP_COMMIT();
    };

    float acc[2][8][4];
    #pragma unroll
    for (int mt = 0; mt < 2; mt++)
        #pragma unroll
        for (int nt = 0; nt < 8; nt++)
            #pragma unroll
            for (int j = 0; j < 4; j++) acc[mt][nt][j] = 0.f;

    load_stage(0, 0);

    const int q = lane >> 3, r = lane & 7;

    for (int ck = 0; ck < NK; ck++) {
        CP_WAIT0();
        __syncthreads();
        if (ck + 1 < NK) load_stage(ck + 1, (ck + 1) & 1);

        const uint32_t st = sb + (ck & 1) * STAGE_B;
        #pragma unroll
        for (int ks = 0; ks < 2; ks++) {
            const int k0 = ks * 16;
            // A fragments: q0: m0 rows @k0; q1: m0+8 @k0; q2: m0 @k0+8; q3: m0+8 @k0+8
            uint32_t ah[2][4], al[2][4];
            #pragma unroll
            for (int mt = 0; mt < 2; mt++) {
                int row = warpM * 32 + mt * 16 + ((q & 1) ? 8 : 0) + r;
                int col = k0 + ((q & 2) ? 8 : 0);
                uint32_t a = st + row * ASTRIDE + col * 2;
                ldsm_x4(a, ah[mt]);
                ldsm_x4(a + ARR_B, al[mt]);
            }
            // B fragments: q0: n0 rows @k0; q1: n0 @k0+8; q2: n0+8 @k0; q3: n0+8 @k0+8
            #pragma unroll
            for (int nt2 = 0; nt2 < 4; nt2++) {
                int row = warpN * 64 + nt2 * 16 + ((q & 2) ? 8 : 0) + r;
                int col = k0 + ((q & 1) ? 8 : 0);
                uint32_t a = st + 2 * ARR_B + row * ASTRIDE + col * 2;
                uint32_t bh[4], bl[4];
                ldsm_x4(a, bh);
                ldsm_x4(a + ARR_B, bl);
                #pragma unroll
                for (int half = 0; half < 2; half++) {
                    const int nt = nt2 * 2 + half;
                    const uint32_t* bhp = bh + half * 2;
                    const uint32_t* blp = bl + half * 2;
                    #pragma unroll
                    for (int mt = 0; mt < 2; mt++) {
                        mma_bf16(acc[mt][nt], ah[mt], bhp);   // Ah*Bh
                        mma_bf16(acc[mt][nt], al[mt], bhp);   // Al*Bh
                        mma_bf16(acc[mt][nt], ah[mt], blp);   // Ah*Bl
                    }
                }
            }
        }
        __syncthreads();
    }

    // Epilogue: direct fp32 stores (float2 per half-tile)
    const int g2 = lane >> 2, ti = lane & 3;
    #pragma unroll
    for (int mt = 0; mt < 2; mt++) {
        size_t row = rowBase + warpM * 32 + mt * 16 + g2;
        #pragma unroll
        for (int nt = 0; nt < 8; nt++) {
            size_t col = colBase + warpN * 64 + nt * 8 + ti * 2;
            float2 v0 = make_float2(acc[mt][nt][0], acc[mt][nt][1]);
            float2 v1 = make_float2(acc[mt][nt][2], acc[mt][nt][3]);
            *(float2*)&C[row * Mout + col]       = v0;
            *(float2*)&C[(row + 8) * Mout + col] = v1;
        }
    }
}

// ===========================================================================
// Static adjacency
// ===========================================================================
__device__ __forceinline__ int get_srcs(int node, int* s)
{
    if (node == 0) {
        #pragma unroll
        for (int j = 0; j < 10; j++) s[j] = 1 + j;
        s[10] = 0;
        return 11;
    }
    if (node <= 10) { s[0] = 0; s[1] = node + 10; s[2] = node; return 3; }
    s[0] = node - 10; s[1] = node; return 2;
}

// ===========================================================================
// Kernel 4: GAT aggregate layer 1 (F=256) + bias + relu, writes y as bf16 hi/lo
// ===========================================================================
__global__ __launch_bounds__(256) void gat_agg1(
    const float* __restrict__ H,
    const float* __restrict__ asrc, const float* __restrict__ adst,
    const float* __restrict__ bias,
    __nv_bfloat16* __restrict__ Yhi, __nv_bfloat16* __restrict__ Ylo)
{
    __shared__ float hs[NPS][F_HID];
    __shared__ float sv[NPS], dv[NPS];
    __shared__ float alpha[NPS][11];

    const int b = blockIdx.x, tid = threadIdx.x;
    const size_t base = (size_t)b * NPS;
    const float* Hb = H + base * F_HID;

    #pragma unroll
    for (int r = 0; r < NPS; r++) hs[r][tid] = Hb[r * F_HID + tid];
    __syncthreads();

    const int wid = tid >> 5, lid = tid & 31;
    for (int node = wid; node < NPS; node += 8) {
        float ss = 0.f, dd = 0.f;
        #pragma unroll
        for (int c = lid; c < F_HID; c += 32) {
            float h = hs[node][c];
            ss = fmaf(h, asrc[c], ss);
            dd = fmaf(h, adst[c], dd);
        }
        #pragma unroll
        for (int o = 16; o; o >>= 1) {
            ss += __shfl_down_sync(0xffffffffu, ss, o);
            dd += __shfl_down_sync(0xffffffffu, dd, o);
        }
        if (lid == 0) { sv[node] = ss; dv[node] = dd; }
    }
    __syncthreads();

    if (tid < NPS) {
        int s[11]; int cnt = get_srcs(tid, s);
        float d = dv[tid];
        float e[11]; float m = -1e30f;
        for (int k = 0; k < cnt; k++) {
            float v = sv[s[k]] + d;
            v = v > 0.f ? v : 0.2f * v;
            e[k] = v; m = fmaxf(m, v);
        }
        float sum = 0.f;
        for (int k = 0; k < cnt; k++) { float t = expf(e[k] - m); e[k] = t; sum += t; }
        float inv = 1.f / sum;
        for (int k = 0; k < cnt; k++) alpha[tid][k] = e[k] * inv;
    }
    __syncthreads();

    const float bcol = bias[tid];
    __nv_bfloat16* Yh = Yhi + base * F_HID;
    __nv_bfloat16* Yl = Ylo + base * F_HID;
    #pragma unroll
    for (int node = 0; node < NPS; node++) {
        int s[11]; int cnt = get_srcs(node, s);
        float acc = 0.f;
        for (int k = 0; k < cnt; k++)
            acc = fmaf(alpha[node][k], hs[s[k]][tid], acc);
        float v = fmaxf(acc + bcol, 0.f);
        __nv_bfloat16 h = __float2bfloat16(v);
        Yh[node * F_HID + tid] = h;
        Yl[node * F_HID + tid] = __float2bfloat16(v - __bfloat162float(h));
    }
}

// ===========================================================================
// Kernel 5: GAT aggregate layer 2 (F=128) + bias -> hidden, fused head
// ===========================================================================
__global__ __launch_bounds__(128) void gat_agg2(
    const float* __restrict__ H,
    const float* __restrict__ asrc, const float* __restrict__ adst,
    const float* __restrict__ bias,
    const float* __restrict__ Wl, const float* __restrict__ bl,
    float* __restrict__ hid, float* __restrict__ yout)
{
    __shared__ float hs[NPS][F_OUT];
    __shared__ float os[NPS][F_OUT];
    __shared__ float sv[NPS], dv[NPS];
    __shared__ float alpha[NPS][11];

    const int b = blockIdx.x, tid = threadIdx.x;
    const size_t base = (size_t)b * NPS;
    const float* Hb = H + base * F_OUT;

    #pragma unroll
    for (int r = 0; r < NPS; r++) hs[r][tid] = Hb[r * F_OUT + tid];
    __syncthreads();

    const int wid = tid >> 5, lid = tid & 31;
    for (int node = wid; node < NPS; node += 4) {
        float ss = 0.f, dd = 0.f;
        #pragma unroll
        for (int c = lid; c < F_OUT; c += 32) {
            float h = hs[node][c];
            ss = fmaf(h, asrc[c], ss);
            dd = fmaf(h, adst[c], dd);
        }
        #pragma unroll
        for (int o = 16; o; o >>= 1) {
            ss += __shfl_down_sync(0xffffffffu, ss, o);
            dd += __shfl_down_sync(0xffffffffu, dd, o);
        }
        if (lid == 0) { sv[node] = ss; dv[node] = dd; }
    }
    __syncthreads();

    if (tid < NPS) {
        int s[11]; int cnt = get_srcs(tid, s);
        float d = dv[tid];
        float e[11]; float m = -1e30f;
        for (int k = 0; k < cnt; k++) {
            float v = sv[s[k]] + d;
            v = v > 0.f ? v : 0.2f * v;
            e[k] = v; m = fmaxf(m, v);
        }
        float sum = 0.f;
        for (int k = 0; k < cnt; k++) { float t = expf(e[k] - m); e[k] = t; sum += t; }
        float inv = 1.f / sum;
        for (int k = 0; k < cnt; k++) alpha[tid][k] = e[k] * inv;
    }
    __syncthreads();

    const float bcol = bias[tid];
    float* Hob = hid + base * F_OUT;
    #pragma unroll
    for (int node = 0; node < NPS; node++) {
        int s[11]; int cnt = get_srcs(node, s);
        float acc = 0.f;
        for (int k = 0; k < cnt; k++)
            acc = fmaf(alpha[node][k], hs[s[k]][tid], acc);
        float v = acc + bcol;
        Hob[node * F_OUT + tid] = v;
        os[node][tid] = fmaxf(v, 0.f);
    }
    __syncthreads();

    const float blv = bl[0];
    for (int node = wid; node < NPS; node += 4) {
        float p = 0.f;
        #pragma unroll
        for (int c = lid; c < F_OUT; c += 32)
            p = fmaf(os[node][c], Wl[c], p);
        #pragma unroll
        for (int o = 16; o; o >>= 1)
            p += __shfl_down_sync(0xffffffffu, p, o);
        if (lid == 0)
            yout[base + node] = 1.f / (1.f + expf(-(p + blv)));
    }
}

// ===========================================================================
extern "C" void kernel_launch(void* const* d_in, const int* in_sizes, int n_in,
                              void* d_out, int out_size)
{
    const float* x     = (const float*)d_in[1];
    const int*   click = (const int*)  d_in[4];
    const int*   query = (const int*)  d_in[5];
    const int*   docu  = (const int*)  d_in[6];
    const int*   title = (const int*)  d_in[7];
    const float* qtab  = (const float*)d_in[8];
    const float* dtab  = (const float*)d_in[9];
    const float* ttab  = (const float*)d_in[10];
    const float* ptab  = (const float*)d_in[11];
    const float* ctab  = (const float*)d_in[12];
    const float* W1    = (const float*)d_in[13];
    const float* as1   = (const float*)d_in[14];
    const float* ad1   = (const float*)d_in[15];
    const float* b1    = (const float*)d_in[16];
    const float* W2    = (const float*)d_in[17];
    const float* as2   = (const float*)d_in[18];
    const float* ad2   = (const float*)d_in[19];
    const float* b2    = (const float*)d_in[20];
    const float* Wl    = (const float*)d_in[21];
    const float* bl    = (const float*)d_in[22];

    float* out  = (float*)d_out;
    float* xout = out + OUT_X_OFF;
    float* hout = out + OUT_HID_OFF;
    float* yout = out + OUT_Y_OFF;

    float *h1p, *h2p;
    __nv_bfloat16 *xhi, *xlo, *yhi, *ylo, *w1hi, *w1lo, *w2hi, *w2lo;
    cudaGetSymbolAddress((void**)&h1p,  g_h1);
    cudaGetSymbolAddress((void**)&h2p,  g_h2);
    cudaGetSymbolAddress((void**)&xhi,  g_xhi);
    cudaGetSymbolAddress((void**)&xlo,  g_xlo);
    cudaGetSymbolAddress((void**)&yhi,  g_yhi);
    cudaGetSymbolAddress((void**)&ylo,  g_ylo);
    cudaGetSymbolAddress((void**)&w1hi, g_w1hi);
    cudaGetSymbolAddress((void**)&w1lo, g_w1lo);
    cudaGetSymbolAddress((void**)&w2hi, g_w2hi);
    cudaGetSymbolAddress((void**)&w2lo, g_w2lo);

    cudaFuncSetAttribute(mma_gemm, cudaFuncAttributeMaxDynamicSharedMemorySize, GEMM_SMEM);

    // 1. scatter embeddings into x output slice + fused bf16 hi/lo split
    {
        long long tot = (long long)N_NODES * K1_PAD;
        build_x_kernel<<<(unsigned)((tot + 255) / 256), 256>>>(
            x, click, query, docu, title, qtab, dtab, ttab, ptab, ctab,
            xout, xhi, xlo);
    }

    // 2. weight splits
    {
        long long tot = (long long)F_HID * K1_PAD;
        conv_split<<<(unsigned)((tot + 255) / 256), 256>>>(W1, F_IN, w1hi, w1lo, K1_PAD, tot);
    }
    {
        long long tot = (long long)F_OUT * F_HID;
        conv_split<<<(unsigned)((tot + 255) / 256), 256>>>(W2, F_HID, w2hi, w2lo, F_HID, tot);
    }

    // 3. h1 = x @ W1^T  (HMMA split-3 bf16)
    mma_gemm<<<dim3(N_NODES / BM, F_HID / BN), 256, GEMM_SMEM>>>(
        xhi, xlo, w1hi, w1lo, h1p, K1_PAD, K1_PAD / BK, F_HID);

    // 4. GAT aggregate 1 + relu -> y (bf16 hi/lo)
    gat_agg1<<<B_SESS, 256>>>(h1p, as1, ad1, b1, yhi, ylo);

    // 5. h2 = y @ W2^T
    mma_gemm<<<dim3(N_NODES / BM, F_OUT / BN), 256, GEMM_SMEM>>>(
        yhi, ylo, w2hi, w2lo, h2p, F_HID, F_HID / BK, F_OUT);

    // 6. GAT aggregate 2 + head
    gat_agg2<<<B_SESS, 128>>>(h2p, as2, ad2, b2, Wl, bl, hout, yout);
}

// round 4
// speedup vs baseline: 2.4364x; 1.2635x over previous
#include <cuda_runtime.h>
#include <cuda_bf16.h>
#include <math.h>
#include <stdint.h>

#define B_SESS   8192
#define NPS      21
#define N_NODES  (B_SESS * NPS)      // 172032
#define F_IN     171
#define K1_PAD   192                 // F_IN padded to 6*32
#define F_HID    256
#define F_OUT    128

// Output layout: hidden_state (N*128) | y (N*1) | x (N*171)
#define OUT_HID_OFF  0
#define OUT_Y_OFF    ((size_t)N_NODES * F_OUT)
#define OUT_X_OFF    ((size_t)N_NODES * (F_OUT + 1))

// Scratch (static device arrays: allocation-free)
__device__ float          g_h1[(size_t)N_NODES * F_HID];
__device__ float          g_h2[(size_t)N_NODES * F_OUT];
__device__ __nv_bfloat16  g_xhi[(size_t)N_NODES * K1_PAD];
__device__ __nv_bfloat16  g_xlo[(size_t)N_NODES * K1_PAD];
__device__ __nv_bfloat16  g_yhi[(size_t)N_NODES * F_HID];
__device__ __nv_bfloat16  g_ylo[(size_t)N_NODES * F_HID];
__device__ __nv_bfloat16  g_w1hi[(size_t)F_HID * K1_PAD];
__device__ __nv_bfloat16  g_w1lo[(size_t)F_HID * K1_PAD];
__device__ __nv_bfloat16  g_w2hi[(size_t)F_OUT * F_HID];
__device__ __nv_bfloat16  g_w2lo[(size_t)F_OUT * F_HID];

// ===========================================================================
// helpers (baseline PTX only: ldmatrix / mma.sync / cp.async)
// ===========================================================================
__device__ __forceinline__ uint32_t smem_to_u32(const void* p) {
    uint32_t a;
    asm("{ .reg .u64 t; cvta.to.shared.u64 t, %1; cvt.u32.u64 %0, t; }" : "=r"(a) : "l"(p));
    return a;
}
__device__ __forceinline__ void cp_async16(uint32_t dst, const void* src) {
    asm volatile("cp.async.cg.shared.global [%0], [%1], 16;" :: "r"(dst), "l"(src));
}
#define CP_COMMIT() asm volatile("cp.async.commit_group;" ::: "memory")
#define CP_WAIT0()  asm volatile("cp.async.wait_group 0;" ::: "memory")

__device__ __forceinline__ void ldsm_x4(uint32_t addr, uint32_t* r) {
    asm volatile("ldmatrix.sync.aligned.m8n8.x4.shared.b16 {%0,%1,%2,%3}, [%4];"
        : "=r"(r[0]), "=r"(r[1]), "=r"(r[2]), "=r"(r[3]) : "r"(addr));
}
__device__ __forceinline__ void mma_bf16(float* d, const uint32_t* a, const uint32_t* b) {
    asm volatile("mma.sync.aligned.m16n8k16.row.col.f32.bf16.bf16.f32 "
        "{%0,%1,%2,%3}, {%4,%5,%6,%7}, {%8,%9}, {%0,%1,%2,%3};"
        : "+f"(d[0]), "+f"(d[1]), "+f"(d[2]), "+f"(d[3])
        : "r"(a[0]), "r"(a[1]), "r"(a[2]), "r"(a[3]), "r"(b[0]), "r"(b[1]));
}

// ===========================================================================
// Kernel 1: build x_mod (scatter) + fused bf16 hi/lo split, 4 cols per thread
// ===========================================================================
__global__ __launch_bounds__(256) void build_x_kernel(
    const float* __restrict__ x,
    const int*   __restrict__ click,
    const int*   __restrict__ query,
    const int*   __restrict__ docu,
    const int*   __restrict__ title_id,
    const float* __restrict__ qtab,
    const float* __restrict__ dtab,
    const float* __restrict__ ttab,
    const float* __restrict__ ptab,
    const float* __restrict__ ctab,
    float* __restrict__ xout,
    __nv_bfloat16* __restrict__ xhi,
    __nv_bfloat16* __restrict__ xlo)
{
    long long t = (long long)blockIdx.x * blockDim.x + threadIdx.x;
    if (t >= (long long)N_NODES * (K1_PAD / 4)) return;
    int n  = (int)(t / (K1_PAD / 4));
    int cc = (int)(t - (long long)n * (K1_PAD / 4));
    int c0 = cc * 4;
    int b = n / NPS;
    int s = n - b * NPS;

    float4 v;
    if (c0 + 3 < 160) {
        // pure embedding region: vector gather
        const float* tab;
        size_t row;
        if (s == 0)            { tab = qtab; row = (size_t)query[b]; }
        else if (s <= 10)      { tab = dtab; row = (size_t)docu[b * 10 + (s - 1)]; }
        else                   { tab = ttab; row = (size_t)title_id[b * 10 + (s - 11)]; }
        v = *(const float4*)(tab + row * 160 + c0);
    } else {
        float vv[4];
        #pragma unroll
        for (int j = 0; j < 4; j++) {
            int c = c0 + j;
            float val = 0.f;
            if (c < F_IN) {
                long long xi = (long long)n * F_IN + c;
                if (s == 0) {
                    val = (c < 160) ? qtab[(size_t)query[b] * 160 + c] : x[xi];
                } else if (s <= 10) {
                    int jj = s - 1;
                    if      (c < 160)  val = dtab[(size_t)docu[b * 10 + jj] * 160 + c];
                    else if (c == 160) val = ptab[jj];
                    else if (c == 161) val = ctab[click[b]];
                    else               val = x[xi];
                } else {
                    val = (c < 160) ? ttab[(size_t)title_id[b * 10 + (s - 11)] * 160 + c] : x[xi];
                }
            }
            vv[j] = val;
        }
        v = make_float4(vv[0], vv[1], vv[2], vv[3]);
    }

    // write xout (scalar — row length 171 breaks alignment)
    {
        long long xi = (long long)n * F_IN + c0;
        if (c0 + 3 < F_IN) {
            xout[xi] = v.x; xout[xi + 1] = v.y; xout[xi + 2] = v.z; xout[xi + 3] = v.w;
        } else {
            float vv[4] = {v.x, v.y, v.z, v.w};
            #pragma unroll
            for (int j = 0; j < 4; j++)
                if (c0 + j < F_IN) xout[xi + j] = vv[j];
        }
    }

    // hi/lo split, 8B vector stores
    long long oi = (long long)n * K1_PAD + c0;
    __nv_bfloat162 h01, h23, l01, l23;
    {
        float vv[4] = {v.x, v.y, v.z, v.w};
        __nv_bfloat16 h[4], l[4];
        #pragma unroll
        for (int j = 0; j < 4; j++) {
            h[j] = __float2bfloat16(vv[j]);
            l[j] = __float2bfloat16(vv[j] - __bfloat162float(h[j]));
        }
        h01 = __nv_bfloat162(h[0], h[1]); h23 = __nv_bfloat162(h[2], h[3]);
        l01 = __nv_bfloat162(l[0], l[1]); l23 = __nv_bfloat162(l[2], l[3]);
    }
    *(__nv_bfloat162*)(xhi + oi)     = h01;
    *(__nv_bfloat162*)(xhi + oi + 2) = h23;
    *(__nv_bfloat162*)(xlo + oi)     = l01;
    *(__nv_bfloat162*)(xlo + oi + 2) = l23;
}

// ===========================================================================
// Kernel 2: fp32 -> bf16 hi/lo split for weights (with K padding)
// ===========================================================================
__global__ __launch_bounds__(256) void conv_split(
    const float* __restrict__ src, int Ksrc,
    __nv_bfloat16* __restrict__ hi, __nv_bfloat16* __restrict__ lo,
    int Kdst, long long total)
{
    long long idx = (long long)blockIdx.x * blockDim.x + threadIdx.x;
    if (idx >= total) return;
    long long row = idx / Kdst;
    int c = (int)(idx - row * Kdst);
    float v = (c < Ksrc) ? src[row * Ksrc + c] : 0.f;
    __nv_bfloat16 h = __float2bfloat16(v);
    hi[idx] = h;
    lo[idx] = __float2bfloat16(v - __bfloat162float(h));
}

// ===========================================================================
// Kernel 3: HMMA bf16 split-3 GEMM.  C[row][m] = sum_k A[row][k]*W[m][k]
// 128x128x32 tiles, 8 warps (32x64 each), double-buffered cp.async.
// blockIdx.x = COL block, blockIdx.y = ROW block (A-tile L2 reuse).
// ===========================================================================
#define BM 128
#define BN 128
#define BK 32
#define ASTRIDE 80                        // 64B data + 16B pad: conflict-free ldmatrix
#define ARR_B   (128 * ASTRIDE)           // 10240 per array
#define STAGE_B (4 * ARR_B)               // 40960: Ah, Al, Bh, Bl
#define GEMM_SMEM (2 * STAGE_B)           // 81920

__global__ __launch_bounds__(256, 2) void mma_gemm(
    const __nv_bfloat16* __restrict__ Ahi, const __nv_bfloat16* __restrict__ Alo,
    const __nv_bfloat16* __restrict__ Bhi, const __nv_bfloat16* __restrict__ Blo,
    float* __restrict__ C, int Kpad, int NK, int Mout)
{
    extern __shared__ char smem[];
    const uint32_t sb = smem_to_u32(smem);
    const int tid = threadIdx.x;
    const int wid = tid >> 5, lane = tid & 31;
    const int warpM = wid & 3, warpN = wid >> 2;           // 4 x 2 warp grid
    const size_t rowBase = (size_t)blockIdx.y * BM;
    const size_t colBase = (size_t)blockIdx.x * BN;

    const __nv_bfloat16* srcs[4] = {
        Ahi + rowBase * Kpad, Alo + rowBase * Kpad,
        Bhi + colBase * Kpad, Blo + colBase * Kpad
    };

    auto load_stage = [&](int ck, int st) {
        uint32_t base = sb + st * STAGE_B;
        #pragma unroll
        for (int i = 0; i < 8; i++) {
            int id = tid + i * 256;            // 0..2047
            int m  = id >> 9;                  // which array
            int v  = id & 511;
            int row = v >> 2, c = v & 3;       // 4 x 16B chunks per 64B row
            const char* g = (const char*)(srcs[m] + (size_t)row * Kpad + ck * BK) + c * 16;
            cp_async16(base + m * ARR_B + row * ASTRIDE + c * 16, g);
        }
        CP_COMMIT();
    };

    float acc[2][8][4];
    #pragma unroll
    for (int mt = 0; mt < 2; mt++)
        #pragma unroll
        for (int nt = 0; nt < 8; nt++)
            #pragma unroll
            for (int j = 0; j < 4; j++) acc[mt][nt][j] = 0.f;

    load_stage(0, 0);

    const int q = lane >> 3, r = lane & 7;

    for (int ck = 0; ck < NK; ck++) {
        CP_WAIT0();
        __syncthreads();
        if (ck + 1 < NK) load_stage(ck + 1, (ck + 1) & 1);

        const uint32_t st = sb + (ck & 1) * STAGE_B;
        #pragma unroll
        for (int ks = 0; ks < 2; ks++) {
            const int k0 = ks * 16;
            uint32_t ah[2][4], al[2][4];
            #pragma unroll
            for (int mt = 0; mt < 2; mt++) {
                int row = warpM * 32 + mt * 16 + ((q & 1) ? 8 : 0) + r;
                int col = k0 + ((q & 2) ? 8 : 0);
                uint32_t a = st + row * ASTRIDE + col * 2;
                ldsm_x4(a, ah[mt]);
                ldsm_x4(a + ARR_B, al[mt]);
            }
            #pragma unroll
            for (int nt2 = 0; nt2 < 4; nt2++) {
                int row = warpN * 64 + nt2 * 16 + ((q & 2) ? 8 : 0) + r;
                int col = k0 + ((q & 1) ? 8 : 0);
                uint32_t a = st + 2 * ARR_B + row * ASTRIDE + col * 2;
                uint32_t bh[4], bl[4];
                ldsm_x4(a, bh);
                ldsm_x4(a + ARR_B, bl);
                #pragma unroll
                for (int half = 0; half < 2; half++) {
                    const int nt = nt2 * 2 + half;
                    const uint32_t* bhp = bh + half * 2;
                    const uint32_t* blp = bl + half * 2;
                    #pragma unroll
                    for (int mt = 0; mt < 2; mt++) {
                        mma_bf16(acc[mt][nt], ah[mt], bhp);   // Ah*Bh
                        mma_bf16(acc[mt][nt], al[mt], bhp);   // Al*Bh
                        mma_bf16(acc[mt][nt], ah[mt], blp);   // Ah*Bl
                    }
                }
            }
        }
        __syncthreads();
    }

    // Epilogue: direct fp32 stores (float2 per half-tile)
    const int g2 = lane >> 2, ti = lane & 3;
    #pragma unroll
    for (int mt = 0; mt < 2; mt++) {
        size_t row = rowBase + warpM * 32 + mt * 16 + g2;
        #pragma unroll
        for (int nt = 0; nt < 8; nt++) {
            size_t col = colBase + warpN * 64 + nt * 8 + ti * 2;
            float2 v0 = make_float2(acc[mt][nt][0], acc[mt][nt][1]);
            float2 v1 = make_float2(acc[mt][nt][2], acc[mt][nt][3]);
            *(float2*)&C[row * Mout + col]       = v0;
            *(float2*)&C[(row + 8) * Mout + col] = v1;
        }
    }
}

// ===========================================================================
// Static adjacency
// ===========================================================================
__device__ __forceinline__ int get_srcs(int node, int* s)
{
    if (node == 0) {
        #pragma unroll
        for (int j = 0; j < 10; j++) s[j] = 1 + j;
        s[10] = 0;
        return 11;
    }
    if (node <= 10) { s[0] = 0; s[1] = node + 10; s[2] = node; return 3; }
    s[0] = node - 10; s[1] = node; return 2;
}

// ===========================================================================
// Kernel 4: GAT aggregate layer 1 (F=256) + bias + relu, writes y as bf16 hi/lo
// ===========================================================================
__global__ __launch_bounds__(256) void gat_agg1(
    const float* __restrict__ H,
    const float* __restrict__ asrc, const float* __restrict__ adst,
    const float* __restrict__ bias,
    __nv_bfloat16* __restrict__ Yhi, __nv_bfloat16* __restrict__ Ylo)
{
    __shared__ float hs[NPS][F_HID];
    __shared__ float sv[NPS], dv[NPS];
    __shared__ float alpha[NPS][11];

    const int b = blockIdx.x, tid = threadIdx.x;
    const size_t base = (size_t)b * NPS;
    const float* Hb = H + base * F_HID;

    #pragma unroll
    for (int r = 0; r < NPS; r++) hs[r][tid] = Hb[r * F_HID + tid];
    __syncthreads();

    const int wid = tid >> 5, lid = tid & 31;
    for (int node = wid; node < NPS; node += 8) {
        float ss = 0.f, dd = 0.f;
        #pragma unroll
        for (int c = lid; c < F_HID; c += 32) {
            float h = hs[node][c];
            ss = fmaf(h, asrc[c], ss);
            dd = fmaf(h, adst[c], dd);
        }
        #pragma unroll
        for (int o = 16; o; o >>= 1) {
            ss += __shfl_down_sync(0xffffffffu, ss, o);
            dd += __shfl_down_sync(0xffffffffu, dd, o);
        }
        if (lid == 0) { sv[node] = ss; dv[node] = dd; }
    }
    __syncthreads();

    if (tid < NPS) {
        int s[11]; int cnt = get_srcs(tid, s);
        float d = dv[tid];
        float e[11]; float m = -1e30f;
        for (int k = 0; k < cnt; k++) {
            float v = sv[s[k]] + d;
            v = v > 0.f ? v : 0.2f * v;
            e[k] = v; m = fmaxf(m, v);
        }
        float sum = 0.f;
        for (int k = 0; k < cnt; k++) { float t = expf(e[k] - m); e[k] = t; sum += t; }
        float inv = 1.f / sum;
        for (int k = 0; k < cnt; k++) alpha[tid][k] = e[k] * inv;
    }
    __syncthreads();

    const float bcol = bias[tid];
    __nv_bfloat16* Yh = Yhi + base * F_HID;
    __nv_bfloat16* Yl = Ylo + base * F_HID;
    #pragma unroll
    for (int node = 0; node < NPS; node++) {
        int s[11]; int cnt = get_srcs(node, s);
        float acc = 0.f;
        for (int k = 0; k < cnt; k++)
            acc = fmaf(alpha[node][k], hs[s[k]][tid], acc);
        float v = fmaxf(acc + bcol, 0.f);
        __nv_bfloat16 h = __float2bfloat16(v);
        Yh[node * F_HID + tid] = h;
        Yl[node * F_HID + tid] = __float2bfloat16(v - __bfloat162float(h));
    }
}

// ===========================================================================
// Kernel 5: GAT aggregate layer 2 (F=128) + bias -> hidden, fused head
// ===========================================================================
__global__ __launch_bounds__(128) void gat_agg2(
    const float* __restrict__ H,
    const float* __restrict__ asrc, const float* __restrict__ adst,
    const float* __restrict__ bias,
    const float* __restrict__ Wl, const float* __restrict__ bl,
    float* __restrict__ hid, float* __restrict__ yout)
{
    __shared__ float hs[NPS][F_OUT];
    __shared__ float os[NPS][F_OUT];
    __shared__ float sv[NPS], dv[NPS];
    __shared__ float alpha[NPS][11];

    const int b = blockIdx.x, tid = threadIdx.x;
    const size_t base = (size_t)b * NPS;
    const float* Hb = H + base * F_OUT;

    #pragma unroll
    for (int r = 0; r < NPS; r++) hs[r][tid] = Hb[r * F_OUT + tid];
    __syncthreads();

    const int wid = tid >> 5, lid = tid & 31;
    for (int node = wid; node < NPS; node += 4) {
        float ss = 0.f, dd = 0.f;
        #pragma unroll
        for (int c = lid; c < F_OUT; c += 32) {
            float h = hs[node][c];
            ss = fmaf(h, asrc[c], ss);
            dd = fmaf(h, adst[c], dd);
        }
        #pragma unroll
        for (int o = 16; o; o >>= 1) {
            ss += __shfl_down_sync(0xffffffffu, ss, o);
            dd += __shfl_down_sync(0xffffffffu, dd, o);
        }
        if (lid == 0) { sv[node] = ss; dv[node] = dd; }
    }
    __syncthreads();

    if (tid < NPS) {
        int s[11]; int cnt = get_srcs(tid, s);
        float d = dv[tid];
        float e[11]; float m = -1e30f;
        for (int k = 0; k < cnt; k++) {
            float v = sv[s[k]] + d;
            v = v > 0.f ? v : 0.2f * v;
            e[k] = v; m = fmaxf(m, v);
        }
        float sum = 0.f;
        for (int k = 0; k < cnt; k++) { float t = expf(e[k] - m); e[k] = t; sum += t; }
        float inv = 1.f / sum;
        for (int k = 0; k < cnt; k++) alpha[tid][k] = e[k] * inv;
    }
    __syncthreads();

    const float bcol = bias[tid];
    float* Hob = hid + base * F_OUT;
    #pragma unroll
    for (int node = 0; node < NPS; node++) {
        int s[11]; int cnt = get_srcs(node, s);
        float acc = 0.f;
        for (int k = 0; k < cnt; k++)
            acc = fmaf(alpha[node][k], hs[s[k]][tid], acc);
        float v = acc + bcol;
        Hob[node * F_OUT + tid] = v;
        os[node][tid] = fmaxf(v, 0.f);
    }
    __syncthreads();

    const float blv = bl[0];
    for (int node = wid; node < NPS; node += 4) {
        float p = 0.f;
        #pragma unroll
        for (int c = lid; c < F_OUT; c += 32)
            p = fmaf(os[node][c], Wl[c], p);
        #pragma unroll
        for (int o = 16; o; o >>= 1)
            p += __shfl_down_sync(0xffffffffu, p, o);
        if (lid == 0)
            yout[base + node] = 1.f / (1.f + expf(-(p + blv)));
    }
}

// ===========================================================================
extern "C" void kernel_launch(void* const* d_in, const int* in_sizes, int n_in,
                              void* d_out, int out_size)
{
    const float* x     = (const float*)d_in[1];
    const int*   click = (const int*)  d_in[4];
    const int*   query = (const int*)  d_in[5];
    const int*   docu  = (const int*)  d_in[6];
    const int*   title = (const int*)  d_in[7];
    const float* qtab  = (const float*)d_in[8];
    const float* dtab  = (const float*)d_in[9];
    const float* ttab  = (const float*)d_in[10];
    const float* ptab  = (const float*)d_in[11];
    const float* ctab  = (const float*)d_in[12];
    const float* W1    = (const float*)d_in[13];
    const float* as1   = (const float*)d_in[14];
    const float* ad1   = (const float*)d_in[15];
    const float* b1    = (const float*)d_in[16];
    const float* W2    = (const float*)d_in[17];
    const float* as2   = (const float*)d_in[18];
    const float* ad2   = (const float*)d_in[19];
    const float* b2    = (const float*)d_in[20];
    const float* Wl    = (const float*)d_in[21];
    const float* bl    = (const float*)d_in[22];

    float* out  = (float*)d_out;
    float* xout = out + OUT_X_OFF;
    float* hout = out + OUT_HID_OFF;
    float* yout = out + OUT_Y_OFF;

    float *h1p, *h2p;
    __nv_bfloat16 *xhi, *xlo, *yhi, *ylo, *w1hi, *w1lo, *w2hi, *w2lo;
    cudaGetSymbolAddress((void**)&h1p,  g_h1);
    cudaGetSymbolAddress((void**)&h2p,  g_h2);
    cudaGetSymbolAddress((void**)&xhi,  g_xhi);
    cudaGetSymbolAddress((void**)&xlo,  g_xlo);
    cudaGetSymbolAddress((void**)&yhi,  g_yhi);
    cudaGetSymbolAddress((void**)&ylo,  g_ylo);
    cudaGetSymbolAddress((void**)&w1hi, g_w1hi);
    cudaGetSymbolAddress((void**)&w1lo, g_w1lo);
    cudaGetSymbolAddress((void**)&w2hi, g_w2hi);
    cudaGetSymbolAddress((void**)&w2lo, g_w2lo);

    cudaFuncSetAttribute(mma_gemm, cudaFuncAttributeMaxDynamicSharedMemorySize, GEMM_SMEM);

    // 1. scatter embeddings into x output slice + fused bf16 hi/lo split
    {
        long long tot = (long long)N_NODES * (K1_PAD / 4);
        build_x_kernel<<<(unsigned)((tot + 255) / 256), 256>>>(
            x, click, query, docu, title, qtab, dtab, ttab, ptab, ctab,
            xout, xhi, xlo);
    }

    // 2. weight splits
    {
        long long tot = (long long)F_HID * K1_PAD;
        conv_split<<<(unsigned)((tot + 255) / 256), 256>>>(W1, F_IN, w1hi, w1lo, K1_PAD, tot);
    }
    {
        long long tot = (long long)F_OUT * F_HID;
        conv_split<<<(unsigned)((tot + 255) / 256), 256>>>(W2, F_HID, w2hi, w2lo, F_HID, tot);
    }

    // 3. h1 = x @ W1^T  (HMMA split-3 bf16); grid.x = col blocks for A L2 reuse
    mma_gemm<<<dim3(F_HID / BN, N_NODES / BM), 256, GEMM_SMEM>>>(
        xhi, xlo, w1hi, w1lo, h1p, K1_PAD, K1_PAD / BK, F_HID);

    // 4. GAT aggregate 1 + relu -> y (bf16 hi/lo)
    gat_agg1<<<B_SESS, 256>>>(h1p, as1, ad1, b1, yhi, ylo);

    // 5. h2 = y @ W2^T
    mma_gemm<<<dim3(F_OUT / BN, N_NODES / BM), 256, GEMM_SMEM>>>(
        yhi, ylo, w2hi, w2lo, h2p, F_HID, F_HID / BK, F_OUT);

    // 6. GAT aggregate 2 + head
    gat_agg2<<<B_SESS, 128>>>(h2p, as2, ad2, b2, Wl, bl, hout, yout);
}

// round 5
// speedup vs baseline: 2.5639x; 1.0523x over previous
#include <cuda_runtime.h>
#include <cuda_bf16.h>
#include <math.h>
#include <stdint.h>

#define B_SESS   8192
#define NPS      21
#define N_NODES  (B_SESS * NPS)      // 172032
#define F_IN     171
#define K1_PAD   192                 // F_IN padded to 6*32
#define F_HID    256
#define F_OUT    128

// Output layout: hidden_state (N*128) | y (N*1) | x (N*171)
#define OUT_HID_OFF  0
#define OUT_Y_OFF    ((size_t)N_NODES * F_OUT)
#define OUT_X_OFF    ((size_t)N_NODES * (F_OUT + 1))

// Scratch (static device arrays: allocation-free)
__device__ float          g_h1[(size_t)N_NODES * F_HID];
__device__ float          g_h2[(size_t)N_NODES * F_OUT];
__device__ __nv_bfloat16  g_xhi[(size_t)N_NODES * K1_PAD];
__device__ __nv_bfloat16  g_xlo[(size_t)N_NODES * K1_PAD];
__device__ __nv_bfloat16  g_yhi[(size_t)N_NODES * F_HID];
__device__ __nv_bfloat16  g_ylo[(size_t)N_NODES * F_HID];
__device__ __nv_bfloat16  g_w1hi[(size_t)F_HID * K1_PAD];
__device__ __nv_bfloat16  g_w1lo[(size_t)F_HID * K1_PAD];
__device__ __nv_bfloat16  g_w2hi[(size_t)F_OUT * F_HID];
__device__ __nv_bfloat16  g_w2lo[(size_t)F_OUT * F_HID];

// ===========================================================================
// helpers (baseline PTX only: ldmatrix / mma.sync / cp.async)
// ===========================================================================
__device__ __forceinline__ uint32_t smem_to_u32(const void* p) {
    uint32_t a;
    asm("{ .reg .u64 t; cvta.to.shared.u64 t, %1; cvt.u32.u64 %0, t; }" : "=r"(a) : "l"(p));
    return a;
}
__device__ __forceinline__ void cp_async16(uint32_t dst, const void* src) {
    asm volatile("cp.async.cg.shared.global [%0], [%1], 16;" :: "r"(dst), "l"(src));
}
#define CP_COMMIT() asm volatile("cp.async.commit_group;" ::: "memory")
#define CP_WAIT0()  asm volatile("cp.async.wait_group 0;" ::: "memory")

__device__ __forceinline__ void ldsm_x4(uint32_t addr, uint32_t* r) {
    asm volatile("ldmatrix.sync.aligned.m8n8.x4.shared.b16 {%0,%1,%2,%3}, [%4];"
        : "=r"(r[0]), "=r"(r[1]), "=r"(r[2]), "=r"(r[3]) : "r"(addr));
}
__device__ __forceinline__ void mma_bf16(float* d, const uint32_t* a, const uint32_t* b) {
    asm volatile("mma.sync.aligned.m16n8k16.row.col.f32.bf16.bf16.f32 "
        "{%0,%1,%2,%3}, {%4,%5,%6,%7}, {%8,%9}, {%0,%1,%2,%3};"
        : "+f"(d[0]), "+f"(d[1]), "+f"(d[2]), "+f"(d[3])
        : "r"(a[0]), "r"(a[1]), "r"(a[2]), "r"(a[3]), "r"(b[0]), "r"(b[1]));
}

// ===========================================================================
// Kernel 1: build x_mod (scatter) + fused bf16 hi/lo split, 4 cols per thread
// ===========================================================================
__global__ __launch_bounds__(256) void build_x_kernel(
    const float* __restrict__ x,
    const int*   __restrict__ click,
    const int*   __restrict__ query,
    const int*   __restrict__ docu,
    const int*   __restrict__ title_id,
    const float* __restrict__ qtab,
    const float* __restrict__ dtab,
    const float* __restrict__ ttab,
    const float* __restrict__ ptab,
    const float* __restrict__ ctab,
    float* __restrict__ xout,
    __nv_bfloat16* __restrict__ xhi,
    __nv_bfloat16* __restrict__ xlo)
{
    long long t = (long long)blockIdx.x * blockDim.x + threadIdx.x;
    if (t >= (long long)N_NODES * (K1_PAD / 4)) return;
    int n  = (int)(t / (K1_PAD / 4));
    int cc = (int)(t - (long long)n * (K1_PAD / 4));
    int c0 = cc * 4;
    int b = n / NPS;
    int s = n - b * NPS;

    float4 v;
    if (c0 + 3 < 160) {
        const float* tab;
        size_t row;
        if (s == 0)            { tab = qtab; row = (size_t)query[b]; }
        else if (s <= 10)      { tab = dtab; row = (size_t)docu[b * 10 + (s - 1)]; }
        else                   { tab = ttab; row = (size_t)title_id[b * 10 + (s - 11)]; }
        v = *(const float4*)(tab + row * 160 + c0);
    } else {
        float vv[4];
        #pragma unroll
        for (int j = 0; j < 4; j++) {
            int c = c0 + j;
            float val = 0.f;
            if (c < F_IN) {
                long long xi = (long long)n * F_IN + c;
                if (s == 0) {
                    val = (c < 160) ? qtab[(size_t)query[b] * 160 + c] : x[xi];
                } else if (s <= 10) {
                    int jj = s - 1;
                    if      (c < 160)  val = dtab[(size_t)docu[b * 10 + jj] * 160 + c];
                    else if (c == 160) val = ptab[jj];
                    else if (c == 161) val = ctab[click[b]];
                    else               val = x[xi];
                } else {
                    val = (c < 160) ? ttab[(size_t)title_id[b * 10 + (s - 11)] * 160 + c] : x[xi];
                }
            }
            vv[j] = val;
        }
        v = make_float4(vv[0], vv[1], vv[2], vv[3]);
    }

    {
        long long xi = (long long)n * F_IN + c0;
        if (c0 + 3 < F_IN) {
            xout[xi] = v.x; xout[xi + 1] = v.y; xout[xi + 2] = v.z; xout[xi + 3] = v.w;
        } else {
            float vv[4] = {v.x, v.y, v.z, v.w};
            #pragma unroll
            for (int j = 0; j < 4; j++)
                if (c0 + j < F_IN) xout[xi + j] = vv[j];
        }
    }

    long long oi = (long long)n * K1_PAD + c0;
    __nv_bfloat162 h01, h23, l01, l23;
    {
        float vv[4] = {v.x, v.y, v.z, v.w};
        __nv_bfloat16 h[4], l[4];
        #pragma unroll
        for (int j = 0; j < 4; j++) {
            h[j] = __float2bfloat16(vv[j]);
            l[j] = __float2bfloat16(vv[j] - __bfloat162float(h[j]));
        }
        h01 = __nv_bfloat162(h[0], h[1]); h23 = __nv_bfloat162(h[2], h[3]);
        l01 = __nv_bfloat162(l[0], l[1]); l23 = __nv_bfloat162(l[2], l[3]);
    }
    *(__nv_bfloat162*)(xhi + oi)     = h01;
    *(__nv_bfloat162*)(xhi + oi + 2) = h23;
    *(__nv_bfloat162*)(xlo + oi)     = l01;
    *(__nv_bfloat162*)(xlo + oi + 2) = l23;
}

// ===========================================================================
// Kernel 2: fp32 -> bf16 hi/lo split for weights (with K padding)
// ===========================================================================
__global__ __launch_bounds__(256) void conv_split(
    const float* __restrict__ src, int Ksrc,
    __nv_bfloat16* __restrict__ hi, __nv_bfloat16* __restrict__ lo,
    int Kdst, long long total)
{
    long long idx = (long long)blockIdx.x * blockDim.x + threadIdx.x;
    if (idx >= total) return;
    long long row = idx / Kdst;
    int c = (int)(idx - row * Kdst);
    float v = (c < Ksrc) ? src[row * Ksrc + c] : 0.f;
    __nv_bfloat16 h = __float2bfloat16(v);
    hi[idx] = h;
    lo[idx] = __float2bfloat16(v - __bfloat162float(h));
}

// ===========================================================================
// Kernel 3: HMMA bf16 split-3 GEMM (templated: full mainloop unroll)
// 128x128x32 tiles, 8 warps (32x64 each), double-buffered cp.async, 1 sync/it
// ===========================================================================
#define BM 128
#define BN 128
#define BK 32
#define ASTRIDE 80                        // 64B data + 16B pad: conflict-free ldmatrix
#define ARR_B   (128 * ASTRIDE)           // 10240 per array
#define STAGE_B (4 * ARR_B)               // 40960: Ah, Al, Bh, Bl
#define GEMM_SMEM (2 * STAGE_B)           // 81920

template<int NK, int KPAD, int MOUT>
__global__ __launch_bounds__(256, 2) void mma_gemm(
    const __nv_bfloat16* __restrict__ Ahi, const __nv_bfloat16* __restrict__ Alo,
    const __nv_bfloat16* __restrict__ Bhi, const __nv_bfloat16* __restrict__ Blo,
    float* __restrict__ C)
{
    extern __shared__ char smem[];
    const uint32_t sb = smem_to_u32(smem);
    const int tid = threadIdx.x;
    const int wid = tid >> 5, lane = tid & 31;
    const int warpM = wid & 3, warpN = wid >> 2;           // 4 x 2 warp grid
    const size_t rowBase = (size_t)blockIdx.y * BM;
    const size_t colBase = (size_t)blockIdx.x * BN;

    const __nv_bfloat16* srcs[4] = {
        Ahi + rowBase * KPAD, Alo + rowBase * KPAD,
        Bhi + colBase * KPAD, Blo + colBase * KPAD
    };

    auto load_stage = [&](int ck, int st) {
        uint32_t base = sb + st * STAGE_B;
        #pragma unroll
        for (int i = 0; i < 8; i++) {
            int id = tid + i * 256;            // 0..2047
            int m  = id >> 9;                  // which array
            int v  = id & 511;
            int row = v >> 2, c = v & 3;       // 4 x 16B chunks per 64B row
            const char* g = (const char*)(srcs[m] + (size_t)row * KPAD + ck * BK) + c * 16;
            cp_async16(base + m * ARR_B + row * ASTRIDE + c * 16, g);
        }
        CP_COMMIT();
    };

    float acc[2][8][4];
    #pragma unroll
    for (int mt = 0; mt < 2; mt++)
        #pragma unroll
        for (int nt = 0; nt < 8; nt++)
            #pragma unroll
            for (int j = 0; j < 4; j++) acc[mt][nt][j] = 0.f;

    load_stage(0, 0);

    const int q = lane >> 3, r = lane & 7;
    const int aRowBase = warpM * 32 + ((q & 1) ? 8 : 0) + r;
    const int aColSel  = (q & 2) ? 8 : 0;
    const int bRowBase = warpN * 64 + ((q & 2) ? 8 : 0) + r;
    const int bColSel  = (q & 1) ? 8 : 0;

    #pragma unroll
    for (int ck = 0; ck < NK; ck++) {
        CP_WAIT0();
        __syncthreads();                     // single barrier per iteration
        if (ck + 1 < NK) load_stage(ck + 1, (ck + 1) & 1);

        const uint32_t st = sb + (ck & 1) * STAGE_B;
        #pragma unroll
        for (int ks = 0; ks < 2; ks++) {
            const int k0 = ks * 16;
            uint32_t ah[2][4], al[2][4];
            #pragma unroll
            for (int mt = 0; mt < 2; mt++) {
                uint32_t a = st + (aRowBase + mt * 16) * ASTRIDE + (k0 + aColSel) * 2;
                ldsm_x4(a, ah[mt]);
                ldsm_x4(a + ARR_B, al[mt]);
            }
            #pragma unroll
            for (int nt2 = 0; nt2 < 4; nt2++) {
                uint32_t a = st + 2 * ARR_B + (bRowBase + nt2 * 16) * ASTRIDE + (k0 + bColSel) * 2;
                uint32_t bh[4], bl[4];
                ldsm_x4(a, bh);
                ldsm_x4(a + ARR_B, bl);
                #pragma unroll
                for (int half = 0; half < 2; half++) {
                    const int nt = nt2 * 2 + half;
                    const uint32_t* bhp = bh + half * 2;
                    const uint32_t* blp = bl + half * 2;
                    // product-major order: same-acc MMA distance = 2
                    mma_bf16(acc[0][nt], ah[0], bhp);
                    mma_bf16(acc[1][nt], ah[1], bhp);
                    mma_bf16(acc[0][nt], al[0], bhp);
                    mma_bf16(acc[1][nt], al[1], bhp);
                    mma_bf16(acc[0][nt], ah[0], blp);
                    mma_bf16(acc[1][nt], ah[1], blp);
                }
            }
        }
    }

    // Epilogue: direct fp32 stores (float2 per half-tile)
    const int g2 = lane >> 2, ti = lane & 3;
    #pragma unroll
    for (int mt = 0; mt < 2; mt++) {
        size_t row = rowBase + warpM * 32 + mt * 16 + g2;
        #pragma unroll
        for (int nt = 0; nt < 8; nt++) {
            size_t col = colBase + warpN * 64 + nt * 8 + ti * 2;
            float2 v0 = make_float2(acc[mt][nt][0], acc[mt][nt][1]);
            float2 v1 = make_float2(acc[mt][nt][2], acc[mt][nt][3]);
            *(float2*)&C[row * MOUT + col]       = v0;
            *(float2*)&C[(row + 8) * MOUT + col] = v1;
        }
    }
}

// ===========================================================================
// Static adjacency
// ===========================================================================
__device__ __forceinline__ int get_srcs(int node, int* s)
{
    if (node == 0) {
        #pragma unroll
        for (int j = 0; j < 10; j++) s[j] = 1 + j;
        s[10] = 0;
        return 11;
    }
    if (node <= 10) { s[0] = 0; s[1] = node + 10; s[2] = node; return 3; }
    s[0] = node - 10; s[1] = node; return 2;
}

// ===========================================================================
// Kernel 4: GAT aggregate layer 1 (F=256) + bias + relu, writes y as bf16 hi/lo
// ===========================================================================
__global__ __launch_bounds__(256) void gat_agg1(
    const float* __restrict__ H,
    const float* __restrict__ asrc, const float* __restrict__ adst,
    const float* __restrict__ bias,
    __nv_bfloat16* __restrict__ Yhi, __nv_bfloat16* __restrict__ Ylo)
{
    __shared__ float hs[NPS][F_HID];
    __shared__ float sv[NPS], dv[NPS];
    __shared__ float alpha[NPS][11];

    const int b = blockIdx.x, tid = threadIdx.x;
    const size_t base = (size_t)b * NPS;
    const float* Hb = H + base * F_HID;

    // vectorized tile load: 21*64 float4
    #pragma unroll
    for (int i = tid; i < NPS * (F_HID / 4); i += 256) {
        int row = i >> 6, c = i & 63;
        ((float4*)hs[row])[c] = ((const float4*)(Hb + row * F_HID))[c];
    }
    __syncthreads();

    const int wid = tid >> 5, lid = tid & 31;
    for (int node = wid; node < NPS; node += 8) {
        float ss = 0.f, dd = 0.f;
        #pragma unroll
        for (int c = lid; c < F_HID; c += 32) {
            float h = hs[node][c];
            ss = fmaf(h, asrc[c], ss);
            dd = fmaf(h, adst[c], dd);
        }
        #pragma unroll
        for (int o = 16; o; o >>= 1) {
            ss += __shfl_down_sync(0xffffffffu, ss, o);
            dd += __shfl_down_sync(0xffffffffu, dd, o);
        }
        if (lid == 0) { sv[node] = ss; dv[node] = dd; }
    }
    __syncthreads();

    if (tid < NPS) {
        int s[11]; int cnt = get_srcs(tid, s);
        float d = dv[tid];
        float e[11]; float m = -1e30f;
        for (int k = 0; k < cnt; k++) {
            float v = sv[s[k]] + d;
            v = v > 0.f ? v : 0.2f * v;
            e[k] = v; m = fmaxf(m, v);
        }
        float sum = 0.f;
        for (int k = 0; k < cnt; k++) { float t = expf(e[k] - m); e[k] = t; sum += t; }
        float inv = 1.f / sum;
        for (int k = 0; k < cnt; k++) alpha[tid][k] = e[k] * inv;
    }
    __syncthreads();

    const float bcol = bias[tid];
    __nv_bfloat16* Yh = Yhi + base * F_HID;
    __nv_bfloat16* Yl = Ylo + base * F_HID;
    #pragma unroll
    for (int node = 0; node < NPS; node++) {
        int s[11]; int cnt = get_srcs(node, s);
        float acc = 0.f;
        for (int k = 0; k < cnt; k++)
            acc = fmaf(alpha[node][k], hs[s[k]][tid], acc);
        float v = fmaxf(acc + bcol, 0.f);
        __nv_bfloat16 h = __float2bfloat16(v);
        Yh[node * F_HID + tid] = h;
        Yl[node * F_HID + tid] = __float2bfloat16(v - __bfloat162float(h));
    }
}

// ===========================================================================
// Kernel 5: GAT aggregate layer 2 (F=128) + bias -> hidden, fused head
// ===========================================================================
__global__ __launch_bounds__(128) void gat_agg2(
    const float* __restrict__ H,
    const float* __restrict__ asrc, const float* __restrict__ adst,
    const float* __restrict__ bias,
    const float* __restrict__ Wl, const float* __restrict__ bl,
    float* __restrict__ hid, float* __restrict__ yout)
{
    __shared__ float hs[NPS][F_OUT];
    __shared__ float os[NPS][F_OUT];
    __shared__ float sv[NPS], dv[NPS];
    __shared__ float alpha[NPS][11];

    const int b = blockIdx.x, tid = threadIdx.x;
    const size_t base = (size_t)b * NPS;
    const float* Hb = H + base * F_OUT;

    #pragma unroll
    for (int i = tid; i < NPS * (F_OUT / 4); i += 128) {
        int row = i >> 5, c = i & 31;
        ((float4*)hs[row])[c] = ((const float4*)(Hb + row * F_OUT))[c];
    }
    __syncthreads();

    const int wid = tid >> 5, lid = tid & 31;
    for (int node = wid; node < NPS; node += 4) {
        float ss = 0.f, dd = 0.f;
        #pragma unroll
        for (int c = lid; c < F_OUT; c += 32) {
            float h = hs[node][c];
            ss = fmaf(h, asrc[c], ss);
            dd = fmaf(h, adst[c], dd);
        }
        #pragma unroll
        for (int o = 16; o; o >>= 1) {
            ss += __shfl_down_sync(0xffffffffu, ss, o);
            dd += __shfl_down_sync(0xffffffffu, dd, o);
        }
        if (lid == 0) { sv[node] = ss; dv[node] = dd; }
    }
    __syncthreads();

    if (tid < NPS) {
        int s[11]; int cnt = get_srcs(tid, s);
        float d = dv[tid];
        float e[11]; float m = -1e30f;
        for (int k = 0; k < cnt; k++) {
            float v = sv[s[k]] + d;
            v = v > 0.f ? v : 0.2f * v;
            e[k] = v; m = fmaxf(m, v);
        }
        float sum = 0.f;
        for (int k = 0; k < cnt; k++) { float t = expf(e[k] - m); e[k] = t; sum += t; }
        float inv = 1.f / sum;
        for (int k = 0; k < cnt; k++) alpha[tid][k] = e[k] * inv;
    }
    __syncthreads();

    const float bcol = bias[tid];
    float* Hob = hid + base * F_OUT;
    #pragma unroll
    for (int node = 0; node < NPS; node++) {
        int s[11]; int cnt = get_srcs(node, s);
        float acc = 0.f;
        for (int k = 0; k < cnt; k++)
            acc = fmaf(alpha[node][k], hs[s[k]][tid], acc);
        float v = acc + bcol;
        Hob[node * F_OUT + tid] = v;
        os[node][tid] = fmaxf(v, 0.f);
    }
    __syncthreads();

    const float blv = bl[0];
    for (int node = wid; node < NPS; node += 4) {
        float p = 0.f;
        #pragma unroll
        for (int c = lid; c < F_OUT; c += 32)
            p = fmaf(os[node][c], Wl[c], p);
        #pragma unroll
        for (int o = 16; o; o >>= 1)
            p += __shfl_down_sync(0xffffffffu, p, o);
        if (lid == 0)
            yout[base + node] = 1.f / (1.f + expf(-(p + blv)));
    }
}

// ===========================================================================
extern "C" void kernel_launch(void* const* d_in, const int* in_sizes, int n_in,
                              void* d_out, int out_size)
{
    const float* x     = (const float*)d_in[1];
    const int*   click = (const int*)  d_in[4];
    const int*   query = (const int*)  d_in[5];
    const int*   docu  = (const int*)  d_in[6];
    const int*   title = (const int*)  d_in[7];
    const float* qtab  = (const float*)d_in[8];
    const float* dtab  = (const float*)d_in[9];
    const float* ttab  = (const float*)d_in[10];
    const float* ptab  = (const float*)d_in[11];
    const float* ctab  = (const float*)d_in[12];
    const float* W1    = (const float*)d_in[13];
    const float* as1   = (const float*)d_in[14];
    const float* ad1   = (const float*)d_in[15];
    const float* b1    = (const float*)d_in[16];
    const float* W2    = (const float*)d_in[17];
    const float* as2   = (const float*)d_in[18];
    const float* ad2   = (const float*)d_in[19];
    const float* b2    = (const float*)d_in[20];
    const float* Wl    = (const float*)d_in[21];
    const float* bl    = (const float*)d_in[22];

    float* out  = (float*)d_out;
    float* xout = out + OUT_X_OFF;
    float* hout = out + OUT_HID_OFF;
    float* yout = out + OUT_Y_OFF;

    float *h1p, *h2p;
    __nv_bfloat16 *xhi, *xlo, *yhi, *ylo, *w1hi, *w1lo, *w2hi, *w2lo;
    cudaGetSymbolAddress((void**)&h1p,  g_h1);
    cudaGetSymbolAddress((void**)&h2p,  g_h2);
    cudaGetSymbolAddress((void**)&xhi,  g_xhi);
    cudaGetSymbolAddress((void**)&xlo,  g_xlo);
    cudaGetSymbolAddress((void**)&yhi,  g_yhi);
    cudaGetSymbolAddress((void**)&ylo,  g_ylo);
    cudaGetSymbolAddress((void**)&w1hi, g_w1hi);
    cudaGetSymbolAddress((void**)&w1lo, g_w1lo);
    cudaGetSymbolAddress((void**)&w2hi, g_w2hi);
    cudaGetSymbolAddress((void**)&w2lo, g_w2lo);

    cudaFuncSetAttribute(mma_gemm<K1_PAD / BK, K1_PAD, F_HID>,
                         cudaFuncAttributeMaxDynamicSharedMemorySize, GEMM_SMEM);
    cudaFuncSetAttribute(mma_gemm<F_HID / BK, F_HID, F_OUT>,
                         cudaFuncAttributeMaxDynamicSharedMemorySize, GEMM_SMEM);

    // 1. scatter embeddings into x output slice + fused bf16 hi/lo split
    {
        long long tot = (long long)N_NODES * (K1_PAD / 4);
        build_x_kernel<<<(unsigned)((tot + 255) / 256), 256>>>(
            x, click, query, docu, title, qtab, dtab, ttab, ptab, ctab,
            xout, xhi, xlo);
    }

    // 2. weight splits
    {
        long long tot = (long long)F_HID * K1_PAD;
        conv_split<<<(unsigned)((tot + 255) / 256), 256>>>(W1, F_IN, w1hi, w1lo, K1_PAD, tot);
    }
    {
        long long tot = (long long)F_OUT * F_HID;
        conv_split<<<(unsigned)((tot + 255) / 256), 256>>>(W2, F_HID, w2hi, w2lo, F_HID, tot);
    }

    // 3. h1 = x @ W1^T  (HMMA split-3 bf16); grid.x = col blocks for A L2 reuse
    mma_gemm<K1_PAD / BK, K1_PAD, F_HID>
        <<<dim3(F_HID / BN, N_NODES / BM), 256, GEMM_SMEM>>>(
        xhi, xlo, w1hi, w1lo, h1p);

    // 4. GAT aggregate 1 + relu -> y (bf16 hi/lo)
    gat_agg1<<<B_SESS, 256>>>(h1p, as1, ad1, b1, yhi, ylo);

    // 5. h2 = y @ W2^T
    mma_gemm<F_HID / BK, F_HID, F_OUT>
        <<<dim3(F_OUT / BN, N_NODES / BM), 256, GEMM_SMEM>>>(
        yhi, ylo, w2hi, w2lo, h2p);

    // 6. GAT aggregate 2 + head
    gat_agg2<<<B_SESS, 128>>>(h2p, as2, ad2, b2, Wl, bl, hout, yout);
}

// round 6
// speedup vs baseline: 2.6914x; 1.0497x over previous
#include <cuda_runtime.h>
#include <cuda_bf16.h>
#include <math.h>
#include <stdint.h>

#define B_SESS   8192
#define NPS      21
#define N_NODES  (B_SESS * NPS)      // 172032
#define F_IN     171
#define K1_PAD   192                 // F_IN padded to 6*32
#define F_HID    256
#define F_OUT    128

// Output layout: hidden_state (N*128) | y (N*1) | x (N*171)
#define OUT_HID_OFF  0
#define OUT_Y_OFF    ((size_t)N_NODES * F_OUT)
#define OUT_X_OFF    ((size_t)N_NODES * (F_OUT + 1))

// Scratch (static device arrays: allocation-free)
__device__ float          g_h1[(size_t)N_NODES * F_HID];
__device__ float          g_h2[(size_t)N_NODES * F_OUT];
__device__ __nv_bfloat16  g_xhi[(size_t)N_NODES * K1_PAD];
__device__ __nv_bfloat16  g_xlo[(size_t)N_NODES * K1_PAD];
__device__ __nv_bfloat16  g_yhi[(size_t)N_NODES * F_HID];
__device__ __nv_bfloat16  g_ylo[(size_t)N_NODES * F_HID];
__device__ __nv_bfloat16  g_w1hi[(size_t)F_HID * K1_PAD];
__device__ __nv_bfloat16  g_w1lo[(size_t)F_HID * K1_PAD];
__device__ __nv_bfloat16  g_w2hi[(size_t)F_OUT * F_HID];
__device__ __nv_bfloat16  g_w2lo[(size_t)F_OUT * F_HID];

// ===========================================================================
// helpers (baseline PTX only: ldmatrix / mma.sync / cp.async)
// ===========================================================================
__device__ __forceinline__ uint32_t smem_to_u32(const void* p) {
    uint32_t a;
    asm("{ .reg .u64 t; cvta.to.shared.u64 t, %1; cvt.u32.u64 %0, t; }" : "=r"(a) : "l"(p));
    return a;
}
__device__ __forceinline__ void cp_async16(uint32_t dst, const void* src) {
    asm volatile("cp.async.cg.shared.global [%0], [%1], 16;" :: "r"(dst), "l"(src));
}
#define CP_COMMIT() asm volatile("cp.async.commit_group;" ::: "memory")
#define CP_WAIT0()  asm volatile("cp.async.wait_group 0;" ::: "memory")
#define CP_WAIT1()  asm volatile("cp.async.wait_group 1;" ::: "memory")

__device__ __forceinline__ void ldsm_x4(uint32_t addr, uint32_t* r) {
    asm volatile("ldmatrix.sync.aligned.m8n8.x4.shared.b16 {%0,%1,%2,%3}, [%4];"
        : "=r"(r[0]), "=r"(r[1]), "=r"(r[2]), "=r"(r[3]) : "r"(addr));
}
__device__ __forceinline__ void mma_bf16(float* d, const uint32_t* a, const uint32_t* b) {
    asm volatile("mma.sync.aligned.m16n8k16.row.col.f32.bf16.bf16.f32 "
        "{%0,%1,%2,%3}, {%4,%5,%6,%7}, {%8,%9}, {%0,%1,%2,%3};"
        : "+f"(d[0]), "+f"(d[1]), "+f"(d[2]), "+f"(d[3])
        : "r"(a[0]), "r"(a[1]), "r"(a[2]), "r"(a[3]), "r"(b[0]), "r"(b[1]));
}

// XOR bank swizzle on 64B rows (16B chunk granularity): conflict-free for
// cp.async 16B stores and all ldmatrix 8-row phases.
__device__ __forceinline__ uint32_t sw_off(int row, int colByte) {
    return (uint32_t)(row * 64 + ((((colByte >> 4) ^ ((row >> 1) & 3)) & 3) << 4));
}

// ===========================================================================
// Kernel 1: build x_mod (scatter) + fused bf16 hi/lo split, 4 cols per thread
// ===========================================================================
__global__ __launch_bounds__(256) void build_x_kernel(
    const float* __restrict__ x,
    const int*   __restrict__ click,
    const int*   __restrict__ query,
    const int*   __restrict__ docu,
    const int*   __restrict__ title_id,
    const float* __restrict__ qtab,
    const float* __restrict__ dtab,
    const float* __restrict__ ttab,
    const float* __restrict__ ptab,
    const float* __restrict__ ctab,
    float* __restrict__ xout,
    __nv_bfloat16* __restrict__ xhi,
    __nv_bfloat16* __restrict__ xlo)
{
    long long t = (long long)blockIdx.x * blockDim.x + threadIdx.x;
    if (t >= (long long)N_NODES * (K1_PAD / 4)) return;
    int n  = (int)(t / (K1_PAD / 4));
    int cc = (int)(t - (long long)n * (K1_PAD / 4));
    int c0 = cc * 4;
    int b = n / NPS;
    int s = n - b * NPS;

    float4 v;
    if (c0 + 3 < 160) {
        const float* tab;
        size_t row;
        if (s == 0)            { tab = qtab; row = (size_t)query[b]; }
        else if (s <= 10)      { tab = dtab; row = (size_t)docu[b * 10 + (s - 1)]; }
        else                   { tab = ttab; row = (size_t)title_id[b * 10 + (s - 11)]; }
        v = *(const float4*)(tab + row * 160 + c0);
    } else {
        float vv[4];
        #pragma unroll
        for (int j = 0; j < 4; j++) {
            int c = c0 + j;
            float val = 0.f;
            if (c < F_IN) {
                long long xi = (long long)n * F_IN + c;
                if (s == 0) {
                    val = (c < 160) ? qtab[(size_t)query[b] * 160 + c] : x[xi];
                } else if (s <= 10) {
                    int jj = s - 1;
                    if      (c < 160)  val = dtab[(size_t)docu[b * 10 + jj] * 160 + c];
                    else if (c == 160) val = ptab[jj];
                    else if (c == 161) val = ctab[click[b]];
                    else               val = x[xi];
                } else {
                    val = (c < 160) ? ttab[(size_t)title_id[b * 10 + (s - 11)] * 160 + c] : x[xi];
                }
            }
            vv[j] = val;
        }
        v = make_float4(vv[0], vv[1], vv[2], vv[3]);
    }

    {
        long long xi = (long long)n * F_IN + c0;
        if (c0 + 3 < F_IN) {
            xout[xi] = v.x; xout[xi + 1] = v.y; xout[xi + 2] = v.z; xout[xi + 3] = v.w;
        } else {
            float vv[4] = {v.x, v.y, v.z, v.w};
            #pragma unroll
            for (int j = 0; j < 4; j++)
                if (c0 + j < F_IN) xout[xi + j] = vv[j];
        }
    }

    long long oi = (long long)n * K1_PAD + c0;
    __nv_bfloat162 h01, h23, l01, l23;
    {
        float vv[4] = {v.x, v.y, v.z, v.w};
        __nv_bfloat16 h[4], l[4];
        #pragma unroll
        for (int j = 0; j < 4; j++) {
            h[j] = __float2bfloat16(vv[j]);
            l[j] = __float2bfloat16(vv[j] - __bfloat162float(h[j]));
        }
        h01 = __nv_bfloat162(h[0], h[1]); h23 = __nv_bfloat162(h[2], h[3]);
        l01 = __nv_bfloat162(l[0], l[1]); l23 = __nv_bfloat162(l[2], l[3]);
    }
    *(__nv_bfloat162*)(xhi + oi)     = h01;
    *(__nv_bfloat162*)(xhi + oi + 2) = h23;
    *(__nv_bfloat162*)(xlo + oi)     = l01;
    *(__nv_bfloat162*)(xlo + oi + 2) = l23;
}

// ===========================================================================
// Kernel 2: fp32 -> bf16 hi/lo split for weights (with K padding)
// ===========================================================================
__global__ __launch_bounds__(256) void conv_split(
    const float* __restrict__ src, int Ksrc,
    __nv_bfloat16* __restrict__ hi, __nv_bfloat16* __restrict__ lo,
    int Kdst, long long total)
{
    long long idx = (long long)blockIdx.x * blockDim.x + threadIdx.x;
    if (idx >= total) return;
    long long row = idx / Kdst;
    int c = (int)(idx - row * Kdst);
    float v = (c < Ksrc) ? src[row * Ksrc + c] : 0.f;
    __nv_bfloat16 h = __float2bfloat16(v);
    hi[idx] = h;
    lo[idx] = __float2bfloat16(v - __bfloat162float(h));
}

// ===========================================================================
// Kernel 3: HMMA bf16 split-3 GEMM (3-stage swizzled cp.async pipeline)
// 128x128x32 tiles, 8 warps (32x64 each), XOR-swizzled 64B rows.
// ===========================================================================
#define BM 128
#define BN 128
#define BK 32
#define ARR_B   (128 * 64)                // 8192 per array (no padding; swizzled)
#define STAGE_B (4 * ARR_B)               // 32768: Ah, Al, Bh, Bl
#define NSTAGE  3
#define GEMM_SMEM (NSTAGE * STAGE_B)      // 98304

template<int NK, int KPAD, int MOUT>
__global__ __launch_bounds__(256, 2) void mma_gemm(
    const __nv_bfloat16* __restrict__ Ahi, const __nv_bfloat16* __restrict__ Alo,
    const __nv_bfloat16* __restrict__ Bhi, const __nv_bfloat16* __restrict__ Blo,
    float* __restrict__ C)
{
    extern __shared__ char smem[];
    const uint32_t sb = smem_to_u32(smem);
    const int tid = threadIdx.x;
    const int wid = tid >> 5, lane = tid & 31;
    const int warpM = wid & 3, warpN = wid >> 2;           // 4 x 2 warp grid
    const size_t rowBase = (size_t)blockIdx.y * BM;
    const size_t colBase = (size_t)blockIdx.x * BN;

    const __nv_bfloat16* srcs[4] = {
        Ahi + rowBase * KPAD, Alo + rowBase * KPAD,
        Bhi + colBase * KPAD, Blo + colBase * KPAD
    };

    auto load_stage = [&](int ck, int st) {
        uint32_t base = sb + st * STAGE_B;
        #pragma unroll
        for (int i = 0; i < 8; i++) {
            int id = tid + i * 256;            // 0..2047
            int m  = id >> 9;                  // which array
            int v  = id & 511;
            int row = v >> 2, c = v & 3;       // 4 x 16B chunks per 64B row
            const char* g = (const char*)(srcs[m] + (size_t)row * KPAD + ck * BK) + c * 16;
            cp_async16(base + m * ARR_B + sw_off(row, c * 16), g);
        }
        CP_COMMIT();
    };

    float acc[2][8][4];
    #pragma unroll
    for (int mt = 0; mt < 2; mt++)
        #pragma unroll
        for (int nt = 0; nt < 8; nt++)
            #pragma unroll
            for (int j = 0; j < 4; j++) acc[mt][nt][j] = 0.f;

    load_stage(0, 0);
    load_stage(1, 1);

    const int q = lane >> 3, r = lane & 7;
    const int aRowBase = warpM * 32 + ((q & 1) ? 8 : 0) + r;
    const int aColSel  = (q & 2) ? 8 : 0;
    const int bRowBase = warpN * 64 + ((q & 2) ? 8 : 0) + r;
    const int bColSel  = (q & 1) ? 8 : 0;

    #pragma unroll
    for (int ck = 0; ck < NK; ck++) {
        if (ck < NK - 1) CP_WAIT1(); else CP_WAIT0();
        __syncthreads();
        if (ck + 2 < NK) load_stage(ck + 2, (ck + 2) % NSTAGE);

        const uint32_t st = sb + (ck % NSTAGE) * STAGE_B;
        #pragma unroll
        for (int ks = 0; ks < 2; ks++) {
            const int k0 = ks * 16;
            uint32_t ah[2][4], al[2][4];
            #pragma unroll
            for (int mt = 0; mt < 2; mt++) {
                uint32_t a = st + sw_off(aRowBase + mt * 16, (k0 + aColSel) * 2);
                ldsm_x4(a, ah[mt]);
                ldsm_x4(a + ARR_B, al[mt]);
            }
            #pragma unroll
            for (int nt2 = 0; nt2 < 4; nt2++) {
                uint32_t a = st + 2 * ARR_B + sw_off(bRowBase + nt2 * 16, (k0 + bColSel) * 2);
                uint32_t bh[4], bl[4];
                ldsm_x4(a, bh);
                ldsm_x4(a + ARR_B, bl);
                #pragma unroll
                for (int half = 0; half < 2; half++) {
                    const int nt = nt2 * 2 + half;
                    const uint32_t* bhp = bh + half * 2;
                    const uint32_t* blp = bl + half * 2;
                    // product-major order: same-acc MMA distance = 2
                    mma_bf16(acc[0][nt], ah[0], bhp);
                    mma_bf16(acc[1][nt], ah[1], bhp);
                    mma_bf16(acc[0][nt], al[0], bhp);
                    mma_bf16(acc[1][nt], al[1], bhp);
                    mma_bf16(acc[0][nt], ah[0], blp);
                    mma_bf16(acc[1][nt], ah[1], blp);
                }
            }
        }
    }

    // Epilogue: direct fp32 stores (float2 per half-tile)
    const int g2 = lane >> 2, ti = lane & 3;
    #pragma unroll
    for (int mt = 0; mt < 2; mt++) {
        size_t row = rowBase + warpM * 32 + mt * 16 + g2;
        #pragma unroll
        for (int nt = 0; nt < 8; nt++) {
            size_t col = colBase + warpN * 64 + nt * 8 + ti * 2;
            float2 v0 = make_float2(acc[mt][nt][0], acc[mt][nt][1]);
            float2 v1 = make_float2(acc[mt][nt][2], acc[mt][nt][3]);
            *(float2*)&C[row * MOUT + col]       = v0;
            *(float2*)&C[(row + 8) * MOUT + col] = v1;
        }
    }
}

// ===========================================================================
// Static adjacency
// ===========================================================================
__device__ __forceinline__ int get_srcs(int node, int* s)
{
    if (node == 0) {
        #pragma unroll
        for (int j = 0; j < 10; j++) s[j] = 1 + j;
        s[10] = 0;
        return 11;
    }
    if (node <= 10) { s[0] = 0; s[1] = node + 10; s[2] = node; return 3; }
    s[0] = node - 10; s[1] = node; return 2;
}

// ===========================================================================
// Kernel 4: GAT aggregate layer 1 (F=256) + bias + relu, writes y as bf16 hi/lo
// ===========================================================================
__global__ __launch_bounds__(256) void gat_agg1(
    const float* __restrict__ H,
    const float* __restrict__ asrc, const float* __restrict__ adst,
    const float* __restrict__ bias,
    __nv_bfloat16* __restrict__ Yhi, __nv_bfloat16* __restrict__ Ylo)
{
    __shared__ float hs[NPS][F_HID];
    __shared__ float sv[NPS], dv[NPS];
    __shared__ float alpha[NPS][11];

    const int b = blockIdx.x, tid = threadIdx.x;
    const size_t base = (size_t)b * NPS;
    const float* Hb = H + base * F_HID;

    // vectorized tile load: 21*64 float4
    #pragma unroll
    for (int i = tid; i < NPS * (F_HID / 4); i += 256) {
        int row = i >> 6, c = i & 63;
        ((float4*)hs[row])[c] = ((const float4*)(Hb + row * F_HID))[c];
    }
    __syncthreads();

    const int wid = tid >> 5, lid = tid & 31;
    for (int node = wid; node < NPS; node += 8) {
        float ss = 0.f, dd = 0.f;
        #pragma unroll
        for (int c = lid; c < F_HID; c += 32) {
            float h = hs[node][c];
            ss = fmaf(h, asrc[c], ss);
            dd = fmaf(h, adst[c], dd);
        }
        #pragma unroll
        for (int o = 16; o; o >>= 1) {
            ss += __shfl_down_sync(0xffffffffu, ss, o);
            dd += __shfl_down_sync(0xffffffffu, dd, o);
        }
        if (lid == 0) { sv[node] = ss; dv[node] = dd; }
    }
    __syncthreads();

    if (tid < NPS) {
        int s[11]; int cnt = get_srcs(tid, s);
        float d = dv[tid];
        float e[11]; float m = -1e30f;
        for (int k = 0; k < cnt; k++) {
            float v = sv[s[k]] + d;
            v = v > 0.f ? v : 0.2f * v;
            e[k] = v; m = fmaxf(m, v);
        }
        float sum = 0.f;
        for (int k = 0; k < cnt; k++) { float t = expf(e[k] - m); e[k] = t; sum += t; }
        float inv = 1.f / sum;
        for (int k = 0; k < cnt; k++) alpha[tid][k] = e[k] * inv;
    }
    __syncthreads();

    const float bcol = bias[tid];
    __nv_bfloat16* Yh = Yhi + base * F_HID;
    __nv_bfloat16* Yl = Ylo + base * F_HID;
    #pragma unroll
    for (int node = 0; node < NPS; node++) {
        int s[11]; int cnt = get_srcs(node, s);
        float acc = 0.f;
        for (int k = 0; k < cnt; k++)
            acc = fmaf(alpha[node][k], hs[s[k]][tid], acc);
        float v = fmaxf(acc + bcol, 0.f);
        __nv_bfloat16 h = __float2bfloat16(v);
        Yh[node * F_HID + tid] = h;
        Yl[node * F_HID + tid] = __float2bfloat16(v - __bfloat162float(h));
    }
}

// ===========================================================================
// Kernel 5: GAT aggregate layer 2 (F=128) + bias -> hidden, fused head
// ===========================================================================
__global__ __launch_bounds__(128) void gat_agg2(
    const float* __restrict__ H,
    const float* __restrict__ asrc, const float* __restrict__ adst,
    const float* __restrict__ bias,
    const float* __restrict__ Wl, const float* __restrict__ bl,
    float* __restrict__ hid, float* __restrict__ yout)
{
    __shared__ float hs[NPS][F_OUT];
    __shared__ float os[NPS][F_OUT];
    __shared__ float sv[NPS], dv[NPS];
    __shared__ float alpha[NPS][11];

    const int b = blockIdx.x, tid = threadIdx.x;
    const size_t base = (size_t)b * NPS;
    const float* Hb = H + base * F_OUT;

    #pragma unroll
    for (int i = tid; i < NPS * (F_OUT / 4); i += 128) {
        int row = i >> 5, c = i & 31;
        ((float4*)hs[row])[c] = ((const float4*)(Hb + row * F_OUT))[c];
    }
    __syncthreads();

    const int wid = tid >> 5, lid = tid & 31;
    for (int node = wid; node < NPS; node += 4) {
        float ss = 0.f, dd = 0.f;
        #pragma unroll
        for (int c = lid; c < F_OUT; c += 32) {
            float h = hs[node][c];
            ss = fmaf(h, asrc[c], ss);
            dd = fmaf(h, adst[c], dd);
        }
        #pragma unroll
        for (int o = 16; o; o >>= 1) {
            ss += __shfl_down_sync(0xffffffffu, ss, o);
            dd += __shfl_down_sync(0xffffffffu, dd, o);
        }
        if (lid == 0) { sv[node] = ss; dv[node] = dd; }
    }
    __syncthreads();

    if (tid < NPS) {
        int s[11]; int cnt = get_srcs(tid, s);
        float d = dv[tid];
        float e[11]; float m = -1e30f;
        for (int k = 0; k < cnt; k++) {
            float v = sv[s[k]] + d;
            v = v > 0.f ? v : 0.2f * v;
            e[k] = v; m = fmaxf(m, v);
        }
        float sum = 0.f;
        for (int k = 0; k < cnt; k++) { float t = expf(e[k] - m); e[k] = t; sum += t; }
        float inv = 1.f / sum;
        for (int k = 0; k < cnt; k++) alpha[tid][k] = e[k] * inv;
    }
    __syncthreads();

    const float bcol = bias[tid];
    float* Hob = hid + base * F_OUT;
    #pragma unroll
    for (int node = 0; node < NPS; node++) {
        int s[11]; int cnt = get_srcs(node, s);
        float acc = 0.f;
        for (int k = 0; k < cnt; k++)
            acc = fmaf(alpha[node][k], hs[s[k]][tid], acc);
        float v = acc + bcol;
        Hob[node * F_OUT + tid] = v;
        os[node][tid] = fmaxf(v, 0.f);
    }
    __syncthreads();

    const float blv = bl[0];
    for (int node = wid; node < NPS; node += 4) {
        float p = 0.f;
        #pragma unroll
        for (int c = lid; c < F_OUT; c += 32)
            p = fmaf(os[node][c], Wl[c], p);
        #pragma unroll
        for (int o = 16; o; o >>= 1)
            p += __shfl_down_sync(0xffffffffu, p, o);
        if (lid == 0)
            yout[base + node] = 1.f / (1.f + expf(-(p + blv)));
    }
}

// ===========================================================================
extern "C" void kernel_launch(void* const* d_in, const int* in_sizes, int n_in,
                              void* d_out, int out_size)
{
    const float* x     = (const float*)d_in[1];
    const int*   click = (const int*)  d_in[4];
    const int*   query = (const int*)  d_in[5];
    const int*   docu  = (const int*)  d_in[6];
    const int*   title = (const int*)  d_in[7];
    const float* qtab  = (const float*)d_in[8];
    const float* dtab  = (const float*)d_in[9];
    const float* ttab  = (const float*)d_in[10];
    const float* ptab  = (const float*)d_in[11];
    const float* ctab  = (const float*)d_in[12];
    const float* W1    = (const float*)d_in[13];
    const float* as1   = (const float*)d_in[14];
    const float* ad1   = (const float*)d_in[15];
    const float* b1    = (const float*)d_in[16];
    const float* W2    = (const float*)d_in[17];
    const float* as2   = (const float*)d_in[18];
    const float* ad2   = (const float*)d_in[19];
    const float* b2    = (const float*)d_in[20];
    const float* Wl    = (const float*)d_in[21];
    const float* bl    = (const float*)d_in[22];

    float* out  = (float*)d_out;
    float* xout = out + OUT_X_OFF;
    float* hout = out + OUT_HID_OFF;
    float* yout = out + OUT_Y_OFF;

    float *h1p, *h2p;
    __nv_bfloat16 *xhi, *xlo, *yhi, *ylo, *w1hi, *w1lo, *w2hi, *w2lo;
    cudaGetSymbolAddress((void**)&h1p,  g_h1);
    cudaGetSymbolAddress((void**)&h2p,  g_h2);
    cudaGetSymbolAddress((void**)&xhi,  g_xhi);
    cudaGetSymbolAddress((void**)&xlo,  g_xlo);
    cudaGetSymbolAddress((void**)&yhi,  g_yhi);
    cudaGetSymbolAddress((void**)&ylo,  g_ylo);
    cudaGetSymbolAddress((void**)&w1hi, g_w1hi);
    cudaGetSymbolAddress((void**)&w1lo, g_w1lo);
    cudaGetSymbolAddress((void**)&w2hi, g_w2hi);
    cudaGetSymbolAddress((void**)&w2lo, g_w2lo);

    cudaFuncSetAttribute(mma_gemm<K1_PAD / BK, K1_PAD, F_HID>,
                         cudaFuncAttributeMaxDynamicSharedMemorySize, GEMM_SMEM);
    cudaFuncSetAttribute(mma_gemm<F_HID / BK, F_HID, F_OUT>,
                         cudaFuncAttributeMaxDynamicSharedMemorySize, GEMM_SMEM);

    // 1. scatter embeddings into x output slice + fused bf16 hi/lo split
    {
        long long tot = (long long)N_NODES * (K1_PAD / 4);
        build_x_kernel<<<(unsigned)((tot + 255) / 256), 256>>>(
            x, click, query, docu, title, qtab, dtab, ttab, ptab, ctab,
            xout, xhi, xlo);
    }

    // 2. weight splits
    {
        long long tot = (long long)F_HID * K1_PAD;
        conv_split<<<(unsigned)((tot + 255) / 256), 256>>>(W1, F_IN, w1hi, w1lo, K1_PAD, tot);
    }
    {
        long long tot = (long long)F_OUT * F_HID;
        conv_split<<<(unsigned)((tot + 255) / 256), 256>>>(W2, F_HID, w2hi, w2lo, F_HID, tot);
    }

    // 3. h1 = x @ W1^T  (HMMA split-3 bf16); grid.x = col blocks for A L2 reuse
    mma_gemm<K1_PAD / BK, K1_PAD, F_HID>
        <<<dim3(F_HID / BN, N_NODES / BM), 256, GEMM_SMEM>>>(
        xhi, xlo, w1hi, w1lo, h1p);

    // 4. GAT aggregate 1 + relu -> y (bf16 hi/lo)
    gat_agg1<<<B_SESS, 256>>>(h1p, as1, ad1, b1, yhi, ylo);

    // 5. h2 = y @ W2^T
    mma_gemm<F_HID / BK, F_HID, F_OUT>
        <<<dim3(F_OUT / BN, N_NODES / BM), 256, GEMM_SMEM>>>(
        yhi, ylo, w2hi, w2lo, h2p);

    // 6. GAT aggregate 2 + head
    gat_agg2<<<B_SESS, 128>>>(h2p, as2, ad2, b2, Wl, bl, hout, yout);
}

// round 7
// speedup vs baseline: 2.6953x; 1.0014x over previous
#include <cuda_runtime.h>
#include <cuda_bf16.h>
#include <math.h>
#include <stdint.h>

#define B_SESS   8192
#define NPS      21
#define N_NODES  (B_SESS * NPS)      // 172032
#define F_IN     171
#define K1_PAD   192                 // F_IN padded to 6*32
#define F_HID    256
#define F_OUT    128
#define SESS_PER_BLK 6
#define ROWS_PER_BLK (SESS_PER_BLK * NPS)   // 126
#define NBLK ((B_SESS + SESS_PER_BLK - 1) / SESS_PER_BLK)  // 1366

// Output layout: hidden_state (N*128) | y (N*1) | x (N*171)
#define OUT_HID_OFF  0
#define OUT_Y_OFF    ((size_t)N_NODES * F_OUT)
#define OUT_X_OFF    ((size_t)N_NODES * (F_OUT + 1))

// Scratch (static device arrays: allocation-free)
__device__ __nv_bfloat16  g_xhi[(size_t)N_NODES * K1_PAD];
__device__ __nv_bfloat16  g_xlo[(size_t)N_NODES * K1_PAD];
__device__ __nv_bfloat16  g_yhi[(size_t)N_NODES * F_HID];
__device__ __nv_bfloat16  g_ylo[(size_t)N_NODES * F_HID];
__device__ __nv_bfloat16  g_w1hi[(size_t)F_HID * K1_PAD];
__device__ __nv_bfloat16  g_w1lo[(size_t)F_HID * K1_PAD];
__device__ __nv_bfloat16  g_w2hi[(size_t)F_OUT * F_HID];
__device__ __nv_bfloat16  g_w2lo[(size_t)F_OUT * F_HID];

// ===========================================================================
// helpers
// ===========================================================================
__device__ __forceinline__ uint32_t smem_to_u32(const void* p) {
    uint32_t a;
    asm("{ .reg .u64 t; cvta.to.shared.u64 t, %1; cvt.u32.u64 %0, t; }" : "=r"(a) : "l"(p));
    return a;
}
__device__ __forceinline__ void cp_async16(uint32_t dst, const void* src) {
    asm volatile("cp.async.cg.shared.global [%0], [%1], 16;" :: "r"(dst), "l"(src));
}
#define CP_COMMIT() asm volatile("cp.async.commit_group;" ::: "memory")
#define CP_WAIT0()  asm volatile("cp.async.wait_group 0;" ::: "memory")
#define CP_WAIT1()  asm volatile("cp.async.wait_group 1;" ::: "memory")

__device__ __forceinline__ void ldsm_x4(uint32_t addr, uint32_t* r) {
    asm volatile("ldmatrix.sync.aligned.m8n8.x4.shared.b16 {%0,%1,%2,%3}, [%4];"
        : "=r"(r[0]), "=r"(r[1]), "=r"(r[2]), "=r"(r[3]) : "r"(addr));
}
__device__ __forceinline__ void mma_bf16(float* d, const uint32_t* a, const uint32_t* b) {
    asm volatile("mma.sync.aligned.m16n8k16.row.col.f32.bf16.bf16.f32 "
        "{%0,%1,%2,%3}, {%4,%5,%6,%7}, {%8,%9}, {%0,%1,%2,%3};"
        : "+f"(d[0]), "+f"(d[1]), "+f"(d[2]), "+f"(d[3])
        : "r"(a[0]), "r"(a[1]), "r"(a[2]), "r"(a[3]), "r"(b[0]), "r"(b[1]));
}

// XOR bank swizzle on 64B rows (16B chunk granularity)
__device__ __forceinline__ uint32_t sw_off(int row, int colByte) {
    return (uint32_t)(row * 64 + ((((colByte >> 4) ^ ((row >> 1) & 3)) & 3) << 4));
}

// Static adjacency: in-neighbor slots (incl. self-loop) for slot 0..20
__device__ __forceinline__ int get_srcs(int node, int* s)
{
    if (node == 0) {
        #pragma unroll
        for (int j = 0; j < 10; j++) s[j] = 1 + j;
        s[10] = 0;
        return 11;
    }
    if (node <= 10) { s[0] = 0; s[1] = node + 10; s[2] = node; return 3; }
    s[0] = node - 10; s[1] = node; return 2;
}

// ===========================================================================
// Kernel 1: build x_mod (scatter) + fused bf16 hi/lo split, 4 cols per thread
// ===========================================================================
__global__ __launch_bounds__(256) void build_x_kernel(
    const float* __restrict__ x,
    const int*   __restrict__ click,
    const int*   __restrict__ query,
    const int*   __restrict__ docu,
    const int*   __restrict__ title_id,
    const float* __restrict__ qtab,
    const float* __restrict__ dtab,
    const float* __restrict__ ttab,
    const float* __restrict__ ptab,
    const float* __restrict__ ctab,
    float* __restrict__ xout,
    __nv_bfloat16* __restrict__ xhi,
    __nv_bfloat16* __restrict__ xlo)
{
    long long t = (long long)blockIdx.x * blockDim.x + threadIdx.x;
    if (t >= (long long)N_NODES * (K1_PAD / 4)) return;
    int n  = (int)(t / (K1_PAD / 4));
    int cc = (int)(t - (long long)n * (K1_PAD / 4));
    int c0 = cc * 4;
    int b = n / NPS;
    int s = n - b * NPS;

    float4 v;
    if (c0 + 3 < 160) {
        const float* tab;
        size_t row;
        if (s == 0)            { tab = qtab; row = (size_t)query[b]; }
        else if (s <= 10)      { tab = dtab; row = (size_t)docu[b * 10 + (s - 1)]; }
        else                   { tab = ttab; row = (size_t)title_id[b * 10 + (s - 11)]; }
        v = *(const float4*)(tab + row * 160 + c0);
    } else {
        float vv[4];
        #pragma unroll
        for (int j = 0; j < 4; j++) {
            int c = c0 + j;
            float val = 0.f;
            if (c < F_IN) {
                long long xi = (long long)n * F_IN + c;
                if (s == 0) {
                    val = (c < 160) ? qtab[(size_t)query[b] * 160 + c] : x[xi];
                } else if (s <= 10) {
                    int jj = s - 1;
                    if      (c < 160)  val = dtab[(size_t)docu[b * 10 + jj] * 160 + c];
                    else if (c == 160) val = ptab[jj];
                    else if (c == 161) val = ctab[click[b]];
                    else               val = x[xi];
                } else {
                    val = (c < 160) ? ttab[(size_t)title_id[b * 10 + (s - 11)] * 160 + c] : x[xi];
                }
            }
            vv[j] = val;
        }
        v = make_float4(vv[0], vv[1], vv[2], vv[3]);
    }

    {
        long long xi = (long long)n * F_IN + c0;
        if (c0 + 3 < F_IN) {
            xout[xi] = v.x; xout[xi + 1] = v.y; xout[xi + 2] = v.z; xout[xi + 3] = v.w;
        } else {
            float vv[4] = {v.x, v.y, v.z, v.w};
            #pragma unroll
            for (int j = 0; j < 4; j++)
                if (c0 + j < F_IN) xout[xi + j] = vv[j];
        }
    }

    long long oi = (long long)n * K1_PAD + c0;
    __nv_bfloat162 h01, h23, l01, l23;
    {
        float vv[4] = {v.x, v.y, v.z, v.w};
        __nv_bfloat16 h[4], l[4];
        #pragma unroll
        for (int j = 0; j < 4; j++) {
            h[j] = __float2bfloat16(vv[j]);
            l[j] = __float2bfloat16(vv[j] - __bfloat162float(h[j]));
        }
        h01 = __nv_bfloat162(h[0], h[1]); h23 = __nv_bfloat162(h[2], h[3]);
        l01 = __nv_bfloat162(l[0], l[1]); l23 = __nv_bfloat162(l[2], l[3]);
    }
    *(__nv_bfloat162*)(xhi + oi)     = h01;
    *(__nv_bfloat162*)(xhi + oi + 2) = h23;
    *(__nv_bfloat162*)(xlo + oi)     = l01;
    *(__nv_bfloat162*)(xlo + oi + 2) = l23;
}

// ===========================================================================
// Kernel 2: fp32 -> bf16 hi/lo split for weights (with K padding)
// ===========================================================================
__global__ __launch_bounds__(256) void conv_split(
    const float* __restrict__ src, int Ksrc,
    __nv_bfloat16* __restrict__ hi, __nv_bfloat16* __restrict__ lo,
    int Kdst, long long total)
{
    long long idx = (long long)blockIdx.x * blockDim.x + threadIdx.x;
    if (idx >= total) return;
    long long row = idx / Kdst;
    int c = (int)(idx - row * Kdst);
    float v = (c < Ksrc) ? src[row * Ksrc + c] : 0.f;
    __nv_bfloat16 h = __float2bfloat16(v);
    hi[idx] = h;
    lo[idx] = __float2bfloat16(v - __bfloat162float(h));
}

// ===========================================================================
// Kernel 3: fused GEMM1 (x @ W1^T, split-3 bf16 HMMA) + GAT agg layer 1
// Block: 512 thr, 16 warps (4x4), tile 128(rows:126 used) x 256, K=192.
// Epilogue: session-local attention + bias + relu -> y bf16 hi/lo.
// ===========================================================================
#define G1_NK 6
#define G1_STAGE_B 49152        // Ahi(8192) Alo(8192) Bhi(16384) Blo(16384)
#define G1_NSTAGE 3
#define G1_SMEM (G1_NSTAGE * G1_STAGE_B)   // 147456
#define HS1_STRIDE 258

__global__ __launch_bounds__(512, 1) void gemm1_fused(
    const __nv_bfloat16* __restrict__ Ahi, const __nv_bfloat16* __restrict__ Alo,
    const __nv_bfloat16* __restrict__ Bhi, const __nv_bfloat16* __restrict__ Blo,
    const float* __restrict__ asrc, const float* __restrict__ adst,
    const float* __restrict__ bias,
    __nv_bfloat16* __restrict__ Yhi, __nv_bfloat16* __restrict__ Ylo)
{
    extern __shared__ char smem[];
    const uint32_t sb = smem_to_u32(smem);
    const int tid = threadIdx.x;
    const int wid = tid >> 5, lane = tid & 31;
    const int warpM = wid & 3, warpN = wid >> 2;     // 4 x 4 warp grid
    const int rowBaseI = blockIdx.x * ROWS_PER_BLK;

    const __nv_bfloat16* srcA[2] = { Ahi + (size_t)rowBaseI * K1_PAD,
                                     Alo + (size_t)rowBaseI * K1_PAD };
    const __nv_bfloat16* srcB[2] = { Bhi, Blo };

    auto load_stage = [&](int ck, int st) {
        uint32_t base = sb + st * G1_STAGE_B;
        #pragma unroll
        for (int i = 0; i < 6; i++) {
            int id = tid + i * 512;            // 0..3071
            if (id < 1024) {                   // A arrays: 2 x 128 rows
                int m = id >> 9;
                int v = id & 511;
                int row = v >> 2, c = v & 3;
                int rowc = row;
                if (rowBaseI + rowc >= N_NODES) rowc = N_NODES - 1 - rowBaseI;
                const char* g = (const char*)(srcA[m] + (size_t)rowc * K1_PAD + ck * 32) + c * 16;
                cp_async16(base + m * 8192 + sw_off(row, c * 16), g);
            } else {                           // B arrays: 2 x 256 rows
                int idb = id - 1024;
                int m = idb >> 10;
                int v = idb & 1023;
                int row = v >> 2, c = v & 3;
                const char* g = (const char*)(srcB[m] + (size_t)row * K1_PAD + ck * 32) + c * 16;
                cp_async16(base + 16384 + m * 16384 + sw_off(row, c * 16), g);
            }
        }
        CP_COMMIT();
    };

    float acc[2][8][4];
    #pragma unroll
    for (int mt = 0; mt < 2; mt++)
        #pragma unroll
        for (int nt = 0; nt < 8; nt++)
            #pragma unroll
            for (int j = 0; j < 4; j++) acc[mt][nt][j] = 0.f;

    load_stage(0, 0);
    load_stage(1, 1);

    const int q = lane >> 3, r = lane & 7;
    const int aRowBase = warpM * 32 + ((q & 1) ? 8 : 0) + r;
    const int aColSel  = (q & 2) ? 8 : 0;
    const int bRowBase = warpN * 64 + ((q & 2) ? 8 : 0) + r;
    const int bColSel  = (q & 1) ? 8 : 0;

    #pragma unroll
    for (int ck = 0; ck < G1_NK; ck++) {
        if (ck < G1_NK - 1) CP_WAIT1(); else CP_WAIT0();
        __syncthreads();
        if (ck + 2 < G1_NK) load_stage(ck + 2, (ck + 2) % G1_NSTAGE);

        const uint32_t st = sb + (ck % G1_NSTAGE) * G1_STAGE_B;
        #pragma unroll
        for (int ks = 0; ks < 2; ks++) {
            const int k0 = ks * 16;
            uint32_t ah[2][4], al[2][4];
            #pragma unroll
            for (int mt = 0; mt < 2; mt++) {
                uint32_t a = st + sw_off(aRowBase + mt * 16, (k0 + aColSel) * 2);
                ldsm_x4(a, ah[mt]);
                ldsm_x4(a + 8192, al[mt]);
            }
            #pragma unroll
            for (int nt2 = 0; nt2 < 4; nt2++) {
                uint32_t a = st + 16384 + sw_off(bRowBase + nt2 * 16, (k0 + bColSel) * 2);
                uint32_t bh[4], bl[4];
                ldsm_x4(a, bh);
                ldsm_x4(a + 16384, bl);
                #pragma unroll
                for (int half = 0; half < 2; half++) {
                    const int nt = nt2 * 2 + half;
                    const uint32_t* bhp = bh + half * 2;
                    const uint32_t* blp = bl + half * 2;
                    mma_bf16(acc[0][nt], ah[0], bhp);
                    mma_bf16(acc[1][nt], ah[1], bhp);
                    mma_bf16(acc[0][nt], al[0], bhp);
                    mma_bf16(acc[1][nt], al[1], bhp);
                    mma_bf16(acc[0][nt], ah[0], blp);
                    mma_bf16(acc[1][nt], ah[1], blp);
                }
            }
        }
    }

    // ---------------- fused epilogue: GAT aggregation ----------------
    __syncthreads();   // all warps done reading stages: reuse smem

    float* hs    = (float*)smem;                          // [128][258]
    float* sv    = (float*)(smem + 132096);               // 128
    float* dvv   = sv + 128;                              // 128
    float* alpha = dvv + 128;                             // [128][12]

    const int g2 = lane >> 2, ti = lane & 3;
    #pragma unroll
    for (int mt = 0; mt < 2; mt++) {
        int row = warpM * 32 + mt * 16 + g2;
        #pragma unroll
        for (int nt = 0; nt < 8; nt++) {
            int col = warpN * 64 + nt * 8 + ti * 2;
            *(float2*)&hs[row * HS1_STRIDE + col]       = make_float2(acc[mt][nt][0], acc[mt][nt][1]);
            *(float2*)&hs[(row + 8) * HS1_STRIDE + col] = make_float2(acc[mt][nt][2], acc[mt][nt][3]);
        }
    }
    __syncthreads();

    const int nSess  = min(SESS_PER_BLK, B_SESS - blockIdx.x * SESS_PER_BLK);
    const int nNodes = nSess * NPS;

    // per-node attention dots
    for (int node = wid; node < nNodes; node += 16) {
        float ss = 0.f, dd = 0.f;
        #pragma unroll
        for (int c = lane; c < F_HID; c += 32) {
            float h = hs[node * HS1_STRIDE + c];
            ss = fmaf(h, asrc[c], ss);
            dd = fmaf(h, adst[c], dd);
        }
        #pragma unroll
        for (int o = 16; o; o >>= 1) {
            ss += __shfl_down_sync(0xffffffffu, ss, o);
            dd += __shfl_down_sync(0xffffffffu, dd, o);
        }
        if (lane == 0) { sv[node] = ss; dvv[node] = dd; }
    }
    __syncthreads();

    // per-node softmax over in-neighbors
    if (tid < nNodes) {
        int slot = tid % NPS;
        int rbase = tid - slot;
        int s[11]; int cnt = get_srcs(slot, s);
        float d = dvv[tid];
        float e[11]; float m = -1e30f;
        for (int k = 0; k < cnt; k++) {
            float v = sv[rbase + s[k]] + d;
            v = v > 0.f ? v : 0.2f * v;
            e[k] = v; m = fmaxf(m, v);
        }
        float sum = 0.f;
        for (int k = 0; k < cnt; k++) { float t = expf(e[k] - m); e[k] = t; sum += t; }
        float inv = 1.f / sum;
        for (int k = 0; k < cnt; k++) alpha[tid * 12 + k] = e[k] * inv;
    }
    __syncthreads();

    // aggregate + bias + relu -> y bf16 hi/lo (2 cols per thread)
    {
        const int col0 = (tid & 127) * 2;
        const int hgrp = tid >> 7;              // 0..3
        const float b0 = bias[col0], b1v = bias[col0 + 1];
        for (int n = hgrp; n < nNodes; n += 4) {
            int slot = n % NPS;
            int rbase = n - slot;
            int s[11]; int cnt = get_srcs(slot, s);
            float a0 = 0.f, a1 = 0.f;
            for (int k = 0; k < cnt; k++) {
                float al_ = alpha[n * 12 + k];
                float2 hv = *(const float2*)&hs[(rbase + s[k]) * HS1_STRIDE + col0];
                a0 = fmaf(al_, hv.x, a0);
                a1 = fmaf(al_, hv.y, a1);
            }
            float v0 = fmaxf(a0 + b0, 0.f);
            float v1 = fmaxf(a1 + b1v, 0.f);
            __nv_bfloat16 h0 = __float2bfloat16(v0);
            __nv_bfloat16 h1 = __float2bfloat16(v1);
            __nv_bfloat16 l0 = __float2bfloat16(v0 - __bfloat162float(h0));
            __nv_bfloat16 l1 = __float2bfloat16(v1 - __bfloat162float(h1));
            size_t off = (size_t)(rowBaseI + n) * F_HID + col0;
            *(__nv_bfloat162*)(Yhi + off) = __nv_bfloat162(h0, h1);
            *(__nv_bfloat162*)(Ylo + off) = __nv_bfloat162(l0, l1);
        }
    }
}

// ===========================================================================
// Kernel 4: fused GEMM2 (y @ W2^T) + GAT agg layer 2 + sigmoid head
// Block: 256 thr, 8 warps (4x2), tile 128(126) x 128, K=256.
// ===========================================================================
#define G2_NK 8
#define G2_STAGE_B 32768        // Ahi Alo Bhi Blo: 4 x 8192
#define G2_NSTAGE 3
#define G2_SMEM (G2_NSTAGE * G2_STAGE_B)   // 98304
#define HS2_STRIDE 130

__global__ __launch_bounds__(256, 2) void gemm2_fused(
    const __nv_bfloat16* __restrict__ Ahi, const __nv_bfloat16* __restrict__ Alo,
    const __nv_bfloat16* __restrict__ Bhi, const __nv_bfloat16* __restrict__ Blo,
    const float* __restrict__ asrc, const float* __restrict__ adst,
    const float* __restrict__ bias,
    const float* __restrict__ Wl, const float* __restrict__ bl,
    float* __restrict__ hid, float* __restrict__ yout)
{
    extern __shared__ char smem[];
    const uint32_t sb = smem_to_u32(smem);
    const int tid = threadIdx.x;
    const int wid = tid >> 5, lane = tid & 31;
    const int warpM = wid & 3, warpN = wid >> 2;     // 4 x 2
    const int rowBaseI = blockIdx.x * ROWS_PER_BLK;

    const __nv_bfloat16* srcs[4] = {
        Ahi + (size_t)rowBaseI * F_HID, Alo + (size_t)rowBaseI * F_HID,
        Bhi, Blo
    };

    auto load_stage = [&](int ck, int st) {
        uint32_t base = sb + st * G2_STAGE_B;
        #pragma unroll
        for (int i = 0; i < 8; i++) {
            int id = tid + i * 256;            // 0..2047
            int m  = id >> 9;
            int v  = id & 511;
            int row = v >> 2, c = v & 3;
            int rowc = row;
            if (m < 2 && rowBaseI + rowc >= N_NODES) rowc = N_NODES - 1 - rowBaseI;
            const char* g = (const char*)(srcs[m] + (size_t)rowc * F_HID + ck * 32) + c * 16;
            cp_async16(base + m * 8192 + sw_off(row, c * 16), g);
        }
        CP_COMMIT();
    };

    float acc[2][8][4];
    #pragma unroll
    for (int mt = 0; mt < 2; mt++)
        #pragma unroll
        for (int nt = 0; nt < 8; nt++)
            #pragma unroll
            for (int j = 0; j < 4; j++) acc[mt][nt][j] = 0.f;

    load_stage(0, 0);
    load_stage(1, 1);

    const int q = lane >> 3, r = lane & 7;
    const int aRowBase = warpM * 32 + ((q & 1) ? 8 : 0) + r;
    const int aColSel  = (q & 2) ? 8 : 0;
    const int bRowBase = warpN * 64 + ((q & 2) ? 8 : 0) + r;
    const int bColSel  = (q & 1) ? 8 : 0;

    #pragma unroll
    for (int ck = 0; ck < G2_NK; ck++) {
        if (ck < G2_NK - 1) CP_WAIT1(); else CP_WAIT0();
        __syncthreads();
        if (ck + 2 < G2_NK) load_stage(ck + 2, (ck + 2) % G2_NSTAGE);

        const uint32_t st = sb + (ck % G2_NSTAGE) * G2_STAGE_B;
        #pragma unroll
        for (int ks = 0; ks < 2; ks++) {
            const int k0 = ks * 16;
            uint32_t ah[2][4], al[2][4];
            #pragma unroll
            for (int mt = 0; mt < 2; mt++) {
                uint32_t a = st + sw_off(aRowBase + mt * 16, (k0 + aColSel) * 2);
                ldsm_x4(a, ah[mt]);
                ldsm_x4(a + 8192, al[mt]);
            }
            #pragma unroll
            for (int nt2 = 0; nt2 < 4; nt2++) {
                uint32_t a = st + 16384 + sw_off(bRowBase + nt2 * 16, (k0 + bColSel) * 2);
                uint32_t bh[4], bl_[4];
                ldsm_x4(a, bh);
                ldsm_x4(a + 8192, bl_);
                #pragma unroll
                for (int half = 0; half < 2; half++) {
                    const int nt = nt2 * 2 + half;
                    const uint32_t* bhp = bh + half * 2;
                    const uint32_t* blp = bl_ + half * 2;
                    mma_bf16(acc[0][nt], ah[0], bhp);
                    mma_bf16(acc[1][nt], ah[1], bhp);
                    mma_bf16(acc[0][nt], al[0], bhp);
                    mma_bf16(acc[1][nt], al[1], bhp);
                    mma_bf16(acc[0][nt], ah[0], blp);
                    mma_bf16(acc[1][nt], ah[1], blp);
                }
            }
        }
    }

    // ---------------- fused epilogue: agg2 + head ----------------
    __syncthreads();

    float* hs    = (float*)smem;                          // [128][130]
    float* sv    = (float*)(smem + 66560);                // 128
    float* dvv   = sv + 128;                              // 128
    float* alpha = dvv + 128;                             // [128][12]
    float* pw    = alpha + 128 * 12;                      // [128][2]

    const int g2 = lane >> 2, ti = lane & 3;
    #pragma unroll
    for (int mt = 0; mt < 2; mt++) {
        int row = warpM * 32 + mt * 16 + g2;
        #pragma unroll
        for (int nt = 0; nt < 8; nt++) {
            int col = warpN * 64 + nt * 8 + ti * 2;
            *(float2*)&hs[row * HS2_STRIDE + col]       = make_float2(acc[mt][nt][0], acc[mt][nt][1]);
            *(float2*)&hs[(row + 8) * HS2_STRIDE + col] = make_float2(acc[mt][nt][2], acc[mt][nt][3]);
        }
    }
    __syncthreads();

    const int nSess  = min(SESS_PER_BLK, B_SESS - blockIdx.x * SESS_PER_BLK);
    const int nNodes = nSess * NPS;

    for (int node = wid; node < nNodes; node += 8) {
        float ss = 0.f, dd = 0.f;
        #pragma unroll
        for (int c = lane; c < F_OUT; c += 32) {
            float h = hs[node * HS2_STRIDE + c];
            ss = fmaf(h, asrc[c], ss);
            dd = fmaf(h, adst[c], dd);
        }
        #pragma unroll
        for (int o = 16; o; o >>= 1) {
            ss += __shfl_down_sync(0xffffffffu, ss, o);
            dd += __shfl_down_sync(0xffffffffu, dd, o);
        }
        if (lane == 0) { sv[node] = ss; dvv[node] = dd; }
    }
    __syncthreads();

    if (tid < nNodes) {
        int slot = tid % NPS;
        int rbase = tid - slot;
        int s[11]; int cnt = get_srcs(slot, s);
        float d = dvv[tid];
        float e[11]; float m = -1e30f;
        for (int k = 0; k < cnt; k++) {
            float v = sv[rbase + s[k]] + d;
            v = v > 0.f ? v : 0.2f * v;
            e[k] = v; m = fmaxf(m, v);
        }
        float sum = 0.f;
        for (int k = 0; k < cnt; k++) { float t = expf(e[k] - m); e[k] = t; sum += t; }
        float inv = 1.f / sum;
        for (int k = 0; k < cnt; k++) alpha[tid * 12 + k] = e[k] * inv;
    }
    __syncthreads();

    // aggregate + bias -> hidden (global), head partials (deterministic)
    {
        const int col0 = (tid & 63) * 2;
        const int hgrp = tid >> 6;              // 0..3
        const int wp = (tid >> 5) & 1;          // warp parity within group
        const float b0 = bias[col0], b1v = bias[col0 + 1];
        const float w0 = Wl[col0],  w1 = Wl[col0 + 1];
        for (int n = hgrp; n < nNodes; n += 4) {
            int slot = n % NPS;
            int rbase = n - slot;
            int s[11]; int cnt = get_srcs(slot, s);
            float a0 = 0.f, a1 = 0.f;
            for (int k = 0; k < cnt; k++) {
                float al_ = alpha[n * 12 + k];
                float2 hv = *(const float2*)&hs[(rbase + s[k]) * HS2_STRIDE + col0];
                a0 = fmaf(al_, hv.x, a0);
                a1 = fmaf(al_, hv.y, a1);
            }
            float v0 = a0 + b0;
            float v1 = a1 + b1v;
            *(float2*)&hid[(size_t)(rowBaseI + n) * F_OUT + col0] = make_float2(v0, v1);
            float pp = fmaxf(v0, 0.f) * w0 + fmaxf(v1, 0.f) * w1;
            #pragma unroll
            for (int o = 16; o; o >>= 1)
                pp += __shfl_down_sync(0xffffffffu, pp, o);
            if (lane == 0) pw[n * 2 + wp] = pp;
        }
    }
    __syncthreads();

    if (tid < nNodes) {
        float p = pw[tid * 2] + pw[tid * 2 + 1] + bl[0];
        yout[rowBaseI + tid] = 1.f / (1.f + expf(-p));
    }
}

// ===========================================================================
extern "C" void kernel_launch(void* const* d_in, const int* in_sizes, int n_in,
                              void* d_out, int out_size)
{
    const float* x     = (const float*)d_in[1];
    const int*   click = (const int*)  d_in[4];
    const int*   query = (const int*)  d_in[5];
    const int*   docu  = (const int*)  d_in[6];
    const int*   title = (const int*)  d_in[7];
    const float* qtab  = (const float*)d_in[8];
    const float* dtab  = (const float*)d_in[9];
    const float* ttab  = (const float*)d_in[10];
    const float* ptab  = (const float*)d_in[11];
    const float* ctab  = (const float*)d_in[12];
    const float* W1    = (const float*)d_in[13];
    const float* as1   = (const float*)d_in[14];
    const float* ad1   = (const float*)d_in[15];
    const float* b1    = (const float*)d_in[16];
    const float* W2    = (const float*)d_in[17];
    const float* as2   = (const float*)d_in[18];
    const float* ad2   = (const float*)d_in[19];
    const float* b2    = (const float*)d_in[20];
    const float* Wl    = (const float*)d_in[21];
    const float* bl    = (const float*)d_in[22];

    float* out  = (float*)d_out;
    float* xout = out + OUT_X_OFF;
    float* hout = out + OUT_HID_OFF;
    float* yout = out + OUT_Y_OFF;

    __nv_bfloat16 *xhi, *xlo, *yhi, *ylo, *w1hi, *w1lo, *w2hi, *w2lo;
    cudaGetSymbolAddress((void**)&xhi,  g_xhi);
    cudaGetSymbolAddress((void**)&xlo,  g_xlo);
    cudaGetSymbolAddress((void**)&yhi,  g_yhi);
    cudaGetSymbolAddress((void**)&ylo,  g_ylo);
    cudaGetSymbolAddress((void**)&w1hi, g_w1hi);
    cudaGetSymbolAddress((void**)&w1lo, g_w1lo);
    cudaGetSymbolAddress((void**)&w2hi, g_w2hi);
    cudaGetSymbolAddress((void**)&w2lo, g_w2lo);

    cudaFuncSetAttribute(gemm1_fused, cudaFuncAttributeMaxDynamicSharedMemorySize, G1_SMEM);
    cudaFuncSetAttribute(gemm2_fused, cudaFuncAttributeMaxDynamicSharedMemorySize, G2_SMEM);

    // 1. scatter embeddings into x output slice + fused bf16 hi/lo split
    {
        long long tot = (long long)N_NODES * (K1_PAD / 4);
        build_x_kernel<<<(unsigned)((tot + 255) / 256), 256>>>(
            x, click, query, docu, title, qtab, dtab, ttab, ptab, ctab,
            xout, xhi, xlo);
    }

    // 2. weight splits
    {
        long long tot = (long long)F_HID * K1_PAD;
        conv_split<<<(unsigned)((tot + 255) / 256), 256>>>(W1, F_IN, w1hi, w1lo, K1_PAD, tot);
    }
    {
        long long tot = (long long)F_OUT * F_HID;
        conv_split<<<(unsigned)((tot + 255) / 256), 256>>>(W2, F_HID, w2hi, w2lo, F_HID, tot);
    }

    // 3. fused GEMM1 + agg1 -> y (bf16 hi/lo)
    gemm1_fused<<<NBLK, 512, G1_SMEM>>>(
        xhi, xlo, w1hi, w1lo, as1, ad1, b1, yhi, ylo);

    // 4. fused GEMM2 + agg2 + head -> hidden, y
    gemm2_fused<<<NBLK, 256, G2_SMEM>>>(
        yhi, ylo, w2hi, w2lo, as2, ad2, b2, Wl, bl, hout, yout);
}

// round 10
// speedup vs baseline: 3.0469x; 1.1304x over previous
#include <cuda_runtime.h>
#include <cuda_bf16.h>
#include <math.h>
#include <stdint.h>

#define B_SESS   8192
#define NPS      21
#define N_NODES  (B_SESS * NPS)      // 172032
#define F_IN     171
#define K1_PAD   192                 // F_IN padded to 6*32
#define F_HID    256
#define F_OUT    128
#define SESS_PER_BLK 6
#define ROWS_PER_BLK (SESS_PER_BLK * NPS)   // 126
#define NBLK ((B_SESS + SESS_PER_BLK - 1) / SESS_PER_BLK)  // 1366

// Output layout: hidden_state (N*128) | y (N*1) | x (N*171)
#define OUT_HID_OFF  0
#define OUT_Y_OFF    ((size_t)N_NODES * F_OUT)
#define OUT_X_OFF    ((size_t)N_NODES * (F_OUT + 1))

// Scratch (static device arrays: allocation-free)
__device__ __nv_bfloat16  g_xhi[(size_t)N_NODES * K1_PAD];
__device__ __nv_bfloat16  g_xlo[(size_t)N_NODES * K1_PAD];
__device__ __nv_bfloat16  g_yhi[(size_t)N_NODES * F_HID];
__device__ __nv_bfloat16  g_ylo[(size_t)N_NODES * F_HID];
__device__ __nv_bfloat16  g_w1hi[(size_t)F_HID * K1_PAD];
__device__ __nv_bfloat16  g_w1lo[(size_t)F_HID * K1_PAD];
__device__ __nv_bfloat16  g_w2hi[(size_t)F_OUT * F_HID];
__device__ __nv_bfloat16  g_w2lo[(size_t)F_OUT * F_HID];

// ===========================================================================
// helpers
// ===========================================================================
__device__ __forceinline__ uint32_t smem_to_u32(const void* p) {
    uint32_t a;
    asm("{ .reg .u64 t; cvta.to.shared.u64 t, %1; cvt.u32.u64 %0, t; }" : "=r"(a) : "l"(p));
    return a;
}
__device__ __forceinline__ void cp_async16(uint32_t dst, const void* src) {
    asm volatile("cp.async.cg.shared.global [%0], [%1], 16;" :: "r"(dst), "l"(src));
}
#define CP_COMMIT() asm volatile("cp.async.commit_group;" ::: "memory")
#define CP_WAIT0()  asm volatile("cp.async.wait_group 0;" ::: "memory")
#define CP_WAIT1()  asm volatile("cp.async.wait_group 1;" ::: "memory")

__device__ __forceinline__ void ldsm_x4(uint32_t addr, uint32_t* r) {
    asm volatile("ldmatrix.sync.aligned.m8n8.x4.shared.b16 {%0,%1,%2,%3}, [%4];"
        : "=r"(r[0]), "=r"(r[1]), "=r"(r[2]), "=r"(r[3]) : "r"(addr));
}
__device__ __forceinline__ void mma_bf16(float* d, const uint32_t* a, const uint32_t* b) {
    asm volatile("mma.sync.aligned.m16n8k16.row.col.f32.bf16.bf16.f32 "
        "{%0,%1,%2,%3}, {%4,%5,%6,%7}, {%8,%9}, {%0,%1,%2,%3};"
        : "+f"(d[0]), "+f"(d[1]), "+f"(d[2]), "+f"(d[3])
        : "r"(a[0]), "r"(a[1]), "r"(a[2]), "r"(a[3]), "r"(b[0]), "r"(b[1]));
}

// XOR bank swizzle on 64B rows (16B chunk granularity)
__device__ __forceinline__ uint32_t sw_off(int row, int colByte) {
    return (uint32_t)(row * 64 + ((((colByte >> 4) ^ ((row >> 1) & 3)) & 3) << 4));
}

__device__ __forceinline__ float lrelu(float v) { return v > 0.f ? v : 0.2f * v; }

// Branch-specialized softmax over in-neighbors (no local arrays).
// alpha layout per node (stride 12), order matches:
//   slot 0:  k=0..9 -> srcs 1..10, k=10 -> self(0)
//   slot 1..10: k0 -> 0, k1 -> slot+10, k2 -> slot (self)
//   slot 11..20: k0 -> slot-10, k1 -> slot (self)
__device__ __forceinline__ void compute_alpha(
    const float* __restrict__ sv, const float* __restrict__ dvv,
    float* __restrict__ alpha, int node)
{
    int slot = node % NPS;
    int rbase = node - slot;
    float d = dvv[node];
    float* al = alpha + node * 12;
    if (slot == 0) {
        float e0 = lrelu(sv[rbase + 1] + d);
        float e1 = lrelu(sv[rbase + 2] + d);
        float e2 = lrelu(sv[rbase + 3] + d);
        float e3 = lrelu(sv[rbase + 4] + d);
        float e4 = lrelu(sv[rbase + 5] + d);
        float e5 = lrelu(sv[rbase + 6] + d);
        float e6 = lrelu(sv[rbase + 7] + d);
        float e7 = lrelu(sv[rbase + 8] + d);
        float e8 = lrelu(sv[rbase + 9] + d);
        float e9 = lrelu(sv[rbase + 10] + d);
        float ea = lrelu(sv[rbase + 0] + d);
        float m = fmaxf(ea, fmaxf(fmaxf(fmaxf(e0, e1), fmaxf(e2, e3)),
                  fmaxf(fmaxf(fmaxf(e4, e5), fmaxf(e6, e7)), fmaxf(e8, e9))));
        e0 = expf(e0 - m); e1 = expf(e1 - m); e2 = expf(e2 - m); e3 = expf(e3 - m);
        e4 = expf(e4 - m); e5 = expf(e5 - m); e6 = expf(e6 - m); e7 = expf(e7 - m);
        e8 = expf(e8 - m); e9 = expf(e9 - m); ea = expf(ea - m);
        float inv = 1.f / (e0 + e1 + e2 + e3 + e4 + e5 + e6 + e7 + e8 + e9 + ea);
        al[0] = e0 * inv; al[1] = e1 * inv; al[2] = e2 * inv; al[3] = e3 * inv;
        al[4] = e4 * inv; al[5] = e5 * inv; al[6] = e6 * inv; al[7] = e7 * inv;
        al[8] = e8 * inv; al[9] = e9 * inv; al[10] = ea * inv;
    } else if (slot <= 10) {
        float v0 = lrelu(sv[rbase] + d);
        float v1 = lrelu(sv[rbase + slot + 10] + d);
        float v2 = lrelu(sv[rbase + slot] + d);
        float m = fmaxf(v0, fmaxf(v1, v2));
        float e0 = expf(v0 - m), e1 = expf(v1 - m), e2 = expf(v2 - m);
        float inv = 1.f / (e0 + e1 + e2);
        al[0] = e0 * inv; al[1] = e1 * inv; al[2] = e2 * inv;
    } else {
        float v0 = lrelu(sv[rbase + slot - 10] + d);
        float v1 = lrelu(sv[rbase + slot] + d);
        float m = fmaxf(v0, v1);
        float e0 = expf(v0 - m), e1 = expf(v1 - m);
        float inv = 1.f / (e0 + e1);
        al[0] = e0 * inv; al[1] = e1 * inv;
    }
}

// Branch-specialized 2-column aggregation (no local arrays).
__device__ __forceinline__ void aggregate2(
    const float* __restrict__ hs, int stride,
    const float* __restrict__ alpha, int node, int col0,
    float& a0, float& a1)
{
    int slot = node % NPS;
    int rbase = node - slot;
    const float* al = alpha + node * 12;
    a0 = 0.f; a1 = 0.f;
    if (slot == 0) {
        #pragma unroll
        for (int j = 0; j < 10; j++) {
            float2 hv = *(const float2*)&hs[(rbase + 1 + j) * stride + col0];
            a0 = fmaf(al[j], hv.x, a0);
            a1 = fmaf(al[j], hv.y, a1);
        }
        float2 hv = *(const float2*)&hs[rbase * stride + col0];
        a0 = fmaf(al[10], hv.x, a0);
        a1 = fmaf(al[10], hv.y, a1);
    } else if (slot <= 10) {
        float2 h0 = *(const float2*)&hs[rbase * stride + col0];
        float2 h1 = *(const float2*)&hs[(rbase + slot + 10) * stride + col0];
        float2 h2 = *(const float2*)&hs[(rbase + slot) * stride + col0];
        a0 = al[0] * h0.x + al[1] * h1.x + al[2] * h2.x;
        a1 = al[0] * h0.y + al[1] * h1.y + al[2] * h2.y;
    } else {
        float2 h0 = *(const float2*)&hs[(rbase + slot - 10) * stride + col0];
        float2 h1 = *(const float2*)&hs[(rbase + slot) * stride + col0];
        a0 = al[0] * h0.x + al[1] * h1.x;
        a1 = al[0] * h0.y + al[1] * h1.y;
    }
}

// ===========================================================================
// Kernel 1: build x_mod (scatter) + fused bf16 hi/lo split, 4 cols per thread
// ===========================================================================
__global__ __launch_bounds__(256) void build_x_kernel(
    const float* __restrict__ x,
    const int*   __restrict__ click,
    const int*   __restrict__ query,
    const int*   __restrict__ docu,
    const int*   __restrict__ title_id,
    const float* __restrict__ qtab,
    const float* __restrict__ dtab,
    const float* __restrict__ ttab,
    const float* __restrict__ ptab,
    const float* __restrict__ ctab,
    float* __restrict__ xout,
    __nv_bfloat16* __restrict__ xhi,
    __nv_bfloat16* __restrict__ xlo)
{
    long long t = (long long)blockIdx.x * blockDim.x + threadIdx.x;
    if (t >= (long long)N_NODES * (K1_PAD / 4)) return;
    int n  = (int)(t / (K1_PAD / 4));
    int cc = (int)(t - (long long)n * (K1_PAD / 4));
    int c0 = cc * 4;
    int b = n / NPS;
    int s = n - b * NPS;

    float4 v;
    if (c0 + 3 < 160) {
        const float* tab;
        size_t row;
        if (s == 0)            { tab = qtab; row = (size_t)query[b]; }
        else if (s <= 10)      { tab = dtab; row = (size_t)docu[b * 10 + (s - 1)]; }
        else                   { tab = ttab; row = (size_t)title_id[b * 10 + (s - 11)]; }
        v = *(const float4*)(tab + row * 160 + c0);
    } else {
        float vv[4];
        #pragma unroll
        for (int j = 0; j < 4; j++) {
            int c = c0 + j;
            float val = 0.f;
            if (c < F_IN) {
                long long xi = (long long)n * F_IN + c;
                if (s == 0) {
                    val = (c < 160) ? qtab[(size_t)query[b] * 160 + c] : x[xi];
                } else if (s <= 10) {
                    int jj = s - 1;
                    if      (c < 160)  val = dtab[(size_t)docu[b * 10 + jj] * 160 + c];
                    else if (c == 160) val = ptab[jj];
                    else if (c == 161) val = ctab[click[b]];
                    else               val = x[xi];
                } else {
                    val = (c < 160) ? ttab[(size_t)title_id[b * 10 + (s - 11)] * 160 + c] : x[xi];
                }
            }
            vv[j] = val;
        }
        v = make_float4(vv[0], vv[1], vv[2], vv[3]);
    }

    {
        long long xi = (long long)n * F_IN + c0;
        if (c0 + 3 < F_IN) {
            xout[xi] = v.x; xout[xi + 1] = v.y; xout[xi + 2] = v.z; xout[xi + 3] = v.w;
        } else {
            float vv[4] = {v.x, v.y, v.z, v.w};
            #pragma unroll
            for (int j = 0; j < 4; j++)
                if (c0 + j < F_IN) xout[xi + j] = vv[j];
        }
    }

    long long oi = (long long)n * K1_PAD + c0;
    __nv_bfloat162 h01, h23, l01, l23;
    {
        float vv[4] = {v.x, v.y, v.z, v.w};
        __nv_bfloat16 h[4], l[4];
        #pragma unroll
        for (int j = 0; j < 4; j++) {
            h[j] = __float2bfloat16(vv[j]);
            l[j] = __float2bfloat16(vv[j] - __bfloat162float(h[j]));
        }
        h01 = __nv_bfloat162(h[0], h[1]); h23 = __nv_bfloat162(h[2], h[3]);
        l01 = __nv_bfloat162(l[0], l[1]); l23 = __nv_bfloat162(l[2], l[3]);
    }
    *(__nv_bfloat162*)(xhi + oi)     = h01;
    *(__nv_bfloat162*)(xhi + oi + 2) = h23;
    *(__nv_bfloat162*)(xlo + oi)     = l01;
    *(__nv_bfloat162*)(xlo + oi + 2) = l23;
}

// ===========================================================================
// Kernel 2: fp32 -> bf16 hi/lo split for weights (with K padding)
// ===========================================================================
__global__ __launch_bounds__(256) void conv_split(
    const float* __restrict__ src, int Ksrc,
    __nv_bfloat16* __restrict__ hi, __nv_bfloat16* __restrict__ lo,
    int Kdst, long long total)
{
    long long idx = (long long)blockIdx.x * blockDim.x + threadIdx.x;
    if (idx >= total) return;
    long long row = idx / Kdst;
    int c = (int)(idx - row * Kdst);
    float v = (c < Ksrc) ? src[row * Ksrc + c] : 0.f;
    __nv_bfloat16 h = __float2bfloat16(v);
    hi[idx] = h;
    lo[idx] = __float2bfloat16(v - __bfloat162float(h));
}

// ===========================================================================
// Kernel 3: fused GEMM1 (x @ W1^T, split-3 bf16 HMMA) + GAT agg layer 1
// Block: 512 thr, 16 warps (4x4), tile 128(126 used) x 256, K=192.
// ===========================================================================
#define G1_NK 6
#define G1_STAGE_B 49152        // Ahi(8192) Alo(8192) Bhi(16384) Blo(16384)
#define G1_NSTAGE 3
#define G1_SMEM (G1_NSTAGE * G1_STAGE_B)   // 147456
#define HS1_STRIDE 258

__global__ __launch_bounds__(512, 1) void gemm1_fused(
    const __nv_bfloat16* __restrict__ Ahi, const __nv_bfloat16* __restrict__ Alo,
    const __nv_bfloat16* __restrict__ Bhi, const __nv_bfloat16* __restrict__ Blo,
    const float* __restrict__ asrc, const float* __restrict__ adst,
    const float* __restrict__ bias,
    __nv_bfloat16* __restrict__ Yhi, __nv_bfloat16* __restrict__ Ylo)
{
    extern __shared__ char smem[];
    const uint32_t sb = smem_to_u32(smem);
    const int tid = threadIdx.x;
    const int wid = tid >> 5, lane = tid & 31;
    const int warpM = wid & 3, warpN = wid >> 2;     // 4 x 4 warp grid
    const int rowBaseI = blockIdx.x * ROWS_PER_BLK;

    const __nv_bfloat16* srcA[2] = { Ahi + (size_t)rowBaseI * K1_PAD,
                                     Alo + (size_t)rowBaseI * K1_PAD };
    const __nv_bfloat16* srcB[2] = { Bhi, Blo };

    auto load_stage = [&](int ck, int st) {
        uint32_t base = sb + st * G1_STAGE_B;
        #pragma unroll
        for (int i = 0; i < 6; i++) {
            int id = tid + i * 512;            // 0..3071
            if (id < 1024) {                   // A arrays: 2 x 128 rows
                int m = id >> 9;
                int v = id & 511;
                int row = v >> 2, c = v & 3;
                int rowc = row;
                if (rowBaseI + rowc >= N_NODES) rowc = N_NODES - 1 - rowBaseI;
                const char* g = (const char*)(srcA[m] + (size_t)rowc * K1_PAD + ck * 32) + c * 16;
                cp_async16(base + m * 8192 + sw_off(row, c * 16), g);
            } else {                           // B arrays: 2 x 256 rows
                int idb = id - 1024;
                int m = idb >> 10;
                int v = idb & 1023;
                int row = v >> 2, c = v & 3;
                const char* g = (const char*)(srcB[m] + (size_t)row * K1_PAD + ck * 32) + c * 16;
                cp_async16(base + 16384 + m * 16384 + sw_off(row, c * 16), g);
            }
        }
        CP_COMMIT();
    };

    float acc[2][8][4];
    #pragma unroll
    for (int mt = 0; mt < 2; mt++)
        #pragma unroll
        for (int nt = 0; nt < 8; nt++)
            #pragma unroll
            for (int j = 0; j < 4; j++) acc[mt][nt][j] = 0.f;

    load_stage(0, 0);
    load_stage(1, 1);

    const int q = lane >> 3, r = lane & 7;
    const int aRowBase = warpM * 32 + ((q & 1) ? 8 : 0) + r;
    const int aColSel  = (q & 2) ? 8 : 0;
    const int bRowBase = warpN * 64 + ((q & 2) ? 8 : 0) + r;
    const int bColSel  = (q & 1) ? 8 : 0;

    #pragma unroll
    for (int ck = 0; ck < G1_NK; ck++) {
        if (ck < G1_NK - 1) CP_WAIT1(); else CP_WAIT0();
        __syncthreads();
        if (ck + 2 < G1_NK) load_stage(ck + 2, (ck + 2) % G1_NSTAGE);

        const uint32_t st = sb + (ck % G1_NSTAGE) * G1_STAGE_B;
        #pragma unroll
        for (int ks = 0; ks < 2; ks++) {
            const int k0 = ks * 16;
            uint32_t ah[2][4], al[2][4];
            #pragma unroll
            for (int mt = 0; mt < 2; mt++) {
                uint32_t a = st + sw_off(aRowBase + mt * 16, (k0 + aColSel) * 2);
                ldsm_x4(a, ah[mt]);
                ldsm_x4(a + 8192, al[mt]);
            }
            #pragma unroll
            for (int nt2 = 0; nt2 < 4; nt2++) {
                uint32_t a = st + 16384 + sw_off(bRowBase + nt2 * 16, (k0 + bColSel) * 2);
                uint32_t bh[4], bl[4];
                ldsm_x4(a, bh);
                ldsm_x4(a + 16384, bl);
                #pragma unroll
                for (int half = 0; half < 2; half++) {
                    const int nt = nt2 * 2 + half;
                    const uint32_t* bhp = bh + half * 2;
                    const uint32_t* blp = bl + half * 2;
                    mma_bf16(acc[0][nt], ah[0], bhp);
                    mma_bf16(acc[1][nt], ah[1], bhp);
                    mma_bf16(acc[0][nt], al[0], bhp);
                    mma_bf16(acc[1][nt], al[1], bhp);
                    mma_bf16(acc[0][nt], ah[0], blp);
                    mma_bf16(acc[1][nt], ah[1], blp);
                }
            }
        }
    }

    // ---------------- fused epilogue: GAT aggregation ----------------
    __syncthreads();   // all warps done reading stages: reuse smem

    float* hs    = (float*)smem;                          // [128][258]
    float* sv    = (float*)(smem + 132096);               // 128
    float* dvv   = sv + 128;                              // 128
    float* alpha = dvv + 128;                             // [128][12]

    const int g2 = lane >> 2, ti = lane & 3;
    #pragma unroll
    for (int mt = 0; mt < 2; mt++) {
        int row = warpM * 32 + mt * 16 + g2;
        #pragma unroll
        for (int nt = 0; nt < 8; nt++) {
            int col = warpN * 64 + nt * 8 + ti * 2;
            *(float2*)&hs[row * HS1_STRIDE + col]       = make_float2(acc[mt][nt][0], acc[mt][nt][1]);
            *(float2*)&hs[(row + 8) * HS1_STRIDE + col] = make_float2(acc[mt][nt][2], acc[mt][nt][3]);
        }
    }
    __syncthreads();

    const int nSess  = min(SESS_PER_BLK, B_SESS - blockIdx.x * SESS_PER_BLK);
    const int nNodes = nSess * NPS;

    // per-node attention dots
    for (int node = wid; node < nNodes; node += 16) {
        float ss = 0.f, dd = 0.f;
        #pragma unroll
        for (int c = lane; c < F_HID; c += 32) {
            float h = hs[node * HS1_STRIDE + c];
            ss = fmaf(h, asrc[c], ss);
            dd = fmaf(h, adst[c], dd);
        }
        #pragma unroll
        for (int o = 16; o; o >>= 1) {
            ss += __shfl_down_sync(0xffffffffu, ss, o);
            dd += __shfl_down_sync(0xffffffffu, dd, o);
        }
        if (lane == 0) { sv[node] = ss; dvv[node] = dd; }
    }
    __syncthreads();

    if (tid < nNodes) compute_alpha(sv, dvv, alpha, tid);
    __syncthreads();

    // aggregate + bias + relu -> y bf16 hi/lo (2 cols per thread)
    {
        const int col0 = (tid & 127) * 2;
        const int hgrp = tid >> 7;              // 0..3 (warp-uniform)
        const float b0 = bias[col0], b1v = bias[col0 + 1];
        for (int n = hgrp; n < nNodes; n += 4) {
            float a0, a1;
            aggregate2(hs, HS1_STRIDE, alpha, n, col0, a0, a1);
            float v0 = fmaxf(a0 + b0, 0.f);
            float v1 = fmaxf(a1 + b1v, 0.f);
            __nv_bfloat16 h0 = __float2bfloat16(v0);
            __nv_bfloat16 h1 = __float2bfloat16(v1);
            __nv_bfloat16 l0 = __float2bfloat16(v0 - __bfloat162float(h0));
            __nv_bfloat16 l1 = __float2bfloat16(v1 - __bfloat162float(h1));
            size_t off = (size_t)(rowBaseI + n) * F_HID + col0;
            *(__nv_bfloat162*)(Yhi + off) = __nv_bfloat162(h0, h1);
            *(__nv_bfloat162*)(Ylo + off) = __nv_bfloat162(l0, l1);
        }
    }
}

// ===========================================================================
// Kernel 4: fused GEMM2 (y @ W2^T) + GAT agg layer 2 + sigmoid head
// Block: 256 thr, 8 warps (4x2), tile 128(126) x 128, K=256.
// ===========================================================================
#define G2_NK 8
#define G2_STAGE_B 32768        // Ahi Alo Bhi Blo: 4 x 8192
#define G2_NSTAGE 3
#define G2_SMEM (G2_NSTAGE * G2_STAGE_B)   // 98304
#define HS2_STRIDE 130

__global__ __launch_bounds__(256, 2) void gemm2_fused(
    const __nv_bfloat16* __restrict__ Ahi, const __nv_bfloat16* __restrict__ Alo,
    const __nv_bfloat16* __restrict__ Bhi, const __nv_bfloat16* __restrict__ Blo,
    const float* __restrict__ asrc, const float* __restrict__ adst,
    const float* __restrict__ bias,
    const float* __restrict__ Wl, const float* __restrict__ bl,
    float* __restrict__ hid, float* __restrict__ yout)
{
    extern __shared__ char smem[];
    const uint32_t sb = smem_to_u32(smem);
    const int tid = threadIdx.x;
    const int wid = tid >> 5, lane = tid & 31;
    const int warpM = wid & 3, warpN = wid >> 2;     // 4 x 2
    const int rowBaseI = blockIdx.x * ROWS_PER_BLK;

    const __nv_bfloat16* srcs[4] = {
        Ahi + (size_t)rowBaseI * F_HID, Alo + (size_t)rowBaseI * F_HID,
        Bhi, Blo
    };

    auto load_stage = [&](int ck, int st) {
        uint32_t base = sb + st * G2_STAGE_B;
        #pragma unroll
        for (int i = 0; i < 8; i++) {
            int id = tid + i * 256;            // 0..2047
            int m  = id >> 9;
            int v  = id & 511;
            int row = v >> 2, c = v & 3;
            int rowc = row;
            if (m < 2 && rowBaseI + rowc >= N_NODES) rowc = N_NODES - 1 - rowBaseI;
            const char* g = (const char*)(srcs[m] + (size_t)rowc * F_HID + ck * 32) + c * 16;
            cp_async16(base + m * 8192 + sw_off(row, c * 16), g);
        }
        CP_COMMIT();
    };

    float acc[2][8][4];
    #pragma unroll
    for (int mt = 0; mt < 2; mt++)
        #pragma unroll
        for (int nt = 0; nt < 8; nt++)
            #pragma unroll
            for (int j = 0; j < 4; j++) acc[mt][nt][j] = 0.f;

    load_stage(0, 0);
    load_stage(1, 1);

    const int q = lane >> 3, r = lane & 7;
    const int aRowBase = warpM * 32 + ((q & 1) ? 8 : 0) + r;
    const int aColSel  = (q & 2) ? 8 : 0;
    const int bRowBase = warpN * 64 + ((q & 2) ? 8 : 0) + r;
    const int bColSel  = (q & 1) ? 8 : 0;

    #pragma unroll
    for (int ck = 0; ck < G2_NK; ck++) {
        if (ck < G2_NK - 1) CP_WAIT1(); else CP_WAIT0();
        __syncthreads();
        if (ck + 2 < G2_NK) load_stage(ck + 2, (ck + 2) % G2_NSTAGE);

        const uint32_t st = sb + (ck % G2_NSTAGE) * G2_STAGE_B;
        #pragma unroll
        for (int ks = 0; ks < 2; ks++) {
            const int k0 = ks * 16;
            uint32_t ah[2][4], al[2][4];
            #pragma unroll
            for (int mt = 0; mt < 2; mt++) {
                uint32_t a = st + sw_off(aRowBase + mt * 16, (k0 + aColSel) * 2);
                ldsm_x4(a, ah[mt]);
                ldsm_x4(a + 8192, al[mt]);
            }
            #pragma unroll
            for (int nt2 = 0; nt2 < 4; nt2++) {
                uint32_t a = st + 16384 + sw_off(bRowBase + nt2 * 16, (k0 + bColSel) * 2);
                uint32_t bh[4], bl_[4];
                ldsm_x4(a, bh);
                ldsm_x4(a + 8192, bl_);
                #pragma unroll
                for (int half = 0; half < 2; half++) {
                    const int nt = nt2 * 2 + half;
                    const uint32_t* bhp = bh + half * 2;
                    const uint32_t* blp = bl_ + half * 2;
                    mma_bf16(acc[0][nt], ah[0], bhp);
                    mma_bf16(acc[1][nt], ah[1], bhp);
                    mma_bf16(acc[0][nt], al[0], bhp);
                    mma_bf16(acc[1][nt], al[1], bhp);
                    mma_bf16(acc[0][nt], ah[0], blp);
                    mma_bf16(acc[1][nt], ah[1], blp);
                }
            }
        }
    }

    // ---------------- fused epilogue: agg2 + head ----------------
    __syncthreads();

    float* hs    = (float*)smem;                          // [128][130]
    float* sv    = (float*)(smem + 66560);                // 128
    float* dvv   = sv + 128;                              // 128
    float* alpha = dvv + 128;                             // [128][12]
    float* pw    = alpha + 128 * 12;                      // [128][2]

    const int g2 = lane >> 2, ti = lane & 3;
    #pragma unroll
    for (int mt = 0; mt < 2; mt++) {
        int row = warpM * 32 + mt * 16 + g2;
        #pragma unroll
        for (int nt = 0; nt < 8; nt++) {
            int col = warpN * 64 + nt * 8 + ti * 2;
            *(float2*)&hs[row * HS2_STRIDE + col]       = make_float2(acc[mt][nt][0], acc[mt][nt][1]);
            *(float2*)&hs[(row + 8) * HS2_STRIDE + col] = make_float2(acc[mt][nt][2], acc[mt][nt][3]);
        }
    }
    __syncthreads();

    const int nSess  = min(SESS_PER_BLK, B_SESS - blockIdx.x * SESS_PER_BLK);
    const int nNodes = nSess * NPS;

    for (int node = wid; node < nNodes; node += 8) {
        float ss = 0.f, dd = 0.f;
        #pragma unroll
        for (int c = lane; c < F_OUT; c += 32) {
            float h = hs[node * HS2_STRIDE + c];
            ss = fmaf(h, asrc[c], ss);
            dd = fmaf(h, adst[c], dd);
        }
        #pragma unroll
        for (int o = 16; o; o >>= 1) {
            ss += __shfl_down_sync(0xffffffffu, ss, o);
            dd += __shfl_down_sync(0xffffffffu, dd, o);
        }
        if (lane == 0) { sv[node] = ss; dvv[node] = dd; }
    }
    __syncthreads();

    if (tid < nNodes) compute_alpha(sv, dvv, alpha, tid);
    __syncthreads();

    // aggregate + bias -> hidden (global), head partials (deterministic)
    {
        const int col0 = (tid & 63) * 2;
        const int hgrp = tid >> 6;              // 0..3 (warp-uniform)
        const int wp = (tid >> 5) & 1;          // warp parity within group
        const float b0 = bias[col0], b1v = bias[col0 + 1];
        const float w0 = Wl[col0],  w1 = Wl[col0 + 1];
        for (int n = hgrp; n < nNodes; n += 4) {
            float a0, a1;
            aggregate2(hs, HS2_STRIDE, alpha, n, col0, a0, a1);
            float v0 = a0 + b0;
            float v1 = a1 + b1v;
            *(float2*)&hid[(size_t)(rowBaseI + n) * F_OUT + col0] = make_float2(v0, v1);
            float pp = fmaxf(v0, 0.f) * w0 + fmaxf(v1, 0.f) * w1;
            #pragma unroll
            for (int o = 16; o; o >>= 1)
                pp += __shfl_down_sync(0xffffffffu, pp, o);
            if (lane == 0) pw[n * 2 + wp] = pp;
        }
    }
    __syncthreads();

    if (tid < nNodes) {
        float p = pw[tid * 2] + pw[tid * 2 + 1] + bl[0];
        yout[rowBaseI + tid] = 1.f / (1.f + expf(-p));
    }
}

// ===========================================================================
extern "C" void kernel_launch(void* const* d_in, const int* in_sizes, int n_in,
                              void* d_out, int out_size)
{
    const float* x     = (const float*)d_in[1];
    const int*   click = (const int*)  d_in[4];
    const int*   query = (const int*)  d_in[5];
    const int*   docu  = (const int*)  d_in[6];
    const int*   title = (const int*)  d_in[7];
    const float* qtab  = (const float*)d_in[8];
    const float* dtab  = (const float*)d_in[9];
    const float* ttab  = (const float*)d_in[10];
    const float* ptab  = (const float*)d_in[11];
    const float* ctab  = (const float*)d_in[12];
    const float* W1    = (const float*)d_in[13];
    const float* as1   = (const float*)d_in[14];
    const float* ad1   = (const float*)d_in[15];
    const float* b1    = (const float*)d_in[16];
    const float* W2    = (const float*)d_in[17];
    const float* as2   = (const float*)d_in[18];
    const float* ad2   = (const float*)d_in[19];
    const float* b2    = (const float*)d_in[20];
    const float* Wl    = (const float*)d_in[21];
    const float* bl    = (const float*)d_in[22];

    float* out  = (float*)d_out;
    float* xout = out + OUT_X_OFF;
    float* hout = out + OUT_HID_OFF;
    float* yout = out + OUT_Y_OFF;

    __nv_bfloat16 *xhi, *xlo, *yhi, *ylo, *w1hi, *w1lo, *w2hi, *w2lo;
    cudaGetSymbolAddress((void**)&xhi,  g_xhi);
    cudaGetSymbolAddress((void**)&xlo,  g_xlo);
    cudaGetSymbolAddress((void**)&yhi,  g_yhi);
    cudaGetSymbolAddress((void**)&ylo,  g_ylo);
    cudaGetSymbolAddress((void**)&w1hi, g_w1hi);
    cudaGetSymbolAddress((void**)&w1lo, g_w1lo);
    cudaGetSymbolAddress((void**)&w2hi, g_w2hi);
    cudaGetSymbolAddress((void**)&w2lo, g_w2lo);

    cudaFuncSetAttribute(gemm1_fused, cudaFuncAttributeMaxDynamicSharedMemorySize, G1_SMEM);
    cudaFuncSetAttribute(gemm2_fused, cudaFuncAttributeMaxDynamicSharedMemorySize, G2_SMEM);

    // 1. scatter embeddings into x output slice + fused bf16 hi/lo split
    {
        long long tot = (long long)N_NODES * (K1_PAD / 4);
        build_x_kernel<<<(unsigned)((tot + 255) / 256), 256>>>(
            x, click, query, docu, title, qtab, dtab, ttab, ptab, ctab,
            xout, xhi, xlo);
    }

    // 2. weight splits
    {
        long long tot = (long long)F_HID * K1_PAD;
        conv_split<<<(unsigned)((tot + 255) / 256), 256>>>(W1, F_IN, w1hi, w1lo, K1_PAD, tot);
    }
    {
        long long tot = (long long)F_OUT * F_HID;
        conv_split<<<(unsigned)((tot + 255) / 256), 256>>>(W2, F_HID, w2hi, w2lo, F_HID, tot);
    }

    // 3. fused GEMM1 + agg1 -> y (bf16 hi/lo)
    gemm1_fused<<<NBLK, 512, G1_SMEM>>>(
        xhi, xlo, w1hi, w1lo, as1, ad1, b1, yhi, ylo);

    // 4. fused GEMM2 + agg2 + head -> hidden, y
    gemm2_fused<<<NBLK, 256, G2_SMEM>>>(
        yhi, ylo, w2hi, w2lo, as2, ad2, b2, Wl, bl, hout, yout);
}

// round 12
// speedup vs baseline: 3.1375x; 1.0297x over previous
#include <cuda_runtime.h>
#include <cuda_bf16.h>
#include <math.h>
#include <stdint.h>

#define B_SESS   8192
#define NPS      21
#define N_NODES  (B_SESS * NPS)      // 172032
#define F_IN     171
#define K1_PAD   192                 // F_IN padded to 6*32
#define F_HID    256
#define F_OUT    128

// GEMM2 blocking (unchanged)
#define SESS_PER_BLK 6
#define ROWS_PER_BLK (SESS_PER_BLK * NPS)   // 126
#define NBLK ((B_SESS + SESS_PER_BLK - 1) / SESS_PER_BLK)  // 1366

// GEMM1 blocking (3 sessions, 64-row tile, 2 CTAs/SM)
#define G1_SESS 3
#define G1_ROWS (G1_SESS * NPS)             // 63
#define G1_NBLK ((B_SESS + G1_SESS - 1) / G1_SESS)  // 2731

// Output layout: hidden_state (N*128) | y (N*1) | x (N*171)
#define OUT_HID_OFF  0
#define OUT_Y_OFF    ((size_t)N_NODES * F_OUT)
#define OUT_X_OFF    ((size_t)N_NODES * (F_OUT + 1))

// Scratch (static device arrays: allocation-free)
__device__ __nv_bfloat16  g_xhi[(size_t)N_NODES * K1_PAD];
__device__ __nv_bfloat16  g_xlo[(size_t)N_NODES * K1_PAD];
__device__ __nv_bfloat16  g_yhi[(size_t)N_NODES * F_HID];
__device__ __nv_bfloat16  g_ylo[(size_t)N_NODES * F_HID];
__device__ __nv_bfloat16  g_w1hi[(size_t)F_HID * K1_PAD];
__device__ __nv_bfloat16  g_w1lo[(size_t)F_HID * K1_PAD];
__device__ __nv_bfloat16  g_w2hi[(size_t)F_OUT * F_HID];
__device__ __nv_bfloat16  g_w2lo[(size_t)F_OUT * F_HID];

// ===========================================================================
// helpers
// ===========================================================================
__device__ __forceinline__ uint32_t smem_to_u32(const void* p) {
    uint32_t a;
    asm("{ .reg .u64 t; cvta.to.shared.u64 t, %1; cvt.u32.u64 %0, t; }" : "=r"(a) : "l"(p));
    return a;
}
__device__ __forceinline__ void cp_async16(uint32_t dst, const void* src) {
    asm volatile("cp.async.cg.shared.global [%0], [%1], 16;" :: "r"(dst), "l"(src));
}
#define CP_COMMIT() asm volatile("cp.async.commit_group;" ::: "memory")
#define CP_WAIT0()  asm volatile("cp.async.wait_group 0;" ::: "memory")
#define CP_WAIT1()  asm volatile("cp.async.wait_group 1;" ::: "memory")

__device__ __forceinline__ void ldsm_x4(uint32_t addr, uint32_t* r) {
    asm volatile("ldmatrix.sync.aligned.m8n8.x4.shared.b16 {%0,%1,%2,%3}, [%4];"
        : "=r"(r[0]), "=r"(r[1]), "=r"(r[2]), "=r"(r[3]) : "r"(addr));
}
__device__ __forceinline__ void mma_bf16(float* d, const uint32_t* a, const uint32_t* b) {
    asm volatile("mma.sync.aligned.m16n8k16.row.col.f32.bf16.bf16.f32 "
        "{%0,%1,%2,%3}, {%4,%5,%6,%7}, {%8,%9}, {%0,%1,%2,%3};"
        : "+f"(d[0]), "+f"(d[1]), "+f"(d[2]), "+f"(d[3])
        : "r"(a[0]), "r"(a[1]), "r"(a[2]), "r"(a[3]), "r"(b[0]), "r"(b[1]));
}

// XOR bank swizzle on 64B rows (16B chunk granularity)
__device__ __forceinline__ uint32_t sw_off(int row, int colByte) {
    return (uint32_t)(row * 64 + ((((colByte >> 4) ^ ((row >> 1) & 3)) & 3) << 4));
}

__device__ __forceinline__ float lrelu(float v) { return v > 0.f ? v : 0.2f * v; }

// Branch-specialized softmax over in-neighbors (no local arrays).
__device__ __forceinline__ void compute_alpha(
    const float* __restrict__ sv, const float* __restrict__ dvv,
    float* __restrict__ alpha, int node)
{
    int slot = node % NPS;
    int rbase = node - slot;
    float d = dvv[node];
    float* al = alpha + node * 12;
    if (slot == 0) {
        float e0 = lrelu(sv[rbase + 1] + d);
        float e1 = lrelu(sv[rbase + 2] + d);
        float e2 = lrelu(sv[rbase + 3] + d);
        float e3 = lrelu(sv[rbase + 4] + d);
        float e4 = lrelu(sv[rbase + 5] + d);
        float e5 = lrelu(sv[rbase + 6] + d);
        float e6 = lrelu(sv[rbase + 7] + d);
        float e7 = lrelu(sv[rbase + 8] + d);
        float e8 = lrelu(sv[rbase + 9] + d);
        float e9 = lrelu(sv[rbase + 10] + d);
        float ea = lrelu(sv[rbase + 0] + d);
        float m = fmaxf(ea, fmaxf(fmaxf(fmaxf(e0, e1), fmaxf(e2, e3)),
                  fmaxf(fmaxf(fmaxf(e4, e5), fmaxf(e6, e7)), fmaxf(e8, e9))));
        e0 = expf(e0 - m); e1 = expf(e1 - m); e2 = expf(e2 - m); e3 = expf(e3 - m);
        e4 = expf(e4 - m); e5 = expf(e5 - m); e6 = expf(e6 - m); e7 = expf(e7 - m);
        e8 = expf(e8 - m); e9 = expf(e9 - m); ea = expf(ea - m);
        float inv = 1.f / (e0 + e1 + e2 + e3 + e4 + e5 + e6 + e7 + e8 + e9 + ea);
        al[0] = e0 * inv; al[1] = e1 * inv; al[2] = e2 * inv; al[3] = e3 * inv;
        al[4] = e4 * inv; al[5] = e5 * inv; al[6] = e6 * inv; al[7] = e7 * inv;
        al[8] = e8 * inv; al[9] = e9 * inv; al[10] = ea * inv;
    } else if (slot <= 10) {
        float v0 = lrelu(sv[rbase] + d);
        float v1 = lrelu(sv[rbase + slot + 10] + d);
        float v2 = lrelu(sv[rbase + slot] + d);
        float m = fmaxf(v0, fmaxf(v1, v2));
        float e0 = expf(v0 - m), e1 = expf(v1 - m), e2 = expf(v2 - m);
        float inv = 1.f / (e0 + e1 + e2);
        al[0] = e0 * inv; al[1] = e1 * inv; al[2] = e2 * inv;
    } else {
        float v0 = lrelu(sv[rbase + slot - 10] + d);
        float v1 = lrelu(sv[rbase + slot] + d);
        float m = fmaxf(v0, v1);
        float e0 = expf(v0 - m), e1 = expf(v1 - m);
        float inv = 1.f / (e0 + e1);
        al[0] = e0 * inv; al[1] = e1 * inv;
    }
}

// Branch-specialized 2-column aggregation (no local arrays).
__device__ __forceinline__ void aggregate2(
    const float* __restrict__ hs, int stride,
    const float* __restrict__ alpha, int node, int col0,
    float& a0, float& a1)
{
    int slot = node % NPS;
    int rbase = node - slot;
    const float* al = alpha + node * 12;
    a0 = 0.f; a1 = 0.f;
    if (slot == 0) {
        #pragma unroll
        for (int j = 0; j < 10; j++) {
            float2 hv = *(const float2*)&hs[(rbase + 1 + j) * stride + col0];
            a0 = fmaf(al[j], hv.x, a0);
            a1 = fmaf(al[j], hv.y, a1);
        }
        float2 hv = *(const float2*)&hs[rbase * stride + col0];
        a0 = fmaf(al[10], hv.x, a0);
        a1 = fmaf(al[10], hv.y, a1);
    } else if (slot <= 10) {
        float2 h0 = *(const float2*)&hs[rbase * stride + col0];
        float2 h1 = *(const float2*)&hs[(rbase + slot + 10) * stride + col0];
        float2 h2 = *(const float2*)&hs[(rbase + slot) * stride + col0];
        a0 = al[0] * h0.x + al[1] * h1.x + al[2] * h2.x;
        a1 = al[0] * h0.y + al[1] * h1.y + al[2] * h2.y;
    } else {
        float2 h0 = *(const float2*)&hs[(rbase + slot - 10) * stride + col0];
        float2 h1 = *(const float2*)&hs[(rbase + slot) * stride + col0];
        a0 = al[0] * h0.x + al[1] * h1.x;
        a1 = al[0] * h0.y + al[1] * h1.y;
    }
}

// ===========================================================================
// Kernel 1: build x_mod (scatter) + fused bf16 hi/lo split, 4 cols per thread
// ===========================================================================
__global__ __launch_bounds__(256) void build_x_kernel(
    const float* __restrict__ x,
    const int*   __restrict__ click,
    const int*   __restrict__ query,
    const int*   __restrict__ docu,
    const int*   __restrict__ title_id,
    const float* __restrict__ qtab,
    const float* __restrict__ dtab,
    const float* __restrict__ ttab,
    const float* __restrict__ ptab,
    const float* __restrict__ ctab,
    float* __restrict__ xout,
    __nv_bfloat16* __restrict__ xhi,
    __nv_bfloat16* __restrict__ xlo)
{
    long long t = (long long)blockIdx.x * blockDim.x + threadIdx.x;
    if (t >= (long long)N_NODES * (K1_PAD / 4)) return;
    int n  = (int)(t / (K1_PAD / 4));
    int cc = (int)(t - (long long)n * (K1_PAD / 4));
    int c0 = cc * 4;
    int b = n / NPS;
    int s = n - b * NPS;

    float4 v;
    if (c0 + 3 < 160) {
        const float* tab;
        size_t row;
        if (s == 0)            { tab = qtab; row = (size_t)query[b]; }
        else if (s <= 10)      { tab = dtab; row = (size_t)docu[b * 10 + (s - 1)]; }
        else                   { tab = ttab; row = (size_t)title_id[b * 10 + (s - 11)]; }
        v = *(const float4*)(tab + row * 160 + c0);
    } else {
        float vv[4];
        #pragma unroll
        for (int j = 0; j < 4; j++) {
            int c = c0 + j;
            float val = 0.f;
            if (c < F_IN) {
                long long xi = (long long)n * F_IN + c;
                if (s == 0) {
                    val = (c < 160) ? qtab[(size_t)query[b] * 160 + c] : x[xi];
                } else if (s <= 10) {
                    int jj = s - 1;
                    if      (c < 160)  val = dtab[(size_t)docu[b * 10 + jj] * 160 + c];
                    else if (c == 160) val = ptab[jj];
                    else if (c == 161) val = ctab[click[b]];
                    else               val = x[xi];
                } else {
                    val = (c < 160) ? ttab[(size_t)title_id[b * 10 + (s - 11)] * 160 + c] : x[xi];
                }
            }
            vv[j] = val;
        }
        v = make_float4(vv[0], vv[1], vv[2], vv[3]);
    }

    {
        long long xi = (long long)n * F_IN + c0;
        if (c0 + 3 < F_IN) {
            xout[xi] = v.x; xout[xi + 1] = v.y; xout[xi + 2] = v.z; xout[xi + 3] = v.w;
        } else {
            float vv[4] = {v.x, v.y, v.z, v.w};
            #pragma unroll
            for (int j = 0; j < 4; j++)
                if (c0 + j < F_IN) xout[xi + j] = vv[j];
        }
    }

    long long oi = (long long)n * K1_PAD + c0;
    __nv_bfloat162 h01, h23, l01, l23;
    {
        float vv[4] = {v.x, v.y, v.z, v.w};
        __nv_bfloat16 h[4], l[4];
        #pragma unroll
        for (int j = 0; j < 4; j++) {
            h[j] = __float2bfloat16(vv[j]);
            l[j] = __float2bfloat16(vv[j] - __bfloat162float(h[j]));
        }
        h01 = __nv_bfloat162(h[0], h[1]); h23 = __nv_bfloat162(h[2], h[3]);
        l01 = __nv_bfloat162(l[0], l[1]); l23 = __nv_bfloat162(l[2], l[3]);
    }
    *(__nv_bfloat162*)(xhi + oi)     = h01;
    *(__nv_bfloat162*)(xhi + oi + 2) = h23;
    *(__nv_bfloat162*)(xlo + oi)     = l01;
    *(__nv_bfloat162*)(xlo + oi + 2) = l23;
}

// ===========================================================================
// Kernel 2: fp32 -> bf16 hi/lo split for weights (with K padding)
// ===========================================================================
__global__ __launch_bounds__(256) void conv_split(
    const float* __restrict__ src, int Ksrc,
    __nv_bfloat16* __restrict__ hi, __nv_bfloat16* __restrict__ lo,
    int Kdst, long long total)
{
    long long idx = (long long)blockIdx.x * blockDim.x + threadIdx.x;
    if (idx >= total) return;
    long long row = idx / Kdst;
    int c = (int)(idx - row * Kdst);
    float v = (c < Ksrc) ? src[row * Ksrc + c] : 0.f;
    __nv_bfloat16 h = __float2bfloat16(v);
    hi[idx] = h;
    lo[idx] = __float2bfloat16(v - __bfloat162float(h));
}

// ===========================================================================
// Kernel 3: fused GEMM1 (x @ W1^T, split-3 bf16 HMMA) + GAT agg layer 1
// Block: 256 thr, 8 warps (2x4), tile 64(63 used) x 256, K=192.
// 2-stage pipeline, 2 CTAs/SM: epilogue overlaps co-resident CTA's mainloop.
// ===========================================================================
#define G1_NK 6
#define G1_ARRA 4096            // 64 rows x 64B
#define G1_ARRB 16384           // 256 rows x 64B
#define G1_STAGE_B (2 * G1_ARRA + 2 * G1_ARRB)   // 40960
#define G1_NSTAGE 2
#define G1_SMEM (G1_NSTAGE * G1_STAGE_B)   // 81920
#define HS1_STRIDE 258

__global__ __launch_bounds__(256, 2) void gemm1_fused(
    const __nv_bfloat16* __restrict__ Ahi, const __nv_bfloat16* __restrict__ Alo,
    const __nv_bfloat16* __restrict__ Bhi, const __nv_bfloat16* __restrict__ Blo,
    const float* __restrict__ asrc, const float* __restrict__ adst,
    const float* __restrict__ bias,
    __nv_bfloat16* __restrict__ Yhi, __nv_bfloat16* __restrict__ Ylo)
{
    extern __shared__ char smem[];
    const uint32_t sb = smem_to_u32(smem);
    const int tid = threadIdx.x;
    const int wid = tid >> 5, lane = tid & 31;
    const int warpM = wid & 1, warpN = wid >> 1;     // 2 x 4 warp grid
    const int rowBaseI = blockIdx.x * G1_ROWS;

    const __nv_bfloat16* srcA[2] = { Ahi + (size_t)rowBaseI * K1_PAD,
                                     Alo + (size_t)rowBaseI * K1_PAD };
    const __nv_bfloat16* srcB[2] = { Bhi, Blo };

    auto load_stage = [&](int ck, int st) {
        uint32_t base = sb + st * G1_STAGE_B;
        #pragma unroll
        for (int i = 0; i < 10; i++) {
            int id = tid + i * 256;            // 0..2559
            if (id < 512) {                    // A arrays: 2 x 64 rows
                int m = id >> 8;
                int v = id & 255;
                int row = v >> 2, c = v & 3;
                int rowc = row;
                if (rowBaseI + rowc >= N_NODES) rowc = N_NODES - 1 - rowBaseI;
                const char* g = (const char*)(srcA[m] + (size_t)rowc * K1_PAD + ck * 32) + c * 16;
                cp_async16(base + m * G1_ARRA + sw_off(row, c * 16), g);
            } else {                           // B arrays: 2 x 256 rows
                int idb = id - 512;
                int m = idb >> 10;
                int v = idb & 1023;
                int row = v >> 2, c = v & 3;
                const char* g = (const char*)(srcB[m] + (size_t)row * K1_PAD + ck * 32) + c * 16;
                cp_async16(base + 2 * G1_ARRA + m * G1_ARRB + sw_off(row, c * 16), g);
            }
        }
        CP_COMMIT();
    };

    float acc[2][8][4];
    #pragma unroll
    for (int mt = 0; mt < 2; mt++)
        #pragma unroll
        for (int nt = 0; nt < 8; nt++)
            #pragma unroll
            for (int j = 0; j < 4; j++) acc[mt][nt][j] = 0.f;

    load_stage(0, 0);

    const int q = lane >> 3, r = lane & 7;
    const int aRowBase = warpM * 32 + ((q & 1) ? 8 : 0) + r;
    const int aColSel  = (q & 2) ? 8 : 0;
    const int bRowBase = warpN * 64 + ((q & 2) ? 8 : 0) + r;
    const int bColSel  = (q & 1) ? 8 : 0;

    #pragma unroll
    for (int ck = 0; ck < G1_NK; ck++) {
        CP_WAIT0();
        __syncthreads();
        if (ck + 1 < G1_NK) load_stage(ck + 1, (ck + 1) & 1);

        const uint32_t st = sb + (ck & 1) * G1_STAGE_B;
        #pragma unroll
        for (int ks = 0; ks < 2; ks++) {
            const int k0 = ks * 16;
            uint32_t ah[2][4], al[2][4];
            #pragma unroll
            for (int mt = 0; mt < 2; mt++) {
                uint32_t a = st + sw_off(aRowBase + mt * 16, (k0 + aColSel) * 2);
                ldsm_x4(a, ah[mt]);
                ldsm_x4(a + G1_ARRA, al[mt]);
            }
            #pragma unroll
            for (int nt2 = 0; nt2 < 4; nt2++) {
                uint32_t a = st + 2 * G1_ARRA + sw_off(bRowBase + nt2 * 16, (k0 + bColSel) * 2);
                uint32_t bh[4], bl[4];
                ldsm_x4(a, bh);
                ldsm_x4(a + G1_ARRB, bl);
                #pragma unroll
                for (int half = 0; half < 2; half++) {
                    const int nt = nt2 * 2 + half;
                    const uint32_t* bhp = bh + half * 2;
                    const uint32_t* blp = bl + half * 2;
                    mma_bf16(acc[0][nt], ah[0], bhp);
                    mma_bf16(acc[1][nt], ah[1], bhp);
                    mma_bf16(acc[0][nt], al[0], bhp);
                    mma_bf16(acc[1][nt], al[1], bhp);
                    mma_bf16(acc[0][nt], ah[0], blp);
                    mma_bf16(acc[1][nt], ah[1], blp);
                }
            }
        }
    }

    // ---------------- fused epilogue: GAT aggregation ----------------
    __syncthreads();   // all warps done reading stages: reuse smem

    float* hs    = (float*)smem;                          // [64][258] = 66048B
    float* sv    = (float*)(smem + 66048);                // 64
    float* dvv   = sv + 64;                               // 64
    float* alpha = dvv + 64;                              // [64][12]

    const int g2 = lane >> 2, ti = lane & 3;
    #pragma unroll
    for (int mt = 0; mt < 2; mt++) {
        int row = warpM * 32 + mt * 16 + g2;
        #pragma unroll
        for (int nt = 0; nt < 8; nt++) {
            int col = warpN * 64 + nt * 8 + ti * 2;
            *(float2*)&hs[row * HS1_STRIDE + col]       = make_float2(acc[mt][nt][0], acc[mt][nt][1]);
            *(float2*)&hs[(row + 8) * HS1_STRIDE + col] = make_float2(acc[mt][nt][2], acc[mt][nt][3]);
        }
    }
    __syncthreads();

    const int nSess  = min(G1_SESS, B_SESS - blockIdx.x * G1_SESS);
    const int nNodes = nSess * NPS;

    // per-node attention dots
    for (int node = wid; node < nNodes; node += 8) {
        float ss = 0.f, dd = 0.f;
        #pragma unroll
        for (int c = lane; c < F_HID; c += 32) {
            float h = hs[node * HS1_STRIDE + c];
            ss = fmaf(h, asrc[c], ss);
            dd = fmaf(h, adst[c], dd);
        }
        #pragma unroll
        for (int o = 16; o; o >>= 1) {
            ss += __shfl_down_sync(0xffffffffu, ss, o);
            dd += __shfl_down_sync(0xffffffffu, dd, o);
        }
        if (lane == 0) { sv[node] = ss; dvv[node] = dd; }
    }
    __syncthreads();

    if (tid < nNodes) compute_alpha(sv, dvv, alpha, tid);
    __syncthreads();

    // aggregate + bias + relu -> y bf16 hi/lo (2 cols per thread)
    {
        const int col0 = (tid & 127) * 2;
        const int hgrp = tid >> 7;              // 0..1 (warp-uniform)
        const float b0 = bias[col0], b1v = bias[col0 + 1];
        for (int n = hgrp; n < nNodes; n += 2) {
            float a0, a1;
            aggregate2(hs, HS1_STRIDE, alpha, n, col0, a0, a1);
            float v0 = fmaxf(a0 + b0, 0.f);
            float v1 = fmaxf(a1 + b1v, 0.f);
            __nv_bfloat16 h0 = __float2bfloat16(v0);
            __nv_bfloat16 h1 = __float2bfloat16(v1);
            __nv_bfloat16 l0 = __float2bfloat16(v0 - __bfloat162float(h0));
            __nv_bfloat16 l1 = __float2bfloat16(v1 - __bfloat162float(h1));
            size_t off = (size_t)(rowBaseI + n) * F_HID + col0;
            *(__nv_bfloat162*)(Yhi + off) = __nv_bfloat162(h0, h1);
            *(__nv_bfloat162*)(Ylo + off) = __nv_bfloat162(l0, l1);
        }
    }
}

// ===========================================================================
// Kernel 4: fused GEMM2 (y @ W2^T) + GAT agg layer 2 + sigmoid head
// Block: 256 thr, 8 warps (4x2), tile 128(126) x 128, K=256.
// ===========================================================================
#define G2_NK 8
#define G2_STAGE_B 32768        // Ahi Alo Bhi Blo: 4 x 8192
#define G2_NSTAGE 3
#define G2_SMEM (G2_NSTAGE * G2_STAGE_B)   // 98304
#define HS2_STRIDE 130

__global__ __launch_bounds__(256, 2) void gemm2_fused(
    const __nv_bfloat16* __restrict__ Ahi, const __nv_bfloat16* __restrict__ Alo,
    const __nv_bfloat16* __restrict__ Bhi, const __nv_bfloat16* __restrict__ Blo,
    const float* __restrict__ asrc, const float* __restrict__ adst,
    const float* __restrict__ bias,
    const float* __restrict__ Wl, const float* __restrict__ bl,
    float* __restrict__ hid, float* __restrict__ yout)
{
    extern __shared__ char smem[];
    const uint32_t sb = smem_to_u32(smem);
    const int tid = threadIdx.x;
    const int wid = tid >> 5, lane = tid & 31;
    const int warpM = wid & 3, warpN = wid >> 2;     // 4 x 2
    const int rowBaseI = blockIdx.x * ROWS_PER_BLK;

    const __nv_bfloat16* srcs[4] = {
        Ahi + (size_t)rowBaseI * F_HID, Alo + (size_t)rowBaseI * F_HID,
        Bhi, Blo
    };

    auto load_stage = [&](int ck, int st) {
        uint32_t base = sb + st * G2_STAGE_B;
        #pragma unroll
        for (int i = 0; i < 8; i++) {
            int id = tid + i * 256;            // 0..2047
            int m  = id >> 9;
            int v  = id & 511;
            int row = v >> 2, c = v & 3;
            int rowc = row;
            if (m < 2 && rowBaseI + rowc >= N_NODES) rowc = N_NODES - 1 - rowBaseI;
            const char* g = (const char*)(srcs[m] + (size_t)rowc * F_HID + ck * 32) + c * 16;
            cp_async16(base + m * 8192 + sw_off(row, c * 16), g);
        }
        CP_COMMIT();
    };

    float acc[2][8][4];
    #pragma unroll
    for (int mt = 0; mt < 2; mt++)
        #pragma unroll
        for (int nt = 0; nt < 8; nt++)
            #pragma unroll
            for (int j = 0; j < 4; j++) acc[mt][nt][j] = 0.f;

    load_stage(0, 0);
    load_stage(1, 1);

    const int q = lane >> 3, r = lane & 7;
    const int aRowBase = warpM * 32 + ((q & 1) ? 8 : 0) + r;
    const int aColSel  = (q & 2) ? 8 : 0;
    const int bRowBase = warpN * 64 + ((q & 2) ? 8 : 0) + r;
    const int bColSel  = (q & 1) ? 8 : 0;

    #pragma unroll
    for (int ck = 0; ck < G2_NK; ck++) {
        if (ck < G2_NK - 1) CP_WAIT1(); else CP_WAIT0();
        __syncthreads();
        if (ck + 2 < G2_NK) load_stage(ck + 2, (ck + 2) % G2_NSTAGE);

        const uint32_t st = sb + (ck % G2_NSTAGE) * G2_STAGE_B;
        #pragma unroll
        for (int ks = 0; ks < 2; ks++) {
            const int k0 = ks * 16;
            uint32_t ah[2][4], al[2][4];
            #pragma unroll
            for (int mt = 0; mt < 2; mt++) {
                uint32_t a = st + sw_off(aRowBase + mt * 16, (k0 + aColSel) * 2);
                ldsm_x4(a, ah[mt]);
                ldsm_x4(a + 8192, al[mt]);
            }
            #pragma unroll
            for (int nt2 = 0; nt2 < 4; nt2++) {
                uint32_t a = st + 16384 + sw_off(bRowBase + nt2 * 16, (k0 + bColSel) * 2);
                uint32_t bh[4], bl_[4];
                ldsm_x4(a, bh);
                ldsm_x4(a + 8192, bl_);
                #pragma unroll
                for (int half = 0; half < 2; half++) {
                    const int nt = nt2 * 2 + half;
                    const uint32_t* bhp = bh + half * 2;
                    const uint32_t* blp = bl_ + half * 2;
                    mma_bf16(acc[0][nt], ah[0], bhp);
                    mma_bf16(acc[1][nt], ah[1], bhp);
                    mma_bf16(acc[0][nt], al[0], bhp);
                    mma_bf16(acc[1][nt], al[1], bhp);
                    mma_bf16(acc[0][nt], ah[0], blp);
                    mma_bf16(acc[1][nt], ah[1], blp);
                }
            }
        }
    }

    // ---------------- fused epilogue: agg2 + head ----------------
    __syncthreads();

    float* hs    = (float*)smem;                          // [128][130]
    float* sv    = (float*)(smem + 66560);                // 128
    float* dvv   = sv + 128;                              // 128
    float* alpha = dvv + 128;                             // [128][12]
    float* pw    = alpha + 128 * 12;                      // [128][2]

    const int g2 = lane >> 2, ti = lane & 3;
    #pragma unroll
    for (int mt = 0; mt < 2; mt++) {
        int row = warpM * 32 + mt * 16 + g2;
        #pragma unroll
        for (int nt = 0; nt < 8; nt++) {
            int col = warpN * 64 + nt * 8 + ti * 2;
            *(float2*)&hs[row * HS2_STRIDE + col]       = make_float2(acc[mt][nt][0], acc[mt][nt][1]);
            *(float2*)&hs[(row + 8) * HS2_STRIDE + col] = make_float2(acc[mt][nt][2], acc[mt][nt][3]);
        }
    }
    __syncthreads();

    const int nSess  = min(SESS_PER_BLK, B_SESS - blockIdx.x * SESS_PER_BLK);
    const int nNodes = nSess * NPS;

    for (int node = wid; node < nNodes; node += 8) {
        float ss = 0.f, dd = 0.f;
        #pragma unroll
        for (int c = lane; c < F_OUT; c += 32) {
            float h = hs[node * HS2_STRIDE + c];
            ss = fmaf(h, asrc[c], ss);
            dd = fmaf(h, adst[c], dd);
        }
        #pragma unroll
        for (int o = 16; o; o >>= 1) {
            ss += __shfl_down_sync(0xffffffffu, ss, o);
            dd += __shfl_down_sync(0xffffffffu, dd, o);
        }
        if (lane == 0) { sv[node] = ss; dvv[node] = dd; }
    }
    __syncthreads();

    if (tid < nNodes) compute_alpha(sv, dvv, alpha, tid);
    __syncthreads();

    // aggregate + bias -> hidden (global), head partials (deterministic)
    {
        const int col0 = (tid & 63) * 2;
        const int hgrp = tid >> 6;              // 0..3 (warp-uniform)
        const int wp = (tid >> 5) & 1;          // warp parity within group
        const float b0 = bias[col0], b1v = bias[col0 + 1];
        const float w0 = Wl[col0],  w1 = Wl[col0 + 1];
        for (int n = hgrp; n < nNodes; n += 4) {
            float a0, a1;
            aggregate2(hs, HS2_STRIDE, alpha, n, col0, a0, a1);
            float v0 = a0 + b0;
            float v1 = a1 + b1v;
            *(float2*)&hid[(size_t)(rowBaseI + n) * F_OUT + col0] = make_float2(v0, v1);
            float pp = fmaxf(v0, 0.f) * w0 + fmaxf(v1, 0.f) * w1;
            #pragma unroll
            for (int o = 16; o; o >>= 1)
                pp += __shfl_down_sync(0xffffffffu, pp, o);
            if (lane == 0) pw[n * 2 + wp] = pp;
        }
    }
    __syncthreads();

    if (tid < nNodes) {
        float p = pw[tid * 2] + pw[tid * 2 + 1] + bl[0];
        yout[rowBaseI + tid] = 1.f / (1.f + expf(-p));
    }
}

// ===========================================================================
extern "C" void kernel_launch(void* const* d_in, const int* in_sizes, int n_in,
                              void* d_out, int out_size)
{
    const float* x     = (const float*)d_in[1];
    const int*   click = (const int*)  d_in[4];
    const int*   query = (const int*)  d_in[5];
    const int*   docu  = (const int*)  d_in[6];
    const int*   title = (const int*)  d_in[7];
    const float* qtab  = (const float*)d_in[8];
    const float* dtab  = (const float*)d_in[9];
    const float* ttab  = (const float*)d_in[10];
    const float* ptab  = (const float*)d_in[11];
    const float* ctab  = (const float*)d_in[12];
    const float* W1    = (const float*)d_in[13];
    const float* as1   = (const float*)d_in[14];
    const float* ad1   = (const float*)d_in[15];
    const float* b1    = (const float*)d_in[16];
    const float* W2    = (const float*)d_in[17];
    const float* as2   = (const float*)d_in[18];
    const float* ad2   = (const float*)d_in[19];
    const float* b2    = (const float*)d_in[20];
    const float* Wl    = (const float*)d_in[21];
    const float* bl    = (const float*)d_in[22];

    float* out  = (float*)d_out;
    float* xout = out + OUT_X_OFF;
    float* hout = out + OUT_HID_OFF;
    float* yout = out + OUT_Y_OFF;

    __nv_bfloat16 *xhi, *xlo, *yhi, *ylo, *w1hi, *w1lo, *w2hi, *w2lo;
    cudaGetSymbolAddress((void**)&xhi,  g_xhi);
    cudaGetSymbolAddress((void**)&xlo,  g_xlo);
    cudaGetSymbolAddress((void**)&yhi,  g_yhi);
    cudaGetSymbolAddress((void**)&ylo,  g_ylo);
    cudaGetSymbolAddress((void**)&w1hi, g_w1hi);
    cudaGetSymbolAddress((void**)&w1lo, g_w1lo);
    cudaGetSymbolAddress((void**)&w2hi, g_w2hi);
    cudaGetSymbolAddress((void**)&w2lo, g_w2lo);

    cudaFuncSetAttribute(gemm1_fused, cudaFuncAttributeMaxDynamicSharedMemorySize, G1_SMEM);
    cudaFuncSetAttribute(gemm2_fused, cudaFuncAttributeMaxDynamicSharedMemorySize, G2_SMEM);

    // 1. scatter embeddings into x output slice + fused bf16 hi/lo split
    {
        long long tot = (long long)N_NODES * (K1_PAD / 4);
        build_x_kernel<<<(unsigned)((tot + 255) / 256), 256>>>(
            x, click, query, docu, title, qtab, dtab, ttab, ptab, ctab,
            xout, xhi, xlo);
    }

    // 2. weight splits
    {
        long long tot = (long long)F_HID * K1_PAD;
        conv_split<<<(unsigned)((tot + 255) / 256), 256>>>(W1, F_IN, w1hi, w1lo, K1_PAD, tot);
    }
    {
        long long tot = (long long)F_OUT * F_HID;
        conv_split<<<(unsigned)((tot + 255) / 256), 256>>>(W2, F_HID, w2hi, w2lo, F_HID, tot);
    }

    // 3. fused GEMM1 + agg1 -> y (bf16 hi/lo)
    gemm1_fused<<<G1_NBLK, 256, G1_SMEM>>>(
        xhi, xlo, w1hi, w1lo, as1, ad1, b1, yhi, ylo);

    // 4. fused GEMM2 + agg2 + head -> hidden, y
    gemm2_fused<<<NBLK, 256, G2_SMEM>>>(
        yhi, ylo, w2hi, w2lo, as2, ad2, b2, Wl, bl, hout, yout);
}

// round 13
// speedup vs baseline: 3.5879x; 1.1435x over previous
#include <cuda_runtime.h>
#include <cuda_bf16.h>
#include <math.h>
#include <stdint.h>

#define B_SESS   8192
#define NPS      21
#define N_NODES  (B_SESS * NPS)      // 172032
#define F_IN     171
#define K1_PAD   192                 // F_IN padded to 6*32
#define F_HID    256
#define F_OUT    128

// GEMM2 blocking
#define SESS_PER_BLK 6
#define ROWS_PER_BLK (SESS_PER_BLK * NPS)   // 126
#define NBLK ((B_SESS + SESS_PER_BLK - 1) / SESS_PER_BLK)  // 1366

// GEMM1 blocking (3 sessions, 64-row tile, 2 CTAs/SM)
#define G1_SESS 3
#define G1_ROWS (G1_SESS * NPS)             // 63
#define G1_NBLK ((B_SESS + G1_SESS - 1) / G1_SESS)  // 2731

// Output layout: hidden_state (N*128) | y (N*1) | x (N*171)
#define OUT_HID_OFF  0
#define OUT_Y_OFF    ((size_t)N_NODES * F_OUT)
#define OUT_X_OFF    ((size_t)N_NODES * (F_OUT + 1))

// Scratch (static device arrays: allocation-free)
__device__ __nv_bfloat16  g_xhi[(size_t)N_NODES * K1_PAD];
__device__ __nv_bfloat16  g_xlo[(size_t)N_NODES * K1_PAD];
__device__ __nv_bfloat16  g_yhi[(size_t)N_NODES * F_HID];
__device__ __nv_bfloat16  g_ylo[(size_t)N_NODES * F_HID];
__device__ __nv_bfloat16  g_w1hi[(size_t)F_HID * K1_PAD];
__device__ __nv_bfloat16  g_w1lo[(size_t)F_HID * K1_PAD];
__device__ __nv_bfloat16  g_w2hi[(size_t)F_OUT * F_HID];
__device__ __nv_bfloat16  g_w2lo[(size_t)F_OUT * F_HID];

// ===========================================================================
// helpers
// ===========================================================================
__device__ __forceinline__ uint32_t smem_to_u32(const void* p) {
    uint32_t a;
    asm("{ .reg .u64 t; cvta.to.shared.u64 t, %1; cvt.u32.u64 %0, t; }" : "=r"(a) : "l"(p));
    return a;
}
__device__ __forceinline__ void cp_async16(uint32_t dst, const void* src) {
    asm volatile("cp.async.cg.shared.global [%0], [%1], 16;" :: "r"(dst), "l"(src));
}
#define CP_COMMIT() asm volatile("cp.async.commit_group;" ::: "memory")
#define CP_WAIT0()  asm volatile("cp.async.wait_group 0;" ::: "memory")
#define CP_WAIT1()  asm volatile("cp.async.wait_group 1;" ::: "memory")

__device__ __forceinline__ void ldsm_x4(uint32_t addr, uint32_t* r) {
    asm volatile("ldmatrix.sync.aligned.m8n8.x4.shared.b16 {%0,%1,%2,%3}, [%4];"
        : "=r"(r[0]), "=r"(r[1]), "=r"(r[2]), "=r"(r[3]) : "r"(addr));
}
__device__ __forceinline__ void mma_bf16(float* d, const uint32_t* a, const uint32_t* b) {
    asm volatile("mma.sync.aligned.m16n8k16.row.col.f32.bf16.bf16.f32 "
        "{%0,%1,%2,%3}, {%4,%5,%6,%7}, {%8,%9}, {%0,%1,%2,%3};"
        : "+f"(d[0]), "+f"(d[1]), "+f"(d[2]), "+f"(d[3])
        : "r"(a[0]), "r"(a[1]), "r"(a[2]), "r"(a[3]), "r"(b[0]), "r"(b[1]));
}

// XOR bank swizzle on 64B rows (16B chunk granularity)
__device__ __forceinline__ uint32_t sw_off(int row, int colByte) {
    return (uint32_t)(row * 64 + ((((colByte >> 4) ^ ((row >> 1) & 3)) & 3) << 4));
}

__device__ __forceinline__ float lrelu(float v) { return v > 0.f ? v : 0.2f * v; }

// Branch-specialized softmax over in-neighbors (no local arrays).
// alpha layout per node (stride 12):
//   slot 0:  k=0..9 -> srcs 1..10, k=10 -> self(0)
//   slot 1..10: k0 -> 0, k1 -> slot+10, k2 -> slot (self)
//   slot 11..20: k0 -> slot-10, k1 -> slot (self)
__device__ __forceinline__ void compute_alpha(
    const float* __restrict__ sv, const float* __restrict__ dvv,
    float* __restrict__ alpha, int node)
{
    int slot = node % NPS;
    int rbase = node - slot;
    float d = dvv[node];
    float* al = alpha + node * 12;
    if (slot == 0) {
        float e0 = lrelu(sv[rbase + 1] + d);
        float e1 = lrelu(sv[rbase + 2] + d);
        float e2 = lrelu(sv[rbase + 3] + d);
        float e3 = lrelu(sv[rbase + 4] + d);
        float e4 = lrelu(sv[rbase + 5] + d);
        float e5 = lrelu(sv[rbase + 6] + d);
        float e6 = lrelu(sv[rbase + 7] + d);
        float e7 = lrelu(sv[rbase + 8] + d);
        float e8 = lrelu(sv[rbase + 9] + d);
        float e9 = lrelu(sv[rbase + 10] + d);
        float ea = lrelu(sv[rbase + 0] + d);
        float m = fmaxf(ea, fmaxf(fmaxf(fmaxf(e0, e1), fmaxf(e2, e3)),
                  fmaxf(fmaxf(fmaxf(e4, e5), fmaxf(e6, e7)), fmaxf(e8, e9))));
        e0 = expf(e0 - m); e1 = expf(e1 - m); e2 = expf(e2 - m); e3 = expf(e3 - m);
        e4 = expf(e4 - m); e5 = expf(e5 - m); e6 = expf(e6 - m); e7 = expf(e7 - m);
        e8 = expf(e8 - m); e9 = expf(e9 - m); ea = expf(ea - m);
        float inv = 1.f / (e0 + e1 + e2 + e3 + e4 + e5 + e6 + e7 + e8 + e9 + ea);
        al[0] = e0 * inv; al[1] = e1 * inv; al[2] = e2 * inv; al[3] = e3 * inv;
        al[4] = e4 * inv; al[5] = e5 * inv; al[6] = e6 * inv; al[7] = e7 * inv;
        al[8] = e8 * inv; al[9] = e9 * inv; al[10] = ea * inv;
    } else if (slot <= 10) {
        float v0 = lrelu(sv[rbase] + d);
        float v1 = lrelu(sv[rbase + slot + 10] + d);
        float v2 = lrelu(sv[rbase + slot] + d);
        float m = fmaxf(v0, fmaxf(v1, v2));
        float e0 = expf(v0 - m), e1 = expf(v1 - m), e2 = expf(v2 - m);
        float inv = 1.f / (e0 + e1 + e2);
        al[0] = e0 * inv; al[1] = e1 * inv; al[2] = e2 * inv;
    } else {
        float v0 = lrelu(sv[rbase + slot - 10] + d);
        float v1 = lrelu(sv[rbase + slot] + d);
        float m = fmaxf(v0, v1);
        float e0 = expf(v0 - m), e1 = expf(v1 - m);
        float inv = 1.f / (e0 + e1);
        al[0] = e0 * inv; al[1] = e1 * inv;
    }
}

// Branch-specialized 4-column aggregation (float4, explicit slot).
__device__ __forceinline__ float4 aggregate4(
    const float* __restrict__ hs, int stride,
    const float* __restrict__ alpha, int rbase, int slot, int col0)
{
    const float* al = alpha + (rbase + slot) * 12;
    float4 a = make_float4(0.f, 0.f, 0.f, 0.f);
    if (slot == 0) {
        #pragma unroll
        for (int j = 0; j < 10; j++) {
            float4 h = *(const float4*)&hs[(rbase + 1 + j) * stride + col0];
            float w = al[j];
            a.x = fmaf(w, h.x, a.x); a.y = fmaf(w, h.y, a.y);
            a.z = fmaf(w, h.z, a.z); a.w = fmaf(w, h.w, a.w);
        }
        float4 h = *(const float4*)&hs[rbase * stride + col0];
        float w = al[10];
        a.x = fmaf(w, h.x, a.x); a.y = fmaf(w, h.y, a.y);
        a.z = fmaf(w, h.z, a.z); a.w = fmaf(w, h.w, a.w);
    } else if (slot <= 10) {
        float4 h0 = *(const float4*)&hs[rbase * stride + col0];
        float4 h1 = *(const float4*)&hs[(rbase + slot + 10) * stride + col0];
        float4 h2 = *(const float4*)&hs[(rbase + slot) * stride + col0];
        float w0 = al[0], w1 = al[1], w2 = al[2];
        a.x = w0 * h0.x + w1 * h1.x + w2 * h2.x;
        a.y = w0 * h0.y + w1 * h1.y + w2 * h2.y;
        a.z = w0 * h0.z + w1 * h1.z + w2 * h2.z;
        a.w = w0 * h0.w + w1 * h1.w + w2 * h2.w;
    } else {
        float4 h0 = *(const float4*)&hs[(rbase + slot - 10) * stride + col0];
        float4 h1 = *(const float4*)&hs[(rbase + slot) * stride + col0];
        float w0 = al[0], w1 = al[1];
        a.x = w0 * h0.x + w1 * h1.x;
        a.y = w0 * h0.y + w1 * h1.y;
        a.z = w0 * h0.z + w1 * h1.z;
        a.w = w0 * h0.w + w1 * h1.w;
    }
    return a;
}

__device__ __forceinline__ uint2 pack_hi_lo4(float v0, float v1, float v2, float v3,
                                             uint2& lo_out)
{
    __nv_bfloat16 h0 = __float2bfloat16(v0), h1 = __float2bfloat16(v1);
    __nv_bfloat16 h2 = __float2bfloat16(v2), h3 = __float2bfloat16(v3);
    __nv_bfloat16 l0 = __float2bfloat16(v0 - __bfloat162float(h0));
    __nv_bfloat16 l1 = __float2bfloat16(v1 - __bfloat162float(h1));
    __nv_bfloat16 l2 = __float2bfloat16(v2 - __bfloat162float(h2));
    __nv_bfloat16 l3 = __float2bfloat16(v3 - __bfloat162float(h3));
    __nv_bfloat162 h01(h0, h1), h23(h2, h3), l01(l0, l1), l23(l2, l3);
    uint2 hi;
    hi.x = *reinterpret_cast<uint32_t*>(&h01);
    hi.y = *reinterpret_cast<uint32_t*>(&h23);
    lo_out.x = *reinterpret_cast<uint32_t*>(&l01);
    lo_out.y = *reinterpret_cast<uint32_t*>(&l23);
    return hi;
}

// ===========================================================================
// Kernel 1: build x_mod (scatter) + fused bf16 hi/lo split, 4 cols per thread
// ===========================================================================
__global__ __launch_bounds__(256) void build_x_kernel(
    const float* __restrict__ x,
    const int*   __restrict__ click,
    const int*   __restrict__ query,
    const int*   __restrict__ docu,
    const int*   __restrict__ title_id,
    const float* __restrict__ qtab,
    const float* __restrict__ dtab,
    const float* __restrict__ ttab,
    const float* __restrict__ ptab,
    const float* __restrict__ ctab,
    float* __restrict__ xout,
    __nv_bfloat16* __restrict__ xhi,
    __nv_bfloat16* __restrict__ xlo)
{
    long long t = (long long)blockIdx.x * blockDim.x + threadIdx.x;
    if (t >= (long long)N_NODES * (K1_PAD / 4)) return;
    int n  = (int)(t / (K1_PAD / 4));
    int cc = (int)(t - (long long)n * (K1_PAD / 4));
    int c0 = cc * 4;
    int b = n / NPS;
    int s = n - b * NPS;

    float4 v;
    if (c0 + 3 < 160) {
        const float* tab;
        size_t row;
        if (s == 0)            { tab = qtab; row = (size_t)query[b]; }
        else if (s <= 10)      { tab = dtab; row = (size_t)docu[b * 10 + (s - 1)]; }
        else                   { tab = ttab; row = (size_t)title_id[b * 10 + (s - 11)]; }
        v = *(const float4*)(tab + row * 160 + c0);
    } else {
        float vv[4];
        #pragma unroll
        for (int j = 0; j < 4; j++) {
            int c = c0 + j;
            float val = 0.f;
            if (c < F_IN) {
                long long xi = (long long)n * F_IN + c;
                if (s == 0) {
                    val = (c < 160) ? qtab[(size_t)query[b] * 160 + c] : x[xi];
                } else if (s <= 10) {
                    int jj = s - 1;
                    if      (c < 160)  val = dtab[(size_t)docu[b * 10 + jj] * 160 + c];
                    else if (c == 160) val = ptab[jj];
                    else if (c == 161) val = ctab[click[b]];
                    else               val = x[xi];
                } else {
                    val = (c < 160) ? ttab[(size_t)title_id[b * 10 + (s - 11)] * 160 + c] : x[xi];
                }
            }
            vv[j] = val;
        }
        v = make_float4(vv[0], vv[1], vv[2], vv[3]);
    }

    {
        long long xi = (long long)n * F_IN + c0;
        if (c0 + 3 < F_IN) {
            xout[xi] = v.x; xout[xi + 1] = v.y; xout[xi + 2] = v.z; xout[xi + 3] = v.w;
        } else {
            float vv[4] = {v.x, v.y, v.z, v.w};
            #pragma unroll
            for (int j = 0; j < 4; j++)
                if (c0 + j < F_IN) xout[xi + j] = vv[j];
        }
    }

    long long oi = (long long)n * K1_PAD + c0;
    uint2 lo;
    uint2 hi = pack_hi_lo4(v.x, v.y, v.z, v.w, lo);
    *(uint2*)(xhi + oi) = hi;
    *(uint2*)(xlo + oi) = lo;
}

// ===========================================================================
// Kernel 2: fp32 -> bf16 hi/lo split for weights (with K padding)
// ===========================================================================
__global__ __launch_bounds__(256) void conv_split(
    const float* __restrict__ src, int Ksrc,
    __nv_bfloat16* __restrict__ hi, __nv_bfloat16* __restrict__ lo,
    int Kdst, long long total)
{
    long long idx = (long long)blockIdx.x * blockDim.x + threadIdx.x;
    if (idx >= total) return;
    long long row = idx / Kdst;
    int c = (int)(idx - row * Kdst);
    float v = (c < Ksrc) ? src[row * Ksrc + c] : 0.f;
    __nv_bfloat16 h = __float2bfloat16(v);
    hi[idx] = h;
    lo[idx] = __float2bfloat16(v - __bfloat162float(h));
}

// ===========================================================================
// Kernel 3: fused GEMM1 (x @ W1^T, split-3 bf16 HMMA) + GAT agg layer 1
// Block: 256 thr, 8 warps (2x4), tile 64(63 used) x 256, K=192. 2-stage.
// ===========================================================================
#define G1_NK 6
#define G1_ARRA 4096            // 64 rows x 64B
#define G1_ARRB 16384           // 256 rows x 64B
#define G1_STAGE_B (2 * G1_ARRA + 2 * G1_ARRB)   // 40960
#define G1_SMEM (2 * G1_STAGE_B)   // 81920
#define HS1_STRIDE 260

__global__ __launch_bounds__(256, 2) void gemm1_fused(
    const __nv_bfloat16* __restrict__ Ahi, const __nv_bfloat16* __restrict__ Alo,
    const __nv_bfloat16* __restrict__ Bhi, const __nv_bfloat16* __restrict__ Blo,
    const float* __restrict__ asrc, const float* __restrict__ adst,
    const float* __restrict__ bias,
    __nv_bfloat16* __restrict__ Yhi, __nv_bfloat16* __restrict__ Ylo)
{
    extern __shared__ char smem[];
    const uint32_t sb = smem_to_u32(smem);
    const int tid = threadIdx.x;
    const int wid = tid >> 5, lane = tid & 31;
    const int warpM = wid & 1, warpN = wid >> 1;     // 2 x 4 warp grid
    const int rowBaseI = blockIdx.x * G1_ROWS;

    const __nv_bfloat16* srcA[2] = { Ahi + (size_t)rowBaseI * K1_PAD,
                                     Alo + (size_t)rowBaseI * K1_PAD };
    const __nv_bfloat16* srcB[2] = { Bhi, Blo };

    auto load_stage = [&](int ck, int st) {
        uint32_t base = sb + st * G1_STAGE_B;
        #pragma unroll
        for (int i = 0; i < 10; i++) {
            int id = tid + i * 256;            // 0..2559
            if (id < 512) {                    // A arrays: 2 x 64 rows
                int m = id >> 8;
                int v = id & 255;
                int row = v >> 2, c = v & 3;
                int rowc = row;
                if (rowBaseI + rowc >= N_NODES) rowc = N_NODES - 1 - rowBaseI;
                const char* g = (const char*)(srcA[m] + (size_t)rowc * K1_PAD + ck * 32) + c * 16;
                cp_async16(base + m * G1_ARRA + sw_off(row, c * 16), g);
            } else {                           // B arrays: 2 x 256 rows
                int idb = id - 512;
                int m = idb >> 10;
                int v = idb & 1023;
                int row = v >> 2, c = v & 3;
                const char* g = (const char*)(srcB[m] + (size_t)row * K1_PAD + ck * 32) + c * 16;
                cp_async16(base + 2 * G1_ARRA + m * G1_ARRB + sw_off(row, c * 16), g);
            }
        }
        CP_COMMIT();
    };

    float acc[2][8][4];
    #pragma unroll
    for (int mt = 0; mt < 2; mt++)
        #pragma unroll
        for (int nt = 0; nt < 8; nt++)
            #pragma unroll
            for (int j = 0; j < 4; j++) acc[mt][nt][j] = 0.f;

    load_stage(0, 0);

    const int q = lane >> 3, r = lane & 7;
    const int aRowBase = warpM * 32 + ((q & 1) ? 8 : 0) + r;
    const int aColSel  = (q & 2) ? 8 : 0;
    const int bRowBase = warpN * 64 + ((q & 2) ? 8 : 0) + r;
    const int bColSel  = (q & 1) ? 8 : 0;

    #pragma unroll
    for (int ck = 0; ck < G1_NK; ck++) {
        CP_WAIT0();
        __syncthreads();
        if (ck + 1 < G1_NK) load_stage(ck + 1, (ck + 1) & 1);

        const uint32_t st = sb + (ck & 1) * G1_STAGE_B;
        #pragma unroll
        for (int ks = 0; ks < 2; ks++) {
            const int k0 = ks * 16;
            uint32_t ah[2][4], al[2][4];
            #pragma unroll
            for (int mt = 0; mt < 2; mt++) {
                uint32_t a = st + sw_off(aRowBase + mt * 16, (k0 + aColSel) * 2);
                ldsm_x4(a, ah[mt]);
                ldsm_x4(a + G1_ARRA, al[mt]);
            }
            #pragma unroll
            for (int nt2 = 0; nt2 < 4; nt2++) {
                uint32_t a = st + 2 * G1_ARRA + sw_off(bRowBase + nt2 * 16, (k0 + bColSel) * 2);
                uint32_t bh[4], bl[4];
                ldsm_x4(a, bh);
                ldsm_x4(a + G1_ARRB, bl);
                #pragma unroll
                for (int half = 0; half < 2; half++) {
                    const int nt = nt2 * 2 + half;
                    const uint32_t* bhp = bh + half * 2;
                    const uint32_t* blp = bl + half * 2;
                    mma_bf16(acc[0][nt], ah[0], bhp);
                    mma_bf16(acc[1][nt], ah[1], bhp);
                    mma_bf16(acc[0][nt], al[0], bhp);
                    mma_bf16(acc[1][nt], al[1], bhp);
                    mma_bf16(acc[0][nt], ah[0], blp);
                    mma_bf16(acc[1][nt], ah[1], blp);
                }
            }
        }
    }

    // ---------------- fused epilogue: GAT aggregation ----------------
    __syncthreads();   // all warps done reading stages: reuse smem

    float* hs    = (float*)smem;                       // [64][260] = 66560B
    float* sv    = (float*)(smem + 66560);             // 64
    float* dvv   = sv + 64;                            // 64
    float* alpha = dvv + 64;                           // [64][12]
    float* sa    = alpha + 64 * 12;                    // 256
    float* sd    = sa + 256;                           // 256

    const int g2 = lane >> 2, ti = lane & 3;
    #pragma unroll
    for (int mt = 0; mt < 2; mt++) {
        int row = warpM * 32 + mt * 16 + g2;
        #pragma unroll
        for (int nt = 0; nt < 8; nt++) {
            int col = warpN * 64 + nt * 8 + ti * 2;
            *(float2*)&hs[row * HS1_STRIDE + col]       = make_float2(acc[mt][nt][0], acc[mt][nt][1]);
            *(float2*)&hs[(row + 8) * HS1_STRIDE + col] = make_float2(acc[mt][nt][2], acc[mt][nt][3]);
        }
    }
    if (tid < F_HID) { sa[tid] = asrc[tid]; sd[tid] = adst[tid]; }
    __syncthreads();

    const int nSess  = min(G1_SESS, B_SESS - blockIdx.x * G1_SESS);
    const int nNodes = nSess * NPS;

    // per-node attention dots (float4, smem-staged a-vectors)
    {
        const float4* sa4 = (const float4*)sa;
        const float4* sd4 = (const float4*)sd;
        float4 s1 = sa4[lane], s2 = sa4[32 + lane];
        float4 d1 = sd4[lane], d2 = sd4[32 + lane];
        for (int node = wid; node < nNodes; node += 8) {
            const float4* hp = (const float4*)&hs[node * HS1_STRIDE];
            float4 h1 = hp[lane], h2 = hp[32 + lane];
            float ss = h1.x * s1.x + h1.y * s1.y + h1.z * s1.z + h1.w * s1.w
                     + h2.x * s2.x + h2.y * s2.y + h2.z * s2.z + h2.w * s2.w;
            float dd = h1.x * d1.x + h1.y * d1.y + h1.z * d1.z + h1.w * d1.w
                     + h2.x * d2.x + h2.y * d2.y + h2.z * d2.z + h2.w * d2.w;
            #pragma unroll
            for (int o = 16; o; o >>= 1) {
                ss += __shfl_down_sync(0xffffffffu, ss, o);
                dd += __shfl_down_sync(0xffffffffu, dd, o);
            }
            if (lane == 0) { sv[node] = ss; dvv[node] = dd; }
        }
    }
    __syncthreads();

    if (tid < nNodes) compute_alpha(sv, dvv, alpha, tid);
    __syncthreads();

    // aggregate + bias + relu -> y bf16 hi/lo (4 cols per thread)
    {
        const int col0 = (tid & 63) * 4;
        const int hgrp = tid >> 6;              // 0..3 (warp-uniform)
        const float4 bv = *(const float4*)&bias[col0];
        int slot = hgrp;
        for (int n = hgrp; n < nNodes; n += 4) {
            int rbase = n - slot;
            float4 a = aggregate4(hs, HS1_STRIDE, alpha, rbase, slot, col0);
            float v0 = fmaxf(a.x + bv.x, 0.f);
            float v1 = fmaxf(a.y + bv.y, 0.f);
            float v2 = fmaxf(a.z + bv.z, 0.f);
            float v3 = fmaxf(a.w + bv.w, 0.f);
            uint2 lo;
            uint2 hi = pack_hi_lo4(v0, v1, v2, v3, lo);
            size_t off = (size_t)(rowBaseI + n) * F_HID + col0;
            *(uint2*)(Yhi + off) = hi;
            *(uint2*)(Ylo + off) = lo;
            slot += 4; if (slot >= NPS) slot -= NPS;
        }
    }
}

// ===========================================================================
// Kernel 4: fused GEMM2 (y @ W2^T) + GAT agg layer 2 + sigmoid head
// Block: 256 thr, 8 warps (4x2), tile 128(126) x 128, K=256.
// ===========================================================================
#define G2_NK 8
#define G2_STAGE_B 32768        // Ahi Alo Bhi Blo: 4 x 8192
#define G2_NSTAGE 3
#define G2_SMEM (G2_NSTAGE * G2_STAGE_B)   // 98304
#define HS2_STRIDE 132

__global__ __launch_bounds__(256, 2) void gemm2_fused(
    const __nv_bfloat16* __restrict__ Ahi, const __nv_bfloat16* __restrict__ Alo,
    const __nv_bfloat16* __restrict__ Bhi, const __nv_bfloat16* __restrict__ Blo,
    const float* __restrict__ asrc, const float* __restrict__ adst,
    const float* __restrict__ bias,
    const float* __restrict__ Wl, const float* __restrict__ bl,
    float* __restrict__ hid, float* __restrict__ yout)
{
    extern __shared__ char smem[];
    const uint32_t sb = smem_to_u32(smem);
    const int tid = threadIdx.x;
    const int wid = tid >> 5, lane = tid & 31;
    const int warpM = wid & 3, warpN = wid >> 2;     // 4 x 2
    const int rowBaseI = blockIdx.x * ROWS_PER_BLK;

    const __nv_bfloat16* srcs[4] = {
        Ahi + (size_t)rowBaseI * F_HID, Alo + (size_t)rowBaseI * F_HID,
        Bhi, Blo
    };

    auto load_stage = [&](int ck, int st) {
        uint32_t base = sb + st * G2_STAGE_B;
        #pragma unroll
        for (int i = 0; i < 8; i++) {
            int id = tid + i * 256;            // 0..2047
            int m  = id >> 9;
            int v  = id & 511;
            int row = v >> 2, c = v & 3;
            int rowc = row;
            if (m < 2 && rowBaseI + rowc >= N_NODES) rowc = N_NODES - 1 - rowBaseI;
            const char* g = (const char*)(srcs[m] + (size_t)rowc * F_HID + ck * 32) + c * 16;
            cp_async16(base + m * 8192 + sw_off(row, c * 16), g);
        }
        CP_COMMIT();
    };

    float acc[2][8][4];
    #pragma unroll
    for (int mt = 0; mt < 2; mt++)
        #pragma unroll
        for (int nt = 0; nt < 8; nt++)
            #pragma unroll
            for (int j = 0; j < 4; j++) acc[mt][nt][j] = 0.f;

    load_stage(0, 0);
    load_stage(1, 1);

    const int q = lane >> 3, r = lane & 7;
    const int aRowBase = warpM * 32 + ((q & 1) ? 8 : 0) + r;
    const int aColSel  = (q & 2) ? 8 : 0;
    const int bRowBase = warpN * 64 + ((q & 2) ? 8 : 0) + r;
    const int bColSel  = (q & 1) ? 8 : 0;

    #pragma unroll
    for (int ck = 0; ck < G2_NK; ck++) {
        if (ck < G2_NK - 1) CP_WAIT1(); else CP_WAIT0();
        __syncthreads();
        if (ck + 2 < G2_NK) load_stage(ck + 2, (ck + 2) % G2_NSTAGE);

        const uint32_t st = sb + (ck % G2_NSTAGE) * G2_STAGE_B;
        #pragma unroll
        for (int ks = 0; ks < 2; ks++) {
            const int k0 = ks * 16;
            uint32_t ah[2][4], al[2][4];
            #pragma unroll
            for (int mt = 0; mt < 2; mt++) {
                uint32_t a = st + sw_off(aRowBase + mt * 16, (k0 + aColSel) * 2);
                ldsm_x4(a, ah[mt]);
                ldsm_x4(a + 8192, al[mt]);
            }
            #pragma unroll
            for (int nt2 = 0; nt2 < 4; nt2++) {
                uint32_t a = st + 16384 + sw_off(bRowBase + nt2 * 16, (k0 + bColSel) * 2);
                uint32_t bh[4], bl_[4];
                ldsm_x4(a, bh);
                ldsm_x4(a + 8192, bl_);
                #pragma unroll
                for (int half = 0; half < 2; half++) {
                    const int nt = nt2 * 2 + half;
                    const uint32_t* bhp = bh + half * 2;
                    const uint32_t* blp = bl_ + half * 2;
                    mma_bf16(acc[0][nt], ah[0], bhp);
                    mma_bf16(acc[1][nt], ah[1], bhp);
                    mma_bf16(acc[0][nt], al[0], bhp);
                    mma_bf16(acc[1][nt], al[1], bhp);
                    mma_bf16(acc[0][nt], ah[0], blp);
                    mma_bf16(acc[1][nt], ah[1], blp);
                }
            }
        }
    }

    // ---------------- fused epilogue: agg2 + head ----------------
    __syncthreads();

    float* hs    = (float*)smem;                       // [128][132] = 67584B
    float* sv    = (float*)(smem + 67584);             // 128
    float* dvv   = sv + 128;                           // 128
    float* alpha = dvv + 128;                          // [128][12]
    float* pw    = alpha + 128 * 12;                   // 128
    float* sa    = pw + 128;                           // 128
    float* sd    = sa + 128;                           // 128

    const int g2 = lane >> 2, ti = lane & 3;
    #pragma unroll
    for (int mt = 0; mt < 2; mt++) {
        int row = warpM * 32 + mt * 16 + g2;
        #pragma unroll
        for (int nt = 0; nt < 8; nt++) {
            int col = warpN * 64 + nt * 8 + ti * 2;
            *(float2*)&hs[row * HS2_STRIDE + col]       = make_float2(acc[mt][nt][0], acc[mt][nt][1]);
            *(float2*)&hs[(row + 8) * HS2_STRIDE + col] = make_float2(acc[mt][nt][2], acc[mt][nt][3]);
        }
    }
    if (tid < F_OUT) { sa[tid] = asrc[tid]; sd[tid] = adst[tid]; }
    __syncthreads();

    const int nSess  = min(SESS_PER_BLK, B_SESS - blockIdx.x * SESS_PER_BLK);
    const int nNodes = nSess * NPS;

    // per-node attention dots (float4)
    {
        const float4* sa4 = (const float4*)sa;
        const float4* sd4 = (const float4*)sd;
        float4 s1 = sa4[lane];
        float4 d1 = sd4[lane];
        for (int node = wid; node < nNodes; node += 8) {
            const float4* hp = (const float4*)&hs[node * HS2_STRIDE];
            float4 h1 = hp[lane];
            float ss = h1.x * s1.x + h1.y * s1.y + h1.z * s1.z + h1.w * s1.w;
            float dd = h1.x * d1.x + h1.y * d1.y + h1.z * d1.z + h1.w * d1.w;
            #pragma unroll
            for (int o = 16; o; o >>= 1) {
                ss += __shfl_down_sync(0xffffffffu, ss, o);
                dd += __shfl_down_sync(0xffffffffu, dd, o);
            }
            if (lane == 0) { sv[node] = ss; dvv[node] = dd; }
        }
    }
    __syncthreads();

    if (tid < nNodes) compute_alpha(sv, dvv, alpha, tid);
    __syncthreads();

    // aggregate + bias -> hidden (global), head: one warp covers all 128 cols
    {
        const int col0 = (lane) * 4;            // 32 lanes x 4 = 128 cols
        const float4 bv = *(const float4*)&bias[col0];
        const float4 wv = *(const float4*)&Wl[col0];
        int slot = wid;                          // wid 0..7 < 21
        for (int n = wid; n < nNodes; n += 8) {
            int rbase = n - slot;
            float4 a = aggregate4(hs, HS2_STRIDE, alpha, rbase, slot, col0);
            float v0 = a.x + bv.x, v1 = a.y + bv.y, v2 = a.z + bv.z, v3 = a.w + bv.w;
            *(float4*)&hid[(size_t)(rowBaseI + n) * F_OUT + col0] = make_float4(v0, v1, v2, v3);
            float pp = fmaxf(v0, 0.f) * wv.x + fmaxf(v1, 0.f) * wv.y
                     + fmaxf(v2, 0.f) * wv.z + fmaxf(v3, 0.f) * wv.w;
            #pragma unroll
            for (int o = 16; o; o >>= 1)
                pp += __shfl_down_sync(0xffffffffu, pp, o);
            if (lane == 0) pw[n] = pp;
            slot += 8; if (slot >= NPS) slot -= NPS;
        }
    }
    __syncthreads();

    if (tid < nNodes) {
        float p = pw[tid] + bl[0];
        yout[rowBaseI + tid] = 1.f / (1.f + expf(-p));
    }
}

// ===========================================================================
extern "C" void kernel_launch(void* const* d_in, const int* in_sizes, int n_in,
                              void* d_out, int out_size)
{
    const float* x     = (const float*)d_in[1];
    const int*   click = (const int*)  d_in[4];
    const int*   query = (const int*)  d_in[5];
    const int*   docu  = (const int*)  d_in[6];
    const int*   title = (const int*)  d_in[7];
    const float* qtab  = (const float*)d_in[8];
    const float* dtab  = (const float*)d_in[9];
    const float* ttab  = (const float*)d_in[10];
    const float* ptab  = (const float*)d_in[11];
    const float* ctab  = (const float*)d_in[12];
    const float* W1    = (const float*)d_in[13];
    const float* as1   = (const float*)d_in[14];
    const float* ad1   = (const float*)d_in[15];
    const float* b1    = (const float*)d_in[16];
    const float* W2    = (const float*)d_in[17];
    const float* as2   = (const float*)d_in[18];
    const float* ad2   = (const float*)d_in[19];
    const float* b2    = (const float*)d_in[20];
    const float* Wl    = (const float*)d_in[21];
    const float* bl    = (const float*)d_in[22];

    float* out  = (float*)d_out;
    float* xout = out + OUT_X_OFF;
    float* hout = out + OUT_HID_OFF;
    float* yout = out + OUT_Y_OFF;

    __nv_bfloat16 *xhi, *xlo, *yhi, *ylo, *w1hi, *w1lo, *w2hi, *w2lo;
    cudaGetSymbolAddress((void**)&xhi,  g_xhi);
    cudaGetSymbolAddress((void**)&xlo,  g_xlo);
    cudaGetSymbolAddress((void**)&yhi,  g_yhi);
    cudaGetSymbolAddress((void**)&ylo,  g_ylo);
    cudaGetSymbolAddress((void**)&w1hi, g_w1hi);
    cudaGetSymbolAddress((void**)&w1lo, g_w1lo);
    cudaGetSymbolAddress((void**)&w2hi, g_w2hi);
    cudaGetSymbolAddress((void**)&w2lo, g_w2lo);

    cudaFuncSetAttribute(gemm1_fused, cudaFuncAttributeMaxDynamicSharedMemorySize, G1_SMEM);
    cudaFuncSetAttribute(gemm2_fused, cudaFuncAttributeMaxDynamicSharedMemorySize, G2_SMEM);

    // 1. scatter embeddings into x output slice + fused bf16 hi/lo split
    {
        long long tot = (long long)N_NODES * (K1_PAD / 4);
        build_x_kernel<<<(unsigned)((tot + 255) / 256), 256>>>(
            x, click, query, docu, title, qtab, dtab, ttab, ptab, ctab,
            xout, xhi, xlo);
    }

    // 2. weight splits
    {
        long long tot = (long long)F_HID * K1_PAD;
        conv_split<<<(unsigned)((tot + 255) / 256), 256>>>(W1, F_IN, w1hi, w1lo, K1_PAD, tot);
    }
    {
        long long tot = (long long)F_OUT * F_HID;
        conv_split<<<(unsigned)((tot + 255) / 256), 256>>>(W2, F_HID, w2hi, w2lo, F_HID, tot);
    }

    // 3. fused GEMM1 + agg1 -> y (bf16 hi/lo)
    gemm1_fused<<<G1_NBLK, 256, G1_SMEM>>>(
        xhi, xlo, w1hi, w1lo, as1, ad1, b1, yhi, ylo);

    // 4. fused GEMM2 + agg2 + head -> hidden, y
    gemm2_fused<<<NBLK, 256, G2_SMEM>>>(
        yhi, ylo, w2hi, w2lo, as2, ad2, b2, Wl, bl, hout, yout);
}